// round 1
// baseline (speedup 1.0000x reference)
#include <cuda_runtime.h>

// ---------------------------------------------------------------------------
// WaveletDiffusion baseline: fp32 direct convs with shared-memory tiles.
// Shapes: x[16,8,256,256] -> dwt -> [16,32,128,128]
//   conv1 32->64 @128, GN8, relu
//   conv2 64->128 s2 -> @64, GN16, relu
//   conv3 128->256 @64, GN32, relu
//   conv4 256->128 @64, GN16, relu
//   convT 128->64 4x4 s2 -> @128, GN8, relu
//   conv6 64->16 @128
//   idwt -> [16,4,256,256]
// ---------------------------------------------------------------------------

#define NB 16

// scratch (device globals; no allocation allowed)
__device__ float g_s0[16 * 32 * 128 * 128];   // 8.39M  (dwt out, conv6 out)
__device__ float g_sA[16 * 256 * 64 * 64];    // 16.78M (conv3 out)
__device__ float g_sB[16 * 128 * 64 * 64];    // 8.39M  (conv2 out, conv4 out)
__device__ float g_sC[16 * 64 * 128 * 128];   // 16.78M (conv1 out, convT out)
__device__ float g_mv[1024];                  // GN mean/rstd pairs (max 16*32)

// ---------------------------------------------------------------------------
// DWT: out[b, c*4+s, h, w] = sum_{d,e} x[b,c,2h+d,2w+e] * Kd[s,d,e]
// ---------------------------------------------------------------------------
__global__ void dwt2d_k(const float* __restrict__ x, const float* __restrict__ Kd,
                        float* __restrict__ out) {
    int idx = blockIdx.x * blockDim.x + threadIdx.x;       // over 16*8*128*128
    if (idx >= 16 * 8 * 128 * 128) return;
    int w = idx & 127;
    int h = (idx >> 7) & 127;
    int c = (idx >> 14) & 7;
    int b = idx >> 17;
    const float* xp = x + (((b * 8 + c) * 256 + 2 * h) * 256 + 2 * w);
    float x00 = xp[0], x01 = xp[1], x10 = xp[256], x11 = xp[257];
    float* op = out + (((b * 32 + c * 4) * 128 + h) * 128 + w);
#pragma unroll
    for (int s = 0; s < 4; s++) {
        float v = x00 * Kd[s * 4 + 0] + x01 * Kd[s * 4 + 1]
                + x10 * Kd[s * 4 + 2] + x11 * Kd[s * 4 + 3];
        op[s * 128 * 128] = v;
    }
}

// ---------------------------------------------------------------------------
// IDWT: y[b,c,2h+d,2w+e] = sum_s in[b,c*4+s,h,w] * Kr[s,d,e]
// ---------------------------------------------------------------------------
__global__ void idwt2d_k(const float* __restrict__ in, const float* __restrict__ Kr,
                         float* __restrict__ out) {
    int idx = blockIdx.x * blockDim.x + threadIdx.x;       // over 16*4*128*128
    if (idx >= 16 * 4 * 128 * 128) return;
    int w = idx & 127;
    int h = (idx >> 7) & 127;
    int c = (idx >> 14) & 3;
    int b = idx >> 16;
    float v[4];
#pragma unroll
    for (int s = 0; s < 4; s++)
        v[s] = in[(((b * 16 + c * 4 + s) * 128 + h) * 128 + w)];
    float* op = out + (((b * 4 + c) * 256 + 2 * h) * 256 + 2 * w);
#pragma unroll
    for (int d = 0; d < 2; d++)
#pragma unroll
        for (int e = 0; e < 2; e++) {
            float y = v[0] * Kr[0 * 4 + d * 2 + e] + v[1] * Kr[1 * 4 + d * 2 + e]
                    + v[2] * Kr[2 * 4 + d * 2 + e] + v[3] * Kr[3 * 4 + d * 2 + e];
            op[d * 256 + e] = y;
        }
}

// ---------------------------------------------------------------------------
// Conv 3x3 stride 1 pad 1. Block 16x16 threads, each thread: 2x2 pixels x
// 4 output channels. Output tile per block = 32x32 pixels, 4 couts.
// grid: (W/32, H/32, B * Cout/4)
// ---------------------------------------------------------------------------
__global__ void conv3x3s1_k(const float* __restrict__ in, const float* __restrict__ wgt,
                            const float* __restrict__ bias, float* __restrict__ out,
                            int Cin, int Cout, int H, int W) {
    __shared__ float tile[34][35];
    __shared__ float wsh[4][9];
    int tx = threadIdx.x, ty = threadIdx.y;
    int tid = ty * 16 + tx;
    int x0 = blockIdx.x * 32, y0 = blockIdx.y * 32;
    int nz = Cout >> 2;
    int co0 = (blockIdx.z % nz) * 4;
    int b = blockIdx.z / nz;

    float acc[2][2][4];
#pragma unroll
    for (int i = 0; i < 2; i++)
#pragma unroll
        for (int j = 0; j < 2; j++)
#pragma unroll
            for (int k = 0; k < 4; k++) acc[i][j][k] = 0.f;

    for (int ci = 0; ci < Cin; ci++) {
        const float* ip = in + (long)((b * Cin + ci) * H) * W;
        for (int i = tid; i < 34 * 34; i += 256) {
            int r = i / 34, c = i % 34;
            int gy = y0 + r - 1, gx = x0 + c - 1;
            tile[r][c] = (gy >= 0 && gy < H && gx >= 0 && gx < W) ? ip[gy * W + gx] : 0.f;
        }
        if (tid < 36)
            wsh[tid / 9][tid % 9] = wgt[((co0 + tid / 9) * Cin + ci) * 9 + tid % 9];
        __syncthreads();

        float p[4][4];
#pragma unroll
        for (int r = 0; r < 4; r++)
#pragma unroll
            for (int c = 0; c < 4; c++) p[r][c] = tile[2 * ty + r][2 * tx + c];

#pragma unroll
        for (int kh = 0; kh < 3; kh++)
#pragma unroll
            for (int kw = 0; kw < 3; kw++) {
#pragma unroll
                for (int co = 0; co < 4; co++) {
                    float wv = wsh[co][kh * 3 + kw];
                    acc[0][0][co] += p[kh][kw] * wv;
                    acc[0][1][co] += p[kh][kw + 1] * wv;
                    acc[1][0][co] += p[kh + 1][kw] * wv;
                    acc[1][1][co] += p[kh + 1][kw + 1] * wv;
                }
            }
        __syncthreads();
    }

#pragma unroll
    for (int co = 0; co < 4; co++) {
        float bv = bias[co0 + co];
#pragma unroll
        for (int dy = 0; dy < 2; dy++)
#pragma unroll
            for (int dx = 0; dx < 2; dx++) {
                int oy = y0 + 2 * ty + dy, ox = x0 + 2 * tx + dx;
                out[(long)((b * Cout + co0 + co) * H + oy) * W + ox] = acc[dy][dx][co] + bv;
            }
    }
}

// ---------------------------------------------------------------------------
// Conv 3x3 stride 2 pad 1. Block 16x16 threads, 1 out pixel x 4 couts each.
// grid: (Wo/16, Ho/16, B * Cout/4). Hi = 2*Ho, Wi = 2*Wo.
// ---------------------------------------------------------------------------
__global__ void conv3x3s2_k(const float* __restrict__ in, const float* __restrict__ wgt,
                            const float* __restrict__ bias, float* __restrict__ out,
                            int Cin, int Cout, int Ho, int Wo) {
    __shared__ float tile[33][35];
    __shared__ float wsh[4][9];
    int Hi = Ho * 2, Wi = Wo * 2;
    int tx = threadIdx.x, ty = threadIdx.y;
    int tid = ty * 16 + tx;
    int x0 = blockIdx.x * 16, y0 = blockIdx.y * 16;
    int nz = Cout >> 2;
    int co0 = (blockIdx.z % nz) * 4;
    int b = blockIdx.z / nz;

    float acc[4] = {0.f, 0.f, 0.f, 0.f};

    for (int ci = 0; ci < Cin; ci++) {
        const float* ip = in + (long)((b * Cin + ci) * Hi) * Wi;
        for (int i = tid; i < 33 * 33; i += 256) {
            int r = i / 33, c = i % 33;
            int gy = 2 * y0 - 1 + r, gx = 2 * x0 - 1 + c;
            tile[r][c] = (gy >= 0 && gy < Hi && gx >= 0 && gx < Wi) ? ip[gy * Wi + gx] : 0.f;
        }
        if (tid < 36)
            wsh[tid / 9][tid % 9] = wgt[((co0 + tid / 9) * Cin + ci) * 9 + tid % 9];
        __syncthreads();

#pragma unroll
        for (int kh = 0; kh < 3; kh++)
#pragma unroll
            for (int kw = 0; kw < 3; kw++) {
                float v = tile[2 * ty + kh][2 * tx + kw];
#pragma unroll
                for (int co = 0; co < 4; co++) acc[co] += v * wsh[co][kh * 3 + kw];
            }
        __syncthreads();
    }

#pragma unroll
    for (int co = 0; co < 4; co++) {
        int oy = y0 + ty, ox = x0 + tx;
        out[(long)((b * Cout + co0 + co) * Ho + oy) * Wo + ox] = acc[co] + bias[co0 + co];
    }
}

// ---------------------------------------------------------------------------
// ConvTranspose 4x4 stride 2 pad 1: in [B,128,64,64] -> out [B,64,128,128].
// Wt layout: [Cin=128, Cout=64, 4, 4].
// y[oh,ow] contributions: kh with (oh+1-kh) even, ih=(oh+1-kh)/2 in range.
// Block 16x16 threads, 2x2 pixels x 4 couts. grid (4,4,16*16).
// ---------------------------------------------------------------------------
__global__ void convT4x4s2_k(const float* __restrict__ in, const float* __restrict__ wgt,
                             const float* __restrict__ bias, float* __restrict__ out) {
    const int Cin = 128, Cout = 64, Hi = 64, Wi = 64, Ho = 128, Wo = 128;
    __shared__ float itile[18][19];
    __shared__ float wsh[4][16];
    int tx = threadIdx.x, ty = threadIdx.y;
    int tid = ty * 16 + tx;
    int x0 = blockIdx.x * 32, y0 = blockIdx.y * 32;
    int co0 = (blockIdx.z % 16) * 4;
    int b = blockIdx.z / 16;
    int ihb = y0 / 2 - 1, iwb = x0 / 2 - 1;

    float acc[2][2][4];
#pragma unroll
    for (int i = 0; i < 2; i++)
#pragma unroll
        for (int j = 0; j < 2; j++)
#pragma unroll
            for (int k = 0; k < 4; k++) acc[i][j][k] = 0.f;

    for (int ci = 0; ci < Cin; ci++) {
        const float* ip = in + (long)((b * Cin + ci) * Hi) * Wi;
        for (int i = tid; i < 18 * 18; i += 256) {
            int r = i / 18, c = i % 18;
            int ih = ihb + r, iw = iwb + c;
            itile[r][c] = (ih >= 0 && ih < Hi && iw >= 0 && iw < Wi) ? ip[ih * Wi + iw] : 0.f;
        }
        if (tid < 64)
            wsh[tid / 16][tid % 16] = wgt[((long)ci * Cout + co0 + tid / 16) * 16 + tid % 16];
        __syncthreads();

        float p[3][3];
#pragma unroll
        for (int r = 0; r < 3; r++)
#pragma unroll
            for (int c = 0; c < 3; c++) p[r][c] = itile[ty + r][tx + c];

#pragma unroll
        for (int co = 0; co < 4; co++) {
            // pixel (dy=0,dx=0): kh in {1,3}, kw in {1,3}
            acc[0][0][co] += p[1][1] * wsh[co][5]  + p[1][0] * wsh[co][7]
                           + p[0][1] * wsh[co][13] + p[0][0] * wsh[co][15];
            // (0,1): kh {1,3}, kw {0,2}
            acc[0][1][co] += p[1][2] * wsh[co][4]  + p[1][1] * wsh[co][6]
                           + p[0][2] * wsh[co][12] + p[0][1] * wsh[co][14];
            // (1,0): kh {0,2}, kw {1,3}
            acc[1][0][co] += p[2][1] * wsh[co][1]  + p[2][0] * wsh[co][3]
                           + p[1][1] * wsh[co][9]  + p[1][0] * wsh[co][11];
            // (1,1): kh {0,2}, kw {0,2}
            acc[1][1][co] += p[2][2] * wsh[co][0]  + p[2][1] * wsh[co][2]
                           + p[1][2] * wsh[co][8]  + p[1][1] * wsh[co][10];
        }
        __syncthreads();
    }

#pragma unroll
    for (int co = 0; co < 4; co++) {
        float bv = bias[co0 + co];
#pragma unroll
        for (int dy = 0; dy < 2; dy++)
#pragma unroll
            for (int dx = 0; dx < 2; dx++) {
                int oy = y0 + 2 * ty + dy, ox = x0 + 2 * tx + dx;
                out[(long)((b * Cout + co0 + co) * Ho + oy) * Wo + ox] = acc[dy][dx][co] + bv;
            }
    }
}

// ---------------------------------------------------------------------------
// GroupNorm stats: one block per (b, g). mv[bg] = {mean, rstd}.
// ---------------------------------------------------------------------------
__global__ void gn_stats_k(const float* __restrict__ x, float* __restrict__ mv,
                           int C, int HW, int groups) {
    int bg = blockIdx.x;
    int g = bg % groups, b = bg / groups;
    int Cg = C / groups;
    long base = (long)(b * C + g * Cg) * HW;
    long n = (long)Cg * HW;
    long n4 = n >> 2;
    const float4* xp = (const float4*)(x + base);
    float s = 0.f, s2 = 0.f;
    for (long i = threadIdx.x; i < n4; i += blockDim.x) {
        float4 v = xp[i];
        s += v.x + v.y + v.z + v.w;
        s2 += v.x * v.x + v.y * v.y + v.z * v.z + v.w * v.w;
    }
    __shared__ float sh[512];
    int tid = threadIdx.x;
    sh[tid] = s;
    sh[256 + tid] = s2;
    __syncthreads();
    for (int o = 128; o > 0; o >>= 1) {
        if (tid < o) { sh[tid] += sh[tid + o]; sh[256 + tid] += sh[256 + tid + o]; }
        __syncthreads();
    }
    if (tid == 0) {
        float mean = sh[0] / (float)n;
        float var = sh[256] / (float)n - mean * mean;
        mv[bg * 2] = mean;
        mv[bg * 2 + 1] = rsqrtf(var + 1e-5f);
    }
}

// ---------------------------------------------------------------------------
// GroupNorm apply (+ optional relu), in place, float4-vectorized.
// ---------------------------------------------------------------------------
__global__ void gn_apply_k(float* __restrict__ x, const float* __restrict__ mv,
                           const float* __restrict__ gamma, const float* __restrict__ beta,
                           int C, int HW, int groups, int relu, int total4) {
    int i = blockIdx.x * blockDim.x + threadIdx.x;
    if (i >= total4) return;
    long e = (long)i * 4;
    int c = (int)((e / HW) % C);
    int b = (int)(e / ((long)HW * C));
    int g = c / (C / groups);
    float mean = mv[(b * groups + g) * 2];
    float rstd = mv[(b * groups + g) * 2 + 1];
    float ga = gamma[c] * rstd;
    float bb = beta[c] - mean * ga;
    float4 v = ((float4*)x)[i];
    v.x = v.x * ga + bb;
    v.y = v.y * ga + bb;
    v.z = v.z * ga + bb;
    v.w = v.w * ga + bb;
    if (relu) {
        v.x = fmaxf(v.x, 0.f); v.y = fmaxf(v.y, 0.f);
        v.z = fmaxf(v.z, 0.f); v.w = fmaxf(v.w, 0.f);
    }
    ((float4*)x)[i] = v;
}

// ---------------------------------------------------------------------------
// Launcher
// ---------------------------------------------------------------------------
static void run_gn(float* buf, const float* mvp, const float* gamma, const float* beta,
                   int C, int HW, int groups) {
    gn_stats_k<<<NB * groups, 256>>>(buf, (float*)mvp, C, HW, groups);
    int total4 = NB * C * HW / 4;
    gn_apply_k<<<(total4 + 255) / 256, 256>>>(buf, mvp, gamma, beta, C, HW, groups, 1, total4);
}

extern "C" void kernel_launch(void* const* d_in, const int* in_sizes, int n_in,
                              void* d_out, int out_size) {
    const float* x  = (const float*)d_in[0];
    const float* Kd = (const float*)d_in[1];
    const float* Kr = (const float*)d_in[2];
    const float* W1 = (const float*)d_in[3];  const float* b1 = (const float*)d_in[4];
    const float* g1 = (const float*)d_in[5];  const float* be1 = (const float*)d_in[6];
    const float* W2 = (const float*)d_in[7];  const float* b2 = (const float*)d_in[8];
    const float* g2 = (const float*)d_in[9];  const float* be2 = (const float*)d_in[10];
    const float* W3 = (const float*)d_in[11]; const float* b3 = (const float*)d_in[12];
    const float* g3 = (const float*)d_in[13]; const float* be3 = (const float*)d_in[14];
    const float* W4 = (const float*)d_in[15]; const float* b4 = (const float*)d_in[16];
    const float* g4 = (const float*)d_in[17]; const float* be4 = (const float*)d_in[18];
    const float* Wt = (const float*)d_in[19]; const float* bt = (const float*)d_in[20];
    const float* g5 = (const float*)d_in[21]; const float* be5 = (const float*)d_in[22];
    const float* W6 = (const float*)d_in[23]; const float* b6 = (const float*)d_in[24];
    float* out = (float*)d_out;

    void *p0, *pA, *pB, *pC, *pm;
    cudaGetSymbolAddress(&p0, g_s0);
    cudaGetSymbolAddress(&pA, g_sA);
    cudaGetSymbolAddress(&pB, g_sB);
    cudaGetSymbolAddress(&pC, g_sC);
    cudaGetSymbolAddress(&pm, g_mv);
    float* s0 = (float*)p0;
    float* sA = (float*)pA;
    float* sB = (float*)pB;
    float* sC = (float*)pC;
    float* mv = (float*)pm;

    dim3 blk2d(16, 16);

    // DWT: x -> s0 [16,32,128,128]
    dwt2d_k<<<(16 * 8 * 128 * 128) / 256, 256>>>(x, Kd, s0);

    // conv1: 32->64 @128 -> sC, GN8+relu
    conv3x3s1_k<<<dim3(4, 4, NB * (64 / 4)), blk2d>>>(s0, W1, b1, sC, 32, 64, 128, 128);
    run_gn(sC, mv, g1, be1, 64, 128 * 128, 8);

    // conv2: 64->128 s2 -> sB @64, GN16+relu
    conv3x3s2_k<<<dim3(4, 4, NB * (128 / 4)), blk2d>>>(sC, W2, b2, sB, 64, 128, 64, 64);
    run_gn(sB, mv, g2, be2, 128, 64 * 64, 16);

    // conv3: 128->256 @64 -> sA, GN32+relu
    conv3x3s1_k<<<dim3(2, 2, NB * (256 / 4)), blk2d>>>(sB, W3, b3, sA, 128, 256, 64, 64);
    run_gn(sA, mv, g3, be3, 256, 64 * 64, 32);

    // conv4: 256->128 @64 -> sB, GN16+relu
    conv3x3s1_k<<<dim3(2, 2, NB * (128 / 4)), blk2d>>>(sA, W4, b4, sB, 256, 128, 64, 64);
    run_gn(sB, mv, g4, be4, 128, 64 * 64, 16);

    // convT: 128->64 x2 -> sC @128, GN8+relu
    convT4x4s2_k<<<dim3(4, 4, NB * 16), blk2d>>>(sB, Wt, bt, sC);
    run_gn(sC, mv, g5, be5, 64, 128 * 128, 8);

    // conv6: 64->16 @128 -> s0 (no GN/relu)
    conv3x3s1_k<<<dim3(4, 4, NB * (16 / 4)), blk2d>>>(sC, W6, b6, s0, 64, 16, 128, 128);

    // IDWT: s0 -> out [16,4,256,256]
    idwt2d_k<<<(16 * 4 * 128 * 128) / 256, 256>>>(s0, Kr, out);
}

// round 3
// speedup vs baseline: 1.0030x; 1.0030x over previous
#include <cuda_runtime.h>

// ---------------------------------------------------------------------------
// WaveletDiffusion, round 1: fp32 direct convs using packed f32x2 FMA (FFMA2)
// which runs at 2x the rate of scalar FFMA on sm_103a.
// ---------------------------------------------------------------------------

#define NB 16
typedef unsigned long long ull;

__device__ float g_s0[16 * 32 * 128 * 128];
__device__ float g_sA[16 * 256 * 64 * 64];
__device__ float g_sB[16 * 128 * 64 * 64];
__device__ float g_sC[16 * 64 * 128 * 128];
__device__ float g_mv[1024];

__device__ __forceinline__ ull pk(float lo, float hi) {
    ull r; asm("mov.b64 %0, {%1,%2};" : "=l"(r) : "f"(lo), "f"(hi)); return r;
}
__device__ __forceinline__ void fma2(ull& d, ull a, ull b) {
    asm("fma.rn.f32x2 %0, %1, %2, %0;" : "+l"(d) : "l"(a), "l"(b));
}
__device__ __forceinline__ float2 upk(ull v) {
    float2 r; asm("mov.b64 {%0,%1}, %2;" : "=f"(r.x), "=f"(r.y) : "l"(v)); return r;
}

// ---------------------------------------------------------------------------
// DWT
// ---------------------------------------------------------------------------
__global__ void dwt2d_k(const float* __restrict__ x, const float* __restrict__ Kd,
                        float* __restrict__ out) {
    int idx = blockIdx.x * blockDim.x + threadIdx.x;
    if (idx >= 16 * 8 * 128 * 128) return;
    int w = idx & 127;
    int h = (idx >> 7) & 127;
    int c = (idx >> 14) & 7;
    int b = idx >> 17;
    const float* xp = x + (((b * 8 + c) * 256 + 2 * h) * 256 + 2 * w);
    float x00 = xp[0], x01 = xp[1], x10 = xp[256], x11 = xp[257];
    float* op = out + (((b * 32 + c * 4) * 128 + h) * 128 + w);
#pragma unroll
    for (int s = 0; s < 4; s++) {
        float v = x00 * Kd[s * 4 + 0] + x01 * Kd[s * 4 + 1]
                + x10 * Kd[s * 4 + 2] + x11 * Kd[s * 4 + 3];
        op[s * 128 * 128] = v;
    }
}

// ---------------------------------------------------------------------------
// IDWT
// ---------------------------------------------------------------------------
__global__ void idwt2d_k(const float* __restrict__ in, const float* __restrict__ Kr,
                         float* __restrict__ out) {
    int idx = blockIdx.x * blockDim.x + threadIdx.x;
    if (idx >= 16 * 4 * 128 * 128) return;
    int w = idx & 127;
    int h = (idx >> 7) & 127;
    int c = (idx >> 14) & 3;
    int b = idx >> 16;
    float v[4];
#pragma unroll
    for (int s = 0; s < 4; s++)
        v[s] = in[(((b * 16 + c * 4 + s) * 128 + h) * 128 + w)];
    float* op = out + (((b * 4 + c) * 256 + 2 * h) * 256 + 2 * w);
#pragma unroll
    for (int d = 0; d < 2; d++)
#pragma unroll
        for (int e = 0; e < 2; e++) {
            float y = v[0] * Kr[0 * 4 + d * 2 + e] + v[1] * Kr[1 * 4 + d * 2 + e]
                    + v[2] * Kr[2 * 4 + d * 2 + e] + v[3] * Kr[3 * 4 + d * 2 + e];
            op[d * 256 + e] = y;
        }
}

// ---------------------------------------------------------------------------
// Conv 3x3 s1 p1, FFMA2. Block 16x16 threads; thread = 4 wide x 2 high x 4 co.
// Block tile: 64x32 pixels, 4 couts. grid (W/64, H/32, B*Cout/4).
// Double-buffered smem, 1 barrier per cin.
// ---------------------------------------------------------------------------
__global__ __launch_bounds__(256, 2)
void conv3x3s1_k(const float* __restrict__ in, const float* __restrict__ wgt,
                 const float* __restrict__ bias, float* __restrict__ out,
                 int Cin, int Cout, int H, int W) {
    __shared__ __align__(16) float tile[2][34][68];
    __shared__ __align__(16) float2 wsh[2][4][9];
    int tx = threadIdx.x, ty = threadIdx.y;
    int tid = ty * 16 + tx;
    int x0 = blockIdx.x * 64, y0 = blockIdx.y * 32;
    int nz = Cout >> 2;
    int co0 = (blockIdx.z % nz) * 4;
    int b = blockIdx.z / nz;

    ull acc[2][2][4];   // [dy][pair j][co]
#pragma unroll
    for (int dy = 0; dy < 2; dy++)
#pragma unroll
        for (int j = 0; j < 2; j++)
#pragma unroll
            for (int co = 0; co < 4; co++) acc[dy][j][co] = 0ull;

    for (int ci = 0; ci < Cin; ci++) {
        int buf = ci & 1;
        const float* ip = in + (long)((b * Cin + ci) * H) * W;
        for (int i = tid; i < 34 * 66; i += 256) {
            int r = i / 66, c = i % 66;
            int gy = y0 + r - 1, gx = x0 + c - 1;
            tile[buf][r][c] = (gy >= 0 && gy < H && gx >= 0 && gx < W) ? ip[gy * W + gx] : 0.f;
        }
        if (tid < 36) {
            int co = tid / 9, e = tid % 9;
            float w = wgt[((co0 + co) * Cin + ci) * 9 + e];
            wsh[buf][co][e] = make_float2(w, w);
        }
        __syncthreads();

        ull P[4][5];
#pragma unroll
        for (int r = 0; r < 4; r++) {
            const float* rp = &tile[buf][2 * ty + r][4 * tx];
            float4 v0 = *(const float4*)rp;
            float2 v1 = *(const float2*)(rp + 4);
            P[r][0] = pk(v0.x, v0.y);
            P[r][1] = pk(v0.y, v0.z);
            P[r][2] = pk(v0.z, v0.w);
            P[r][3] = pk(v0.w, v1.x);
            P[r][4] = pk(v1.x, v1.y);
        }

#pragma unroll
        for (int co = 0; co < 4; co++)
#pragma unroll
            for (int kh = 0; kh < 3; kh++)
#pragma unroll
                for (int kw = 0; kw < 3; kw++) {
                    ull w2 = *(const ull*)&wsh[buf][co][kh * 3 + kw];
                    fma2(acc[0][0][co], P[kh][kw], w2);
                    fma2(acc[0][1][co], P[kh][kw + 2], w2);
                    fma2(acc[1][0][co], P[kh + 1][kw], w2);
                    fma2(acc[1][1][co], P[kh + 1][kw + 2], w2);
                }
        // (buffer parity provides the second ordering point; one barrier/cin)
    }

#pragma unroll
    for (int co = 0; co < 4; co++) {
        float bv = bias[co0 + co];
#pragma unroll
        for (int dy = 0; dy < 2; dy++) {
            float2 a = upk(acc[dy][0][co]);
            float2 c2 = upk(acc[dy][1][co]);
            float4 o = make_float4(a.x + bv, a.y + bv, c2.x + bv, c2.y + bv);
            *(float4*)&out[(long)((b * Cout + co0 + co) * H + y0 + 2 * ty + dy) * W + x0 + 4 * tx] = o;
        }
    }
}

// ---------------------------------------------------------------------------
// Conv 3x3 s2 p1, FFMA2. Block 16x16; thread = 4 wide x 1 high x 4 co.
// Block out tile 64x16. grid (Wo/64, Ho/16, B*Cout/4). Hi=2Ho, Wi=2Wo.
// ---------------------------------------------------------------------------
__global__ __launch_bounds__(256, 2)
void conv3x3s2_k(const float* __restrict__ in, const float* __restrict__ wgt,
                 const float* __restrict__ bias, float* __restrict__ out,
                 int Cin, int Cout, int Ho, int Wo) {
    __shared__ __align__(16) float tile[33][132];
    __shared__ __align__(16) float2 wsh[4][9];
    int Hi = Ho * 2, Wi = Wo * 2;
    int tx = threadIdx.x, ty = threadIdx.y;
    int tid = ty * 16 + tx;
    int x0 = blockIdx.x * 64, y0 = blockIdx.y * 16;
    int nz = Cout >> 2;
    int co0 = (blockIdx.z % nz) * 4;
    int b = blockIdx.z / nz;

    ull accA[4], accB[4];
#pragma unroll
    for (int co = 0; co < 4; co++) { accA[co] = 0ull; accB[co] = 0ull; }

    for (int ci = 0; ci < Cin; ci++) {
        const float* ip = in + (long)((b * Cin + ci) * Hi) * Wi;
        for (int i = tid; i < 33 * 130; i += 256) {
            int r = i / 130, c = i % 130;
            int gy = 2 * y0 + r - 1, gx = 2 * x0 + c - 1;
            tile[r][c] = (gy >= 0 && gy < Hi && gx >= 0 && gx < Wi) ? ip[gy * Wi + gx] : 0.f;
        }
        if (tid < 36) {
            int co = tid / 9, e = tid % 9;
            float w = wgt[((co0 + co) * Cin + ci) * 9 + e];
            wsh[co][e] = make_float2(w, w);
        }
        __syncthreads();

        ull P[3][6];
#pragma unroll
        for (int r = 0; r < 3; r++) {
            const float* rp = &tile[2 * ty + r][8 * tx];
            float4 v0 = *(const float4*)rp;
            float4 v1 = *(const float4*)(rp + 4);
            float v8 = rp[8];
            P[r][0] = pk(v0.x, v0.z);
            P[r][1] = pk(v0.y, v0.w);
            P[r][2] = pk(v0.z, v1.x);
            P[r][3] = pk(v1.x, v1.z);
            P[r][4] = pk(v1.y, v1.w);
            P[r][5] = pk(v1.z, v8);
        }

#pragma unroll
        for (int co = 0; co < 4; co++)
#pragma unroll
            for (int kh = 0; kh < 3; kh++)
#pragma unroll
                for (int kw = 0; kw < 3; kw++) {
                    ull w2 = *(const ull*)&wsh[co][kh * 3 + kw];
                    fma2(accA[co], P[kh][kw], w2);
                    fma2(accB[co], P[kh][kw + 3], w2);
                }
        __syncthreads();
    }

    int oy = y0 + ty;
#pragma unroll
    for (int co = 0; co < 4; co++) {
        float bv = bias[co0 + co];
        float2 a = upk(accA[co]);
        float2 c2 = upk(accB[co]);
        float4 o = make_float4(a.x + bv, a.y + bv, c2.x + bv, c2.y + bv);
        *(float4*)&out[(long)((b * Cout + co0 + co) * Ho + oy) * Wo + x0 + 4 * tx] = o;
    }
}

// ---------------------------------------------------------------------------
// ConvTranspose 4x4 s2 p1: [B,128,64,64] -> [B,64,128,128], FFMA2.
// Block 16x16; thread = 4 wide x 2 high x 8 co. Block out tile 64x32.
// grid (2, 4, B * Cout/8). Weight pairs are packed (odd-kw, even-kw) per term.
// ---------------------------------------------------------------------------
__global__ __launch_bounds__(256, 2)
void convT4x4s2_k(const float* __restrict__ in, const float* __restrict__ wgt,
                  const float* __restrict__ bias, float* __restrict__ out) {
    const int Cin = 128, Cout = 64, Hi = 64, Wi = 64, Ho = 128, Wo = 128;
    __shared__ __align__(16) float itile[18][36];
    __shared__ __align__(16) float2 wsh[8][8];
    int tx = threadIdx.x, ty = threadIdx.y;
    int tid = ty * 16 + tx;
    int x0 = blockIdx.x * 64, y0 = blockIdx.y * 32;
    int co0 = (blockIdx.z & 7) * 8;
    int b = blockIdx.z >> 3;
    int ihb = y0 / 2 - 1, iwb = x0 / 2 - 1;

    // weight-pair element tables: (odd kw -> lo lane, even kw -> hi lane)
    const int ehi[8] = {5, 7, 13, 15, 1, 3, 9, 11};
    const int elo[8] = {4, 6, 12, 14, 0, 2, 8, 10};

    ull accA[2][8], accB[2][8];
#pragma unroll
    for (int dy = 0; dy < 2; dy++)
#pragma unroll
        for (int co = 0; co < 8; co++) { accA[dy][co] = 0ull; accB[dy][co] = 0ull; }

    for (int ci = 0; ci < Cin; ci++) {
        const float* ip = in + (long)((b * Cin + ci) * Hi) * Wi;
        for (int i = tid; i < 18 * 34; i += 256) {
            int r = i / 34, c = i % 34;
            int ih = ihb + r, iw = iwb + c;
            itile[r][c] = (ih >= 0 && ih < Hi && iw >= 0 && iw < Wi) ? ip[ih * Wi + iw] : 0.f;
        }
        if (tid < 64) {
            int co = tid >> 3, e = tid & 7;
            const float* wp = wgt + ((long)ci * Cout + co0 + co) * 16;
            wsh[co][e] = make_float2(wp[ehi[e]], wp[elo[e]]);
        }
        __syncthreads();

        ull Q[3][3];
#pragma unroll
        for (int r = 0; r < 3; r++) {
            const float* rp = &itile[ty + r][2 * tx];
            float2 v0 = *(const float2*)rp;
            float2 v1 = *(const float2*)(rp + 2);
            Q[r][0] = pk(v0.x, v0.y);
            Q[r][1] = pk(v0.y, v1.x);
            Q[r][2] = pk(v1.x, v1.y);
        }

#pragma unroll
        for (int co = 0; co < 8; co++) {
            ull e0 = *(const ull*)&wsh[co][0];
            ull e1 = *(const ull*)&wsh[co][1];
            ull e2 = *(const ull*)&wsh[co][2];
            ull e3 = *(const ull*)&wsh[co][3];
            ull e4 = *(const ull*)&wsh[co][4];
            ull e5 = *(const ull*)&wsh[co][5];
            ull e6 = *(const ull*)&wsh[co][6];
            ull e7 = *(const ull*)&wsh[co][7];
            fma2(accA[0][co], Q[1][1], e0); fma2(accA[0][co], Q[1][0], e1);
            fma2(accA[0][co], Q[0][1], e2); fma2(accA[0][co], Q[0][0], e3);
            fma2(accA[1][co], Q[2][1], e4); fma2(accA[1][co], Q[2][0], e5);
            fma2(accA[1][co], Q[1][1], e6); fma2(accA[1][co], Q[1][0], e7);
            fma2(accB[0][co], Q[1][2], e0); fma2(accB[0][co], Q[1][1], e1);
            fma2(accB[0][co], Q[0][2], e2); fma2(accB[0][co], Q[0][1], e3);
            fma2(accB[1][co], Q[2][2], e4); fma2(accB[1][co], Q[2][1], e5);
            fma2(accB[1][co], Q[1][2], e6); fma2(accB[1][co], Q[1][1], e7);
        }
        __syncthreads();
    }

#pragma unroll
    for (int co = 0; co < 8; co++) {
        float bv = bias[co0 + co];
#pragma unroll
        for (int dy = 0; dy < 2; dy++) {
            float2 a = upk(accA[dy][co]);
            float2 c2 = upk(accB[dy][co]);
            float4 o = make_float4(a.x + bv, a.y + bv, c2.x + bv, c2.y + bv);
            *(float4*)&out[(long)((b * Cout + co0 + co) * Ho + y0 + 2 * ty + dy) * Wo + x0 + 4 * tx] = o;
        }
    }
}

// ---------------------------------------------------------------------------
// GroupNorm
// ---------------------------------------------------------------------------
__global__ void gn_stats_k(const float* __restrict__ x, float* __restrict__ mv,
                           int C, int HW, int groups) {
    int bg = blockIdx.x;
    int g = bg % groups, b = bg / groups;
    int Cg = C / groups;
    long base = (long)(b * C + g * Cg) * HW;
    long n = (long)Cg * HW;
    long n4 = n >> 2;
    const float4* xp = (const float4*)(x + base);
    float s = 0.f, s2 = 0.f;
    for (long i = threadIdx.x; i < n4; i += blockDim.x) {
        float4 v = xp[i];
        s += v.x + v.y + v.z + v.w;
        s2 += v.x * v.x + v.y * v.y + v.z * v.z + v.w * v.w;
    }
    __shared__ float sh[512];
    int tid = threadIdx.x;
    sh[tid] = s;
    sh[256 + tid] = s2;
    __syncthreads();
    for (int o = 128; o > 0; o >>= 1) {
        if (tid < o) { sh[tid] += sh[tid + o]; sh[256 + tid] += sh[256 + tid + o]; }
        __syncthreads();
    }
    if (tid == 0) {
        float mean = sh[0] / (float)n;
        float var = sh[256] / (float)n - mean * mean;
        mv[bg * 2] = mean;
        mv[bg * 2 + 1] = rsqrtf(var + 1e-5f);
    }
}

__global__ void gn_apply_k(float* __restrict__ x, const float* __restrict__ mv,
                           const float* __restrict__ gamma, const float* __restrict__ beta,
                           int C, int HW, int groups, int relu, int total4) {
    int i = blockIdx.x * blockDim.x + threadIdx.x;
    if (i >= total4) return;
    long e = (long)i * 4;
    int c = (int)((e / HW) % C);
    int b = (int)(e / ((long)HW * C));
    int g = c / (C / groups);
    float mean = mv[(b * groups + g) * 2];
    float rstd = mv[(b * groups + g) * 2 + 1];
    float ga = gamma[c] * rstd;
    float bb = beta[c] - mean * ga;
    float4 v = ((float4*)x)[i];
    v.x = v.x * ga + bb;
    v.y = v.y * ga + bb;
    v.z = v.z * ga + bb;
    v.w = v.w * ga + bb;
    if (relu) {
        v.x = fmaxf(v.x, 0.f); v.y = fmaxf(v.y, 0.f);
        v.z = fmaxf(v.z, 0.f); v.w = fmaxf(v.w, 0.f);
    }
    ((float4*)x)[i] = v;
}

// ---------------------------------------------------------------------------
// Launcher
// ---------------------------------------------------------------------------
static void run_gn(float* buf, const float* mvp, const float* gamma, const float* beta,
                   int C, int HW, int groups) {
    gn_stats_k<<<NB * groups, 256>>>(buf, (float*)mvp, C, HW, groups);
    int total4 = NB * C * HW / 4;
    gn_apply_k<<<(total4 + 255) / 256, 256>>>(buf, mvp, gamma, beta, C, HW, groups, 1, total4);
}

extern "C" void kernel_launch(void* const* d_in, const int* in_sizes, int n_in,
                              void* d_out, int out_size) {
    const float* x  = (const float*)d_in[0];
    const float* Kd = (const float*)d_in[1];
    const float* Kr = (const float*)d_in[2];
    const float* W1 = (const float*)d_in[3];  const float* b1 = (const float*)d_in[4];
    const float* g1 = (const float*)d_in[5];  const float* be1 = (const float*)d_in[6];
    const float* W2 = (const float*)d_in[7];  const float* b2 = (const float*)d_in[8];
    const float* g2 = (const float*)d_in[9];  const float* be2 = (const float*)d_in[10];
    const float* W3 = (const float*)d_in[11]; const float* b3 = (const float*)d_in[12];
    const float* g3 = (const float*)d_in[13]; const float* be3 = (const float*)d_in[14];
    const float* W4 = (const float*)d_in[15]; const float* b4 = (const float*)d_in[16];
    const float* g4 = (const float*)d_in[17]; const float* be4 = (const float*)d_in[18];
    const float* Wt = (const float*)d_in[19]; const float* bt = (const float*)d_in[20];
    const float* g5 = (const float*)d_in[21]; const float* be5 = (const float*)d_in[22];
    const float* W6 = (const float*)d_in[23]; const float* b6 = (const float*)d_in[24];
    float* out = (float*)d_out;

    void *p0, *pA, *pB, *pC, *pm;
    cudaGetSymbolAddress(&p0, g_s0);
    cudaGetSymbolAddress(&pA, g_sA);
    cudaGetSymbolAddress(&pB, g_sB);
    cudaGetSymbolAddress(&pC, g_sC);
    cudaGetSymbolAddress(&pm, g_mv);
    float* s0 = (float*)p0;
    float* sA = (float*)pA;
    float* sB = (float*)pB;
    float* sC = (float*)pC;
    float* mv = (float*)pm;

    dim3 blk(16, 16);

    // DWT: x -> s0 [16,32,128,128]
    dwt2d_k<<<(16 * 8 * 128 * 128) / 256, 256>>>(x, Kd, s0);

    // conv1: 32->64 @128 -> sC
    conv3x3s1_k<<<dim3(2, 4, NB * 16), blk>>>(s0, W1, b1, sC, 32, 64, 128, 128);
    run_gn(sC, mv, g1, be1, 64, 128 * 128, 8);

    // conv2: 64->128 s2 -> sB @64
    conv3x3s2_k<<<dim3(1, 4, NB * 32), blk>>>(sC, W2, b2, sB, 64, 128, 64, 64);
    run_gn(sB, mv, g2, be2, 128, 64 * 64, 16);

    // conv3: 128->256 @64 -> sA
    conv3x3s1_k<<<dim3(1, 2, NB * 64), blk>>>(sB, W3, b3, sA, 128, 256, 64, 64);
    run_gn(sA, mv, g3, be3, 256, 64 * 64, 32);

    // conv4: 256->128 @64 -> sB
    conv3x3s1_k<<<dim3(1, 2, NB * 32), blk>>>(sA, W4, b4, sB, 256, 128, 64, 64);
    run_gn(sB, mv, g4, be4, 128, 64 * 64, 16);

    // convT: 128->64 x2 -> sC @128
    convT4x4s2_k<<<dim3(2, 4, NB * 8), blk>>>(sB, Wt, bt, sC);
    run_gn(sC, mv, g5, be5, 64, 128 * 128, 8);

    // conv6: 64->16 @128 -> s0
    conv3x3s1_k<<<dim3(2, 4, NB * 4), blk>>>(sC, W6, b6, s0, 64, 16, 128, 128);

    // IDWT
    idwt2d_k<<<(16 * 4 * 128 * 128) / 256, 256>>>(s0, Kr, out);
}

// round 4
// speedup vs baseline: 1.9217x; 1.9160x over previous
#include <cuda_runtime.h>

// ---------------------------------------------------------------------------
// WaveletDiffusion, round 3: implicit-GEMM convs on tensor cores
// (mma.sync.m16n8k8.tf32) with 3xTF32 hi/lo split for fp32-class accuracy.
// ---------------------------------------------------------------------------

#define NB 16

__device__ float g_s0[16 * 32 * 128 * 128];
__device__ float g_sA[16 * 256 * 64 * 64];
__device__ float g_sB[16 * 128 * 64 * 64];
__device__ float g_sC[16 * 64 * 128 * 128];
__device__ float g_wrep[4 * 64 * 512];     // repacked convT weights, per class
__device__ float g_mv[1024];

__device__ __forceinline__ float tf32r(float x) {
    unsigned u;
    asm("cvt.rna.tf32.f32 %0, %1;" : "=r"(u) : "f"(x));
    return __uint_as_float(u);
}

__device__ __forceinline__ void mma8(float* c, const unsigned* a, unsigned b0, unsigned b1) {
    asm volatile(
        "mma.sync.aligned.m16n8k8.row.col.f32.tf32.tf32.f32 "
        "{%0,%1,%2,%3}, {%4,%5,%6,%7}, {%8,%9}, {%0,%1,%2,%3};"
        : "+f"(c[0]), "+f"(c[1]), "+f"(c[2]), "+f"(c[3])
        : "r"(a[0]), "r"(a[1]), "r"(a[2]), "r"(a[3]), "r"(b0), "r"(b1));
}

// ---------------------------------------------------------------------------
// DWT / IDWT (unchanged, memory-bound)
// ---------------------------------------------------------------------------
__global__ void dwt2d_k(const float* __restrict__ x, const float* __restrict__ Kd,
                        float* __restrict__ out) {
    int idx = blockIdx.x * blockDim.x + threadIdx.x;
    if (idx >= 16 * 8 * 128 * 128) return;
    int w = idx & 127;
    int h = (idx >> 7) & 127;
    int c = (idx >> 14) & 7;
    int b = idx >> 17;
    const float* xp = x + (((b * 8 + c) * 256 + 2 * h) * 256 + 2 * w);
    float x00 = xp[0], x01 = xp[1], x10 = xp[256], x11 = xp[257];
    float* op = out + (((b * 32 + c * 4) * 128 + h) * 128 + w);
#pragma unroll
    for (int s = 0; s < 4; s++) {
        float v = x00 * Kd[s * 4 + 0] + x01 * Kd[s * 4 + 1]
                + x10 * Kd[s * 4 + 2] + x11 * Kd[s * 4 + 3];
        op[s * 128 * 128] = v;
    }
}

__global__ void idwt2d_k(const float* __restrict__ in, const float* __restrict__ Kr,
                         float* __restrict__ out) {
    int idx = blockIdx.x * blockDim.x + threadIdx.x;
    if (idx >= 16 * 4 * 128 * 128) return;
    int w = idx & 127;
    int h = (idx >> 7) & 127;
    int c = (idx >> 14) & 3;
    int b = idx >> 16;
    float v[4];
#pragma unroll
    for (int s = 0; s < 4; s++)
        v[s] = in[(((b * 16 + c * 4 + s) * 128 + h) * 128 + w)];
    float* op = out + (((b * 4 + c) * 256 + 2 * h) * 256 + 2 * w);
#pragma unroll
    for (int d = 0; d < 2; d++)
#pragma unroll
        for (int e = 0; e < 2; e++) {
            float y = v[0] * Kr[0 * 4 + d * 2 + e] + v[1] * Kr[1 * 4 + d * 2 + e]
                    + v[2] * Kr[2 * 4 + d * 2 + e] + v[3] * Kr[3 * 4 + d * 2 + e];
            op[d * 256 + e] = y;
        }
}

// ---------------------------------------------------------------------------
// Implicit-GEMM conv. Tile: M=64 couts x N=128 pixels (32w x 4h), K-stage 32.
// 8 warps as 2(M) x 4(N); warp tile M=32 x N=32 via 2x4 m16n8k8 mmas.
// 3xTF32: acc += Ah*Bh + Ah*Bl + Al*Bh.
//   KS: kernel size (3 or 2), STRIDE: output->input stride,
//   SGN: sign on kernel-offset in input coord, ILV: interleave-store (convT).
//   Input coord: iy = (y0+py)*STRIDE + SGN*(e/KS) + OY, ix analog.
// Weights: A[m][k] = wgt[m*K + k]  (K = Cin*KS*KS).
// ---------------------------------------------------------------------------
template <int KS, int STRIDE, int SGN, int ILV>
__global__ __launch_bounds__(256, 2)
void conv_gemm_k(const float* __restrict__ in, const float* __restrict__ wgt,
                 const float* __restrict__ bias, float* __restrict__ out,
                 int Cin, int Cout, int H, int W, int Hi, int Wi, int OY, int OX) {
    const int K = Cin * KS * KS;
    __shared__ float As[2][64][36];    // [hi/lo][m][k]   (stride 36: conflict-free)
    __shared__ float Bs[2][32][136];   // [hi/lo][k][n]   (stride 136: conflict-free)

    int tid = threadIdx.x;
    int warp = tid >> 5, lane = tid & 31;
    int nx = W >> 5;
    int x0 = (blockIdx.x % nx) * 32, y0 = (blockIdx.x / nx) * 4;
    int co0 = blockIdx.y * 64;
    int b = blockIdx.z;
    int wm = warp >> 2, wn = warp & 3;

    float acc[2][4][4];
#pragma unroll
    for (int mt = 0; mt < 2; mt++)
#pragma unroll
        for (int nt = 0; nt < 4; nt++)
#pragma unroll
            for (int i = 0; i < 4; i++) acc[mt][nt][i] = 0.f;

    const float* inb = in + (long)b * Cin * Hi * Wi;

    for (int kk = 0; kk < K; kk += 32) {
        // fill A: 64 rows x 32 k
#pragma unroll
        for (int i = 0; i < 8; i++) {
            int idx = tid + i * 256;
            int m = idx >> 5, k = idx & 31;
            float v = 0.f;
            if (co0 + m < Cout) v = wgt[(long)(co0 + m) * K + kk + k];
            float hi = tf32r(v);
            As[0][m][k] = hi;
            As[1][m][k] = tf32r(v - hi);
        }
        // fill B: 32 k-rows x 128 pixels (on-the-fly im2col)
#pragma unroll
        for (int i = 0; i < 16; i++) {
            int idx = tid + i * 256;
            int kr = idx >> 7, p = idx & 127;
            int k = kk + kr;
            int ci = k / (KS * KS), e = k % (KS * KS);
            int dh = e / KS, dw = e % KS;
            int py = p >> 5, px = p & 31;
            int iy = (y0 + py) * STRIDE + SGN * dh + OY;
            int ix = (x0 + px) * STRIDE + SGN * dw + OX;
            float v = 0.f;
            if (iy >= 0 && iy < Hi && ix >= 0 && ix < Wi)
                v = inb[((long)ci * Hi + iy) * Wi + ix];
            float hi = tf32r(v);
            Bs[0][kr][p] = hi;
            Bs[1][kr][p] = tf32r(v - hi);
        }
        __syncthreads();

#pragma unroll
        for (int ks = 0; ks < 4; ks++) {
            int k0 = ks * 8;
            unsigned ah[2][4], al[2][4];
#pragma unroll
            for (int mt = 0; mt < 2; mt++) {
                int r = wm * 32 + mt * 16 + (lane >> 2);
                int c = k0 + (lane & 3);
                ah[mt][0] = __float_as_uint(As[0][r][c]);
                ah[mt][1] = __float_as_uint(As[0][r + 8][c]);
                ah[mt][2] = __float_as_uint(As[0][r][c + 4]);
                ah[mt][3] = __float_as_uint(As[0][r + 8][c + 4]);
                al[mt][0] = __float_as_uint(As[1][r][c]);
                al[mt][1] = __float_as_uint(As[1][r + 8][c]);
                al[mt][2] = __float_as_uint(As[1][r][c + 4]);
                al[mt][3] = __float_as_uint(As[1][r + 8][c + 4]);
            }
#pragma unroll
            for (int nt = 0; nt < 4; nt++) {
                int col = wn * 32 + nt * 8 + (lane >> 2);
                int kr = k0 + (lane & 3);
                unsigned bh0 = __float_as_uint(Bs[0][kr][col]);
                unsigned bh1 = __float_as_uint(Bs[0][kr + 4][col]);
                unsigned bl0 = __float_as_uint(Bs[1][kr][col]);
                unsigned bl1 = __float_as_uint(Bs[1][kr + 4][col]);
#pragma unroll
                for (int mt = 0; mt < 2; mt++) {
                    mma8(acc[mt][nt], ah[mt], bh0, bh1);
                    mma8(acc[mt][nt], ah[mt], bl0, bl1);
                    mma8(acc[mt][nt], al[mt], bh0, bh1);
                }
            }
        }
        __syncthreads();
    }

    // store with bias
#pragma unroll
    for (int mt = 0; mt < 2; mt++) {
#pragma unroll
        for (int nt = 0; nt < 4; nt++) {
            int p = wn * 32 + nt * 8 + (lane & 3) * 2;
            int py = p >> 5, px = p & 31;
#pragma unroll
            for (int half = 0; half < 2; half++) {
                int row = co0 + wm * 32 + mt * 16 + (lane >> 2) + half * 8;
                if (row >= Cout) continue;
                float bv = bias[row];
                float v0 = acc[mt][nt][half * 2 + 0] + bv;
                float v1 = acc[mt][nt][half * 2 + 1] + bv;
                if (ILV) {
                    int oy = 2 * (y0 + py) + OY;
                    long base = ((long)(b * Cout + row) * (2 * H) + oy) * (2 * W);
                    out[base + 2 * (x0 + px) + OX] = v0;
                    out[base + 2 * (x0 + px + 1) + OX] = v1;
                } else {
                    long base = ((long)(b * Cout + row) * H + y0 + py) * W;
                    *(float2*)&out[base + x0 + px] = make_float2(v0, v1);
                }
            }
        }
    }
}

// ---------------------------------------------------------------------------
// convT weight repack: Wrep[cls][co][ci*4 + u*2+v]
//   = Wt[ci][co][((1-dy)+2u)*4 + (1-dx)+2v],   cls = dy*2+dx
// ---------------------------------------------------------------------------
__global__ void wrep_k(const float* __restrict__ Wt, float* __restrict__ Wrep) {
    int idx = blockIdx.x * blockDim.x + threadIdx.x;   // 4*64*512
    if (idx >= 4 * 64 * 512) return;
    int e = idx & 3;
    int ci = (idx >> 2) & 127;
    int co = (idx >> 9) & 63;
    int cls = idx >> 15;
    int dy = cls >> 1, dx = cls & 1;
    int u = e >> 1, v = e & 1;
    Wrep[idx] = Wt[((long)ci * 64 + co) * 16 + ((1 - dy) + 2 * u) * 4 + (1 - dx) + 2 * v];
}

// ---------------------------------------------------------------------------
// GroupNorm (unchanged)
// ---------------------------------------------------------------------------
__global__ void gn_stats_k(const float* __restrict__ x, float* __restrict__ mv,
                           int C, int HW, int groups) {
    int bg = blockIdx.x;
    int g = bg % groups, b = bg / groups;
    int Cg = C / groups;
    long base = (long)(b * C + g * Cg) * HW;
    long n = (long)Cg * HW;
    long n4 = n >> 2;
    const float4* xp = (const float4*)(x + base);
    float s = 0.f, s2 = 0.f;
    for (long i = threadIdx.x; i < n4; i += blockDim.x) {
        float4 v = xp[i];
        s += v.x + v.y + v.z + v.w;
        s2 += v.x * v.x + v.y * v.y + v.z * v.z + v.w * v.w;
    }
    __shared__ float sh[512];
    int tid = threadIdx.x;
    sh[tid] = s;
    sh[256 + tid] = s2;
    __syncthreads();
    for (int o = 128; o > 0; o >>= 1) {
        if (tid < o) { sh[tid] += sh[tid + o]; sh[256 + tid] += sh[256 + tid + o]; }
        __syncthreads();
    }
    if (tid == 0) {
        float mean = sh[0] / (float)n;
        float var = sh[256] / (float)n - mean * mean;
        mv[bg * 2] = mean;
        mv[bg * 2 + 1] = rsqrtf(var + 1e-5f);
    }
}

__global__ void gn_apply_k(float* __restrict__ x, const float* __restrict__ mv,
                           const float* __restrict__ gamma, const float* __restrict__ beta,
                           int C, int HW, int groups, int relu, int total4) {
    int i = blockIdx.x * blockDim.x + threadIdx.x;
    if (i >= total4) return;
    long e = (long)i * 4;
    int c = (int)((e / HW) % C);
    int b = (int)(e / ((long)HW * C));
    int g = c / (C / groups);
    float mean = mv[(b * groups + g) * 2];
    float rstd = mv[(b * groups + g) * 2 + 1];
    float ga = gamma[c] * rstd;
    float bb = beta[c] - mean * ga;
    float4 v = ((float4*)x)[i];
    v.x = v.x * ga + bb;
    v.y = v.y * ga + bb;
    v.z = v.z * ga + bb;
    v.w = v.w * ga + bb;
    if (relu) {
        v.x = fmaxf(v.x, 0.f); v.y = fmaxf(v.y, 0.f);
        v.z = fmaxf(v.z, 0.f); v.w = fmaxf(v.w, 0.f);
    }
    ((float4*)x)[i] = v;
}

// ---------------------------------------------------------------------------
// Launcher
// ---------------------------------------------------------------------------
static void run_gn(float* buf, float* mvp, const float* gamma, const float* beta,
                   int C, int HW, int groups) {
    gn_stats_k<<<NB * groups, 256>>>(buf, mvp, C, HW, groups);
    int total4 = NB * C * HW / 4;
    gn_apply_k<<<(total4 + 255) / 256, 256>>>(buf, mvp, gamma, beta, C, HW, groups, 1, total4);
}

extern "C" void kernel_launch(void* const* d_in, const int* in_sizes, int n_in,
                              void* d_out, int out_size) {
    const float* x  = (const float*)d_in[0];
    const float* Kd = (const float*)d_in[1];
    const float* Kr = (const float*)d_in[2];
    const float* W1 = (const float*)d_in[3];  const float* b1 = (const float*)d_in[4];
    const float* g1 = (const float*)d_in[5];  const float* be1 = (const float*)d_in[6];
    const float* W2 = (const float*)d_in[7];  const float* b2 = (const float*)d_in[8];
    const float* g2 = (const float*)d_in[9];  const float* be2 = (const float*)d_in[10];
    const float* W3 = (const float*)d_in[11]; const float* b3 = (const float*)d_in[12];
    const float* g3 = (const float*)d_in[13]; const float* be3 = (const float*)d_in[14];
    const float* W4 = (const float*)d_in[15]; const float* b4 = (const float*)d_in[16];
    const float* g4 = (const float*)d_in[17]; const float* be4 = (const float*)d_in[18];
    const float* Wt = (const float*)d_in[19]; const float* bt = (const float*)d_in[20];
    const float* g5 = (const float*)d_in[21]; const float* be5 = (const float*)d_in[22];
    const float* W6 = (const float*)d_in[23]; const float* b6 = (const float*)d_in[24];
    float* out = (float*)d_out;

    void *p0, *pA, *pB, *pC, *pm, *pw;
    cudaGetSymbolAddress(&p0, g_s0);
    cudaGetSymbolAddress(&pA, g_sA);
    cudaGetSymbolAddress(&pB, g_sB);
    cudaGetSymbolAddress(&pC, g_sC);
    cudaGetSymbolAddress(&pm, g_mv);
    cudaGetSymbolAddress(&pw, g_wrep);
    float* s0 = (float*)p0;
    float* sA = (float*)pA;
    float* sB = (float*)pB;
    float* sC = (float*)pC;
    float* mv = (float*)pm;
    float* wrep = (float*)pw;

    // DWT: x -> s0 [16,32,128,128]
    dwt2d_k<<<(16 * 8 * 128 * 128) / 256, 256>>>(x, Kd, s0);

    // repack convT weights (cheap, runs concurrently-early)
    wrep_k<<<(4 * 64 * 512) / 256, 256>>>(Wt, wrep);

    // conv1: 32->64 @128x128  (grid.x = 4 * 32)
    conv_gemm_k<3, 1, 1, 0><<<dim3(128, 1, NB), 256>>>(s0, W1, b1, sC,
                                                       32, 64, 128, 128, 128, 128, -1, -1);
    run_gn(sC, mv, g1, be1, 64, 128 * 128, 8);

    // conv2: 64->128, stride 2, out 64x64  (grid.x = 2 * 16)
    conv_gemm_k<3, 2, 1, 0><<<dim3(32, 2, NB), 256>>>(sC, W2, b2, sB,
                                                      64, 128, 64, 64, 128, 128, -1, -1);
    run_gn(sB, mv, g2, be2, 128, 64 * 64, 16);

    // conv3: 128->256 @64x64
    conv_gemm_k<3, 1, 1, 0><<<dim3(32, 4, NB), 256>>>(sB, W3, b3, sA,
                                                      128, 256, 64, 64, 64, 64, -1, -1);
    run_gn(sA, mv, g3, be3, 256, 64 * 64, 32);

    // conv4: 256->128 @64x64
    conv_gemm_k<3, 1, 1, 0><<<dim3(32, 2, NB), 256>>>(sA, W4, b4, sB,
                                                      256, 128, 64, 64, 64, 64, -1, -1);
    run_gn(sB, mv, g4, be4, 128, 64 * 64, 16);

    // convT: 128->64, 4 interleaved classes, each 2x2-kernel GEMM on 64x64 grid
    for (int cls = 0; cls < 4; cls++) {
        int dy = cls >> 1, dx = cls & 1;
        conv_gemm_k<2, 1, -1, 1><<<dim3(32, 1, NB), 256>>>(
            sB, wrep + (long)cls * 64 * 512, bt, sC,
            128, 64, 64, 64, 64, 64, dy, dx);
    }
    run_gn(sC, mv, g5, be5, 64, 128 * 128, 8);

    // conv6: 64->16 @128x128
    conv_gemm_k<3, 1, 1, 0><<<dim3(128, 1, NB), 256>>>(sC, W6, b6, s0,
                                                       64, 16, 128, 128, 128, 128, -1, -1);

    // IDWT
    idwt2d_k<<<(16 * 4 * 128 * 128) / 256, 256>>>(s0, Kr, out);
}

// round 5
// speedup vs baseline: 2.6743x; 1.3916x over previous
#include <cuda_runtime.h>
#include <cuda_bf16.h>

// ---------------------------------------------------------------------------
// WaveletDiffusion, round 4: implicit-GEMM convs on bf16 tensor cores
// (mma.sync.m16n8k16) with 3-term hi/lo split, ldmatrix fragment loads.
// ---------------------------------------------------------------------------

#define NB 16

__device__ float g_s0[16 * 32 * 128 * 128];
__device__ float g_sA[16 * 256 * 64 * 64];
__device__ float g_sB[16 * 128 * 64 * 64];
__device__ float g_sC[16 * 64 * 128 * 128];
__device__ float g_wrep[4 * 64 * 512];
__device__ float g_mv[1024];
__device__ float g_part[512 * 16 * 2];

__device__ __forceinline__ unsigned short bhi(float v) {
    return __bfloat16_as_ushort(__float2bfloat16_rn(v));
}
__device__ __forceinline__ float bback(unsigned short u) {
    return __bfloat162float(__ushort_as_bfloat16(u));
}

__device__ __forceinline__ void mma16(float* c, const unsigned* a, const unsigned* b) {
    asm volatile(
        "mma.sync.aligned.m16n8k16.row.col.f32.bf16.bf16.f32 "
        "{%0,%1,%2,%3}, {%4,%5,%6,%7}, {%8,%9}, {%0,%1,%2,%3};"
        : "+f"(c[0]), "+f"(c[1]), "+f"(c[2]), "+f"(c[3])
        : "r"(a[0]), "r"(a[1]), "r"(a[2]), "r"(a[3]), "r"(b[0]), "r"(b[1]));
}
__device__ __forceinline__ void ldsm4(unsigned* r, unsigned addr) {
    asm volatile("ldmatrix.sync.aligned.m8n8.x4.shared.b16 {%0,%1,%2,%3}, [%4];"
                 : "=r"(r[0]), "=r"(r[1]), "=r"(r[2]), "=r"(r[3]) : "r"(addr));
}
__device__ __forceinline__ void ldsm2t(unsigned* r, unsigned addr) {
    asm volatile("ldmatrix.sync.aligned.m8n8.x2.trans.shared.b16 {%0,%1}, [%2];"
                 : "=r"(r[0]), "=r"(r[1]) : "r"(addr));
}

// ---------------------------------------------------------------------------
// DWT / IDWT
// ---------------------------------------------------------------------------
__global__ void dwt2d_k(const float* __restrict__ x, const float* __restrict__ Kd,
                        float* __restrict__ out) {
    int idx = blockIdx.x * blockDim.x + threadIdx.x;
    if (idx >= 16 * 8 * 128 * 128) return;
    int w = idx & 127;
    int h = (idx >> 7) & 127;
    int c = (idx >> 14) & 7;
    int b = idx >> 17;
    const float* xp = x + (((b * 8 + c) * 256 + 2 * h) * 256 + 2 * w);
    float x00 = xp[0], x01 = xp[1], x10 = xp[256], x11 = xp[257];
    float* op = out + (((b * 32 + c * 4) * 128 + h) * 128 + w);
#pragma unroll
    for (int s = 0; s < 4; s++) {
        float v = x00 * Kd[s * 4 + 0] + x01 * Kd[s * 4 + 1]
                + x10 * Kd[s * 4 + 2] + x11 * Kd[s * 4 + 3];
        op[s * 128 * 128] = v;
    }
}

__global__ void idwt2d_k(const float* __restrict__ in, const float* __restrict__ Kr,
                         float* __restrict__ out) {
    int idx = blockIdx.x * blockDim.x + threadIdx.x;
    if (idx >= 16 * 4 * 128 * 128) return;
    int w = idx & 127;
    int h = (idx >> 7) & 127;
    int c = (idx >> 14) & 3;
    int b = idx >> 16;
    float v[4];
#pragma unroll
    for (int s = 0; s < 4; s++)
        v[s] = in[(((b * 16 + c * 4 + s) * 128 + h) * 128 + w)];
    float* op = out + (((b * 4 + c) * 256 + 2 * h) * 256 + 2 * w);
#pragma unroll
    for (int d = 0; d < 2; d++)
#pragma unroll
        for (int e = 0; e < 2; e++) {
            float y = v[0] * Kr[0 * 4 + d * 2 + e] + v[1] * Kr[1 * 4 + d * 2 + e]
                    + v[2] * Kr[2 * 4 + d * 2 + e] + v[3] * Kr[3 * 4 + d * 2 + e];
            op[d * 256 + e] = y;
        }
}

// ---------------------------------------------------------------------------
// Implicit-GEMM conv, bf16 3-term. Tile M=64 x N=128 pixels (32w x 4h),
// K-stage 32 (2 x k16 MMA steps). 8 warps = 2(M) x 4(N); warp tile 32x32.
// ---------------------------------------------------------------------------
template <int KS, int STRIDE, int SGN, int ILV>
__global__ __launch_bounds__(256, 2)
void conv_gemm_k(const float* __restrict__ in, const float* __restrict__ wgt,
                 const float* __restrict__ bias, float* __restrict__ out,
                 int Cin, int Cout, int H, int W, int Hi, int Wi, int OY, int OX) {
    const int KS2 = KS * KS;
    const int K = Cin * KS2;
    __shared__ __align__(16) unsigned short As[2][64][40];    // [hi/lo][m][k]
    __shared__ __align__(16) unsigned short Bs[2][32][136];   // [hi/lo][k][n]

    int tid = threadIdx.x;
    int warp = tid >> 5, lane = tid & 31;
    int nx = W >> 5;
    int x0 = (blockIdx.x % nx) * 32, y0 = (blockIdx.x / nx) * 4;
    int co0 = blockIdx.y * 64;
    int b = blockIdx.z;
    int wm = warp >> 2, wn = warp & 3;

    float acc[2][4][4];
#pragma unroll
    for (int mt = 0; mt < 2; mt++)
#pragma unroll
        for (int nt = 0; nt < 4; nt++)
#pragma unroll
            for (int i = 0; i < 4; i++) acc[mt][nt][i] = 0.f;

    const float* inb = in + (long)b * Cin * Hi * Wi;

    // per-thread fill coordinates
    int fm = tid >> 2, fk8 = (tid & 3) * 8;          // A: row fm, k chunk of 8
    int fkr = tid >> 3, fc = (tid & 7) * 16;         // B: k-row fkr, 16 pixels at fc
    int fpy = fc >> 5, fpx = fc & 31;

    // fragment smem addresses (ldmatrix)
    unsigned aAddr[2][2], bAddr[2][4];
#pragma unroll
    for (int h = 0; h < 2; h++) {
#pragma unroll
        for (int mt = 0; mt < 2; mt++) {
            int row = wm * 32 + mt * 16 + (lane & 7) + ((lane >> 3) & 1) * 8;
            int kc = ((lane >> 4) & 1) * 8;
            aAddr[h][mt] = (unsigned)__cvta_generic_to_shared(&As[h][row][kc]);
        }
#pragma unroll
        for (int nt = 0; nt < 4; nt++)
            bAddr[h][nt] = (unsigned)__cvta_generic_to_shared(&Bs[h][lane & 15][wn * 32 + nt * 8]);
    }

    for (int kk = 0; kk < K; kk += 32) {
        // ---- fill A (weights): 64 x 32, hi/lo bf16 ----
        {
            float v[8];
            if (co0 + fm < Cout) {
                const float* wp = &wgt[(long)(co0 + fm) * K + kk + fk8];
                float4 v0 = *(const float4*)wp;
                float4 v1 = *(const float4*)(wp + 4);
                v[0] = v0.x; v[1] = v0.y; v[2] = v0.z; v[3] = v0.w;
                v[4] = v1.x; v[5] = v1.y; v[6] = v1.z; v[7] = v1.w;
            } else {
#pragma unroll
                for (int j = 0; j < 8; j++) v[j] = 0.f;
            }
            unsigned hi[4], lo[4];
#pragma unroll
            for (int j = 0; j < 4; j++) {
                unsigned short h0 = bhi(v[2 * j]), h1 = bhi(v[2 * j + 1]);
                unsigned short l0 = bhi(v[2 * j] - bback(h0));
                unsigned short l1 = bhi(v[2 * j + 1] - bback(h1));
                hi[j] = (unsigned)h0 | ((unsigned)h1 << 16);
                lo[j] = (unsigned)l0 | ((unsigned)l1 << 16);
            }
            *(uint4*)&As[0][fm][fk8] = *(uint4*)hi;
            *(uint4*)&As[1][fm][fk8] = *(uint4*)lo;
        }
        // ---- fill B (im2col): 32 k-rows x 128 pixels ----
        {
            int k = kk + fkr;
            int ci = k / KS2, e = k - ci * KS2;
            int dh = e / KS, dw = e - dh * KS;
            int iy = (y0 + fpy) * STRIDE + SGN * dh + OY;
            int ixs = (x0 + fpx) * STRIDE + SGN * dw + OX;
            const float* rp = inb + ((long)ci * Hi + iy) * Wi;
            bool rowok = (iy >= 0 && iy < Hi);
            float v[16];
            if (rowok && ixs >= 0 && ixs + 15 * STRIDE < Wi) {
#pragma unroll
                for (int j = 0; j < 16; j++) v[j] = rp[ixs + j * STRIDE];
            } else {
#pragma unroll
                for (int j = 0; j < 16; j++) {
                    int ix = ixs + j * STRIDE;
                    v[j] = (rowok && ix >= 0 && ix < Wi) ? rp[ix] : 0.f;
                }
            }
            unsigned hi[8], lo[8];
#pragma unroll
            for (int j = 0; j < 8; j++) {
                unsigned short h0 = bhi(v[2 * j]), h1 = bhi(v[2 * j + 1]);
                unsigned short l0 = bhi(v[2 * j] - bback(h0));
                unsigned short l1 = bhi(v[2 * j + 1] - bback(h1));
                hi[j] = (unsigned)h0 | ((unsigned)h1 << 16);
                lo[j] = (unsigned)l0 | ((unsigned)l1 << 16);
            }
            *(uint4*)&Bs[0][fkr][fc] = *(uint4*)hi;
            *(uint4*)&Bs[0][fkr][fc + 8] = *(uint4*)(hi + 4);
            *(uint4*)&Bs[1][fkr][fc] = *(uint4*)lo;
            *(uint4*)&Bs[1][fkr][fc + 8] = *(uint4*)(lo + 4);
        }
        __syncthreads();

#pragma unroll
        for (int ks = 0; ks < 2; ks++) {
            unsigned aH[2][4], aL[2][4];
#pragma unroll
            for (int mt = 0; mt < 2; mt++) {
                ldsm4(aH[mt], aAddr[0][mt] + ks * 32);
                ldsm4(aL[mt], aAddr[1][mt] + ks * 32);
            }
#pragma unroll
            for (int nt = 0; nt < 4; nt++) {
                unsigned bH[2], bL[2];
                ldsm2t(bH, bAddr[0][nt] + ks * 4352);
                ldsm2t(bL, bAddr[1][nt] + ks * 4352);
#pragma unroll
                for (int mt = 0; mt < 2; mt++) {
                    mma16(acc[mt][nt], aH[mt], bH);
                    mma16(acc[mt][nt], aH[mt], bL);
                    mma16(acc[mt][nt], aL[mt], bH);
                }
            }
        }
        __syncthreads();
    }

    // ---- store with bias ----
#pragma unroll
    for (int mt = 0; mt < 2; mt++) {
#pragma unroll
        for (int nt = 0; nt < 4; nt++) {
            int p = wn * 32 + nt * 8 + (lane & 3) * 2;
            int py = p >> 5, px = p & 31;
#pragma unroll
            for (int half = 0; half < 2; half++) {
                int row = co0 + wm * 32 + mt * 16 + (lane >> 2) + half * 8;
                if (row >= Cout) continue;
                float bv = bias[row];
                float v0 = acc[mt][nt][half * 2 + 0] + bv;
                float v1 = acc[mt][nt][half * 2 + 1] + bv;
                if (ILV) {
                    int oy = 2 * (y0 + py) + OY;
                    long base = ((long)(b * Cout + row) * (2 * H) + oy) * (2 * W);
                    out[base + 2 * (x0 + px) + OX] = v0;
                    out[base + 2 * (x0 + px + 1) + OX] = v1;
                } else {
                    long base = ((long)(b * Cout + row) * H + y0 + py) * W;
                    *(float2*)&out[base + x0 + px] = make_float2(v0, v1);
                }
            }
        }
    }
}

// ---------------------------------------------------------------------------
// convT weight repack
// ---------------------------------------------------------------------------
__global__ void wrep_k(const float* __restrict__ Wt, float* __restrict__ Wrep) {
    int idx = blockIdx.x * blockDim.x + threadIdx.x;
    if (idx >= 4 * 64 * 512) return;
    int e = idx & 3;
    int ci = (idx >> 2) & 127;
    int co = (idx >> 9) & 63;
    int cls = idx >> 15;
    int dy = cls >> 1, dx = cls & 1;
    int u = e >> 1, v = e & 1;
    Wrep[idx] = Wt[((long)ci * 64 + co) * 16 + ((1 - dy) + 2 * u) * 4 + (1 - dx) + 2 * v];
}

// ---------------------------------------------------------------------------
// GroupNorm: 16-way-parallel partial stats + tiny finalize (deterministic)
// ---------------------------------------------------------------------------
#define GN_CH 16

__global__ void gn_part_k(const float* __restrict__ x, float* __restrict__ part,
                          int C, int HW, int groups) {
    int bg = blockIdx.x;
    int chunk = blockIdx.y;
    int g = bg % groups, b = bg / groups;
    int Cg = C / groups;
    long base = (long)(b * C + g * Cg) * HW;
    long n4 = ((long)Cg * HW) >> 2;
    long clen = n4 / GN_CH;
    const float4* xp = (const float4*)(x + base) + chunk * clen;
    float s = 0.f, s2 = 0.f;
    for (long i = threadIdx.x; i < clen; i += blockDim.x) {
        float4 v = xp[i];
        s += v.x + v.y + v.z + v.w;
        s2 += v.x * v.x + v.y * v.y + v.z * v.z + v.w * v.w;
    }
    __shared__ float sh[512];
    int tid = threadIdx.x;
    sh[tid] = s;
    sh[256 + tid] = s2;
    __syncthreads();
    for (int o = 128; o > 0; o >>= 1) {
        if (tid < o) { sh[tid] += sh[tid + o]; sh[256 + tid] += sh[256 + tid + o]; }
        __syncthreads();
    }
    if (tid == 0) {
        part[(bg * GN_CH + chunk) * 2] = sh[0];
        part[(bg * GN_CH + chunk) * 2 + 1] = sh[256];
    }
}

__global__ void gn_fin_k(const float* __restrict__ part, float* __restrict__ mv,
                         int C, int HW, int groups) {
    int bg = blockIdx.x;
    int lane = threadIdx.x;
    float s = 0.f, s2 = 0.f;
    if (lane < GN_CH) {
        s = part[(bg * GN_CH + lane) * 2];
        s2 = part[(bg * GN_CH + lane) * 2 + 1];
    }
#pragma unroll
    for (int o = 16; o > 0; o >>= 1) {
        s += __shfl_xor_sync(0xffffffff, s, o);
        s2 += __shfl_xor_sync(0xffffffff, s2, o);
    }
    if (lane == 0) {
        float n = (float)((long)(C / groups) * HW);
        float mean = s / n;
        float var = s2 / n - mean * mean;
        mv[bg * 2] = mean;
        mv[bg * 2 + 1] = rsqrtf(var + 1e-5f);
    }
}

__global__ void gn_apply_k(float* __restrict__ x, const float* __restrict__ mv,
                           const float* __restrict__ gamma, const float* __restrict__ beta,
                           int C, int HW, int groups, int relu, int total4) {
    int i = blockIdx.x * blockDim.x + threadIdx.x;
    if (i >= total4) return;
    long e = (long)i * 4;
    int c = (int)((e / HW) % C);
    int b = (int)(e / ((long)HW * C));
    int g = c / (C / groups);
    float mean = mv[(b * groups + g) * 2];
    float rstd = mv[(b * groups + g) * 2 + 1];
    float ga = gamma[c] * rstd;
    float bb = beta[c] - mean * ga;
    float4 v = ((float4*)x)[i];
    v.x = v.x * ga + bb;
    v.y = v.y * ga + bb;
    v.z = v.z * ga + bb;
    v.w = v.w * ga + bb;
    if (relu) {
        v.x = fmaxf(v.x, 0.f); v.y = fmaxf(v.y, 0.f);
        v.z = fmaxf(v.z, 0.f); v.w = fmaxf(v.w, 0.f);
    }
    ((float4*)x)[i] = v;
}

// ---------------------------------------------------------------------------
// Launcher
// ---------------------------------------------------------------------------
static float* s_part;

static void run_gn(float* buf, float* mvp, const float* gamma, const float* beta,
                   int C, int HW, int groups) {
    gn_part_k<<<dim3(NB * groups, GN_CH), 256>>>(buf, s_part, C, HW, groups);
    gn_fin_k<<<NB * groups, 32>>>(s_part, mvp, C, HW, groups);
    int total4 = NB * C * HW / 4;
    gn_apply_k<<<(total4 + 255) / 256, 256>>>(buf, mvp, gamma, beta, C, HW, groups, 1, total4);
}

extern "C" void kernel_launch(void* const* d_in, const int* in_sizes, int n_in,
                              void* d_out, int out_size) {
    const float* x  = (const float*)d_in[0];
    const float* Kd = (const float*)d_in[1];
    const float* Kr = (const float*)d_in[2];
    const float* W1 = (const float*)d_in[3];  const float* b1 = (const float*)d_in[4];
    const float* g1 = (const float*)d_in[5];  const float* be1 = (const float*)d_in[6];
    const float* W2 = (const float*)d_in[7];  const float* b2 = (const float*)d_in[8];
    const float* g2 = (const float*)d_in[9];  const float* be2 = (const float*)d_in[10];
    const float* W3 = (const float*)d_in[11]; const float* b3 = (const float*)d_in[12];
    const float* g3 = (const float*)d_in[13]; const float* be3 = (const float*)d_in[14];
    const float* W4 = (const float*)d_in[15]; const float* b4 = (const float*)d_in[16];
    const float* g4 = (const float*)d_in[17]; const float* be4 = (const float*)d_in[18];
    const float* Wt = (const float*)d_in[19]; const float* bt = (const float*)d_in[20];
    const float* g5 = (const float*)d_in[21]; const float* be5 = (const float*)d_in[22];
    const float* W6 = (const float*)d_in[23]; const float* b6 = (const float*)d_in[24];
    float* out = (float*)d_out;

    void *p0, *pA, *pB, *pC, *pm, *pw, *pp;
    cudaGetSymbolAddress(&p0, g_s0);
    cudaGetSymbolAddress(&pA, g_sA);
    cudaGetSymbolAddress(&pB, g_sB);
    cudaGetSymbolAddress(&pC, g_sC);
    cudaGetSymbolAddress(&pm, g_mv);
    cudaGetSymbolAddress(&pw, g_wrep);
    cudaGetSymbolAddress(&pp, g_part);
    float* s0 = (float*)p0;
    float* sA = (float*)pA;
    float* sB = (float*)pB;
    float* sC = (float*)pC;
    float* mv = (float*)pm;
    float* wrep = (float*)pw;
    s_part = (float*)pp;

    // DWT: x -> s0 [16,32,128,128]
    dwt2d_k<<<(16 * 8 * 128 * 128) / 256, 256>>>(x, Kd, s0);

    // repack convT weights
    wrep_k<<<(4 * 64 * 512) / 256, 256>>>(Wt, wrep);

    // conv1: 32->64 @128x128
    conv_gemm_k<3, 1, 1, 0><<<dim3(128, 1, NB), 256>>>(s0, W1, b1, sC,
                                                       32, 64, 128, 128, 128, 128, -1, -1);
    run_gn(sC, mv, g1, be1, 64, 128 * 128, 8);

    // conv2: 64->128, stride 2, out 64x64
    conv_gemm_k<3, 2, 1, 0><<<dim3(32, 2, NB), 256>>>(sC, W2, b2, sB,
                                                      64, 128, 64, 64, 128, 128, -1, -1);
    run_gn(sB, mv, g2, be2, 128, 64 * 64, 16);

    // conv3: 128->256 @64x64
    conv_gemm_k<3, 1, 1, 0><<<dim3(32, 4, NB), 256>>>(sB, W3, b3, sA,
                                                      128, 256, 64, 64, 64, 64, -1, -1);
    run_gn(sA, mv, g3, be3, 256, 64 * 64, 32);

    // conv4: 256->128 @64x64
    conv_gemm_k<3, 1, 1, 0><<<dim3(32, 2, NB), 256>>>(sA, W4, b4, sB,
                                                      256, 128, 64, 64, 64, 64, -1, -1);
    run_gn(sB, mv, g4, be4, 128, 64 * 64, 16);

    // convT: 4 interleaved classes, each 2x2-kernel GEMM
    for (int cls = 0; cls < 4; cls++) {
        int dy = cls >> 1, dx = cls & 1;
        conv_gemm_k<2, 1, -1, 1><<<dim3(32, 1, NB), 256>>>(
            sB, wrep + (long)cls * 64 * 512, bt, sC,
            128, 64, 64, 64, 64, 64, dy, dx);
    }
    run_gn(sC, mv, g5, be5, 64, 128 * 128, 8);

    // conv6: 64->16 @128x128
    conv_gemm_k<3, 1, 1, 0><<<dim3(128, 1, NB), 256>>>(sC, W6, b6, s0,
                                                       64, 16, 128, 128, 128, 128, -1, -1);

    // IDWT
    idwt2d_k<<<(16 * 4 * 128 * 128) / 256, 256>>>(s0, Kr, out);
}

// round 6
// speedup vs baseline: 3.4232x; 1.2800x over previous
#include <cuda_runtime.h>
#include <cuda_bf16.h>

// ---------------------------------------------------------------------------
// WaveletDiffusion round 5: bf16 3-term implicit GEMM with pre-split hi/lo
// operand planes (padded halo -> no bounds checks, no in-loop conversion)
// and an M=128 block tile for the big layers.
// ---------------------------------------------------------------------------

#define NB 16
typedef unsigned short u16;
typedef unsigned int u32;

// fp32 conv outputs (GN stats read these)
__device__ float g_s0[16 * 32 * 128 * 128];
__device__ float g_sA[16 * 256 * 64 * 64];
__device__ float g_sB[16 * 128 * 64 * 64];
__device__ float g_sC[16 * 64 * 128 * 128];
// padded bf16 hi/lo activation planes  [B*C][H+2][W+4]
__device__ __align__(16) u16 g_p0H[16 * 32 * 130 * 132], g_p0L[16 * 32 * 130 * 132];
__device__ __align__(16) u16 g_pCH[16 * 64 * 130 * 132], g_pCL[16 * 64 * 130 * 132];
__device__ __align__(16) u16 g_pBH[16 * 128 * 66 * 68],  g_pBL[16 * 128 * 66 * 68];
__device__ __align__(16) u16 g_pAH[16 * 256 * 66 * 68],  g_pAL[16 * 256 * 66 * 68];
// pre-converted weights (k-major, hi/lo)
#define WO1 0
#define WO2 18432
#define WO3 92160
#define WO4 387072
#define WOT 681984
#define WO6 813056
#define WTOT 822272
__device__ __align__(16) u16 g_wH[WTOT], g_wL[WTOT];
__device__ float g_mv[1024];
__device__ float g_part[512 * 16 * 2];

__device__ __forceinline__ u16 bhi(float v) {
    return __bfloat16_as_ushort(__float2bfloat16_rn(v));
}
__device__ __forceinline__ float bback(u16 u) {
    return __bfloat162float(__ushort_as_bfloat16(u));
}
__device__ __forceinline__ void mma16(float* c, const u32* a, const u32* b) {
    asm volatile(
        "mma.sync.aligned.m16n8k16.row.col.f32.bf16.bf16.f32 "
        "{%0,%1,%2,%3}, {%4,%5,%6,%7}, {%8,%9}, {%0,%1,%2,%3};"
        : "+f"(c[0]), "+f"(c[1]), "+f"(c[2]), "+f"(c[3])
        : "r"(a[0]), "r"(a[1]), "r"(a[2]), "r"(a[3]), "r"(b[0]), "r"(b[1]));
}
__device__ __forceinline__ void ldsm4(u32* r, u32 addr) {
    asm volatile("ldmatrix.sync.aligned.m8n8.x4.shared.b16 {%0,%1,%2,%3}, [%4];"
                 : "=r"(r[0]), "=r"(r[1]), "=r"(r[2]), "=r"(r[3]) : "r"(addr));
}
__device__ __forceinline__ void ldsm2t(u32* r, u32 addr) {
    asm volatile("ldmatrix.sync.aligned.m8n8.x2.trans.shared.b16 {%0,%1}, [%2];"
                 : "=r"(r[0]), "=r"(r[1]) : "r"(addr));
}

// ---------------------------------------------------------------------------
// prep: weight convert (hi/lo), convT repack+convert, plane halo-ring zero
// ---------------------------------------------------------------------------
__global__ void wcvt_k(const float* __restrict__ src, u16* __restrict__ dH,
                       u16* __restrict__ dL, int n) {
    int i = blockIdx.x * blockDim.x + threadIdx.x;
    if (i >= n) return;
    float v = src[i];
    u16 h = bhi(v);
    dH[i] = h;
    dL[i] = bhi(v - bback(h));
}

__global__ void wrepcvt_k(const float* __restrict__ Wt, u16* __restrict__ dH,
                          u16* __restrict__ dL) {
    int idx = blockIdx.x * blockDim.x + threadIdx.x;
    if (idx >= 4 * 64 * 512) return;
    int e = idx & 3;
    int ci = (idx >> 2) & 127;
    int co = (idx >> 9) & 63;
    int cls = idx >> 15;
    int dy = cls >> 1, dx = cls & 1;
    int u = e >> 1, v = e & 1;
    float w = Wt[((long)ci * 64 + co) * 16 + ((1 - dy) + 2 * u) * 4 + (1 - dx) + 2 * v];
    u16 h = bhi(w);
    dH[WOT + idx] = h;
    dL[WOT + idx] = bhi(w - bback(h));
}

__global__ void ring_k(u16* __restrict__ pH, u16* __restrict__ pL,
                       int nch, int Hp, int Wp) {
    int ring = 2 * Wp + (Hp - 2) * 4;
    int idx = blockIdx.x * blockDim.x + threadIdx.x;
    if (idx >= nch * ring) return;
    int ch = idx / ring, r = idx - ch * ring;
    int row, col;
    if (r < 2 * Wp) { row = (r < Wp) ? 0 : Hp - 1; col = (r < Wp) ? r : r - Wp; }
    else {
        int rr = r - 2 * Wp;
        row = 1 + (rr >> 2);
        int q = rr & 3;
        col = (q < 2) ? q : Wp - 4 + q;
    }
    long off = ((long)ch * Hp + row) * Wp + col;
    pH[off] = 0;
    pL[off] = 0;
}

// ---------------------------------------------------------------------------
// DWT: writes hi/lo planes directly
// ---------------------------------------------------------------------------
__global__ void dwt2d_k(const float* __restrict__ x, const float* __restrict__ Kd,
                        u16* __restrict__ oH, u16* __restrict__ oL) {
    int idx = blockIdx.x * blockDim.x + threadIdx.x;
    if (idx >= 16 * 8 * 128 * 128) return;
    int w = idx & 127;
    int h = (idx >> 7) & 127;
    int c = (idx >> 14) & 7;
    int b = idx >> 17;
    const float* xp = x + (((b * 8 + c) * 256 + 2 * h) * 256 + 2 * w);
    float x00 = xp[0], x01 = xp[1], x10 = xp[256], x11 = xp[257];
#pragma unroll
    for (int s = 0; s < 4; s++) {
        float v = x00 * Kd[s * 4 + 0] + x01 * Kd[s * 4 + 1]
                + x10 * Kd[s * 4 + 2] + x11 * Kd[s * 4 + 3];
        long off = ((long)(b * 32 + c * 4 + s) * 130 + h + 1) * 132 + w + 2;
        u16 hv = bhi(v);
        oH[off] = hv;
        oL[off] = bhi(v - bback(hv));
    }
}

__global__ void idwt2d_k(const float* __restrict__ in, const float* __restrict__ Kr,
                         float* __restrict__ out) {
    int idx = blockIdx.x * blockDim.x + threadIdx.x;
    if (idx >= 16 * 4 * 128 * 128) return;
    int w = idx & 127;
    int h = (idx >> 7) & 127;
    int c = (idx >> 14) & 3;
    int b = idx >> 16;
    float v[4];
#pragma unroll
    for (int s = 0; s < 4; s++)
        v[s] = in[(((b * 16 + c * 4 + s) * 128 + h) * 128 + w)];
    float* op = out + (((b * 4 + c) * 256 + 2 * h) * 256 + 2 * w);
#pragma unroll
    for (int d = 0; d < 2; d++)
#pragma unroll
        for (int e = 0; e < 2; e++) {
            float y = v[0] * Kr[0 * 4 + d * 2 + e] + v[1] * Kr[1 * 4 + d * 2 + e]
                    + v[2] * Kr[2 * 4 + d * 2 + e] + v[3] * Kr[3 * 4 + d * 2 + e];
            op[d * 256 + e] = y;
        }
}

// ---------------------------------------------------------------------------
// Implicit-GEMM conv from pre-split padded planes.
// BIGM=1: M=128, warps 4Mx2N (warp 32x64). BIGM=0: M=64, warps 2Mx4N (32x32).
// N = 128 pixels (32w x 4h). K-stage 32 (2 x k16).
// ---------------------------------------------------------------------------
template <int KS, int STRIDE, int SGN, int ILV, int BIGM>
__global__ __launch_bounds__(256, 2)
void conv_gemm_k(const u16* __restrict__ inH, const u16* __restrict__ inL,
                 const u16* __restrict__ wHp, const u16* __restrict__ wLp,
                 const float* __restrict__ bias, float* __restrict__ out,
                 int Cin, int Cout, int H, int W, int Hi, int Wi, int OY, int OX) {
    const int KS2 = KS * KS;
    const int K = Cin * KS2;
    const int MROWS = BIGM ? 128 : 64;
    const int NSPAN = BIGM ? 64 : 32;
    const int NT = NSPAN / 8;
    const int Hp = Hi + 2, Wp = Wi + 4;

    __shared__ __align__(16) u16 As[2][MROWS][40];
    __shared__ __align__(16) u16 Bs[2][32][136];

    int tid = threadIdx.x;
    int warp = tid >> 5, lane = tid & 31;
    int nx = W >> 5;
    int x0 = (blockIdx.x % nx) * 32, y0 = (blockIdx.x / nx) * 4;
    int co0 = blockIdx.y * MROWS;
    int b = blockIdx.z;
    int wm = BIGM ? (warp >> 1) : (warp >> 2);
    int wn = BIGM ? (warp & 1) : (warp & 3);

    float acc[2][NT][4];
#pragma unroll
    for (int mt = 0; mt < 2; mt++)
#pragma unroll
        for (int nt = 0; nt < NT; nt++)
#pragma unroll
            for (int i = 0; i < 4; i++) acc[mt][nt][i] = 0.f;

    const u16* ibH = inH + (long)b * Cin * Hp * Wp;
    const u16* ibL = inL + (long)b * Cin * Hp * Wp;

    // B fill coords: thread -> (k-row, 16-pixel segment)
    int fkr = tid >> 3, seg = tid & 7;
    int px0 = seg * 16, fpy = px0 >> 5, fpx = px0 & 31;
    // A fill coords
    int fm = BIGM ? (tid >> 1) : (tid >> 2);
    int fq = BIGM ? ((tid & 1) * 16) : ((tid & 3) * 8);

    u32 aAddr[2][2], bBase[2];
#pragma unroll
    for (int h = 0; h < 2; h++) {
#pragma unroll
        for (int mt = 0; mt < 2; mt++) {
            int row = wm * 32 + mt * 16 + (lane & 7) + ((lane >> 3) & 1) * 8;
            int kc = ((lane >> 4) & 1) * 8;
            aAddr[h][mt] = (u32)__cvta_generic_to_shared(&As[h][row][kc]);
        }
        bBase[h] = (u32)__cvta_generic_to_shared(&Bs[h][lane & 15][wn * NSPAN]);
    }

    for (int kk = 0; kk < K; kk += 32) {
        // ---- A fill: pure copies from pre-converted weights ----
        {
            bool ok = (co0 + fm) < Cout;
            const uint4* phh = (const uint4*)(wHp + (long)(co0 + fm) * K + kk + fq);
            const uint4* pll = (const uint4*)(wLp + (long)(co0 + fm) * K + kk + fq);
            uint4 z = make_uint4(0, 0, 0, 0);
            if (BIGM) {
                uint4 h0 = ok ? phh[0] : z, h1 = ok ? phh[1] : z;
                uint4 l0 = ok ? pll[0] : z, l1 = ok ? pll[1] : z;
                *(uint4*)&As[0][fm][fq] = h0;
                *(uint4*)&As[0][fm][fq + 8] = h1;
                *(uint4*)&As[1][fm][fq] = l0;
                *(uint4*)&As[1][fm][fq + 8] = l1;
            } else {
                uint4 h0 = ok ? phh[0] : z;
                uint4 l0 = ok ? pll[0] : z;
                *(uint4*)&As[0][fm][fq] = h0;
                *(uint4*)&As[1][fm][fq] = l0;
            }
        }
        // ---- B fill: bare u16 gathers from padded planes (no predicates) ----
        {
            int k = kk + fkr;
            int ci = k / KS2, e = k - ci * KS2;
            int dh = e / KS, dw = e - dh * KS;
            int iy = (y0 + fpy) * STRIDE + SGN * dh + OY;
            int ixb = (x0 + fpx) * STRIDE + SGN * dw + OX;
            long roff = ((long)ci * Hp + iy + 1) * Wp + ixb + 2;
            const u16* pH = ibH + roff;
            const u16* pL = ibL + roff;
            u32 hv[8], lv[8];
#pragma unroll
            for (int j = 0; j < 8; j++) {
                hv[j] = (u32)pH[(2 * j) * STRIDE] | ((u32)pH[(2 * j + 1) * STRIDE] << 16);
                lv[j] = (u32)pL[(2 * j) * STRIDE] | ((u32)pL[(2 * j + 1) * STRIDE] << 16);
            }
            *(uint4*)&Bs[0][fkr][px0] = *(uint4*)hv;
            *(uint4*)&Bs[0][fkr][px0 + 8] = *(uint4*)(hv + 4);
            *(uint4*)&Bs[1][fkr][px0] = *(uint4*)lv;
            *(uint4*)&Bs[1][fkr][px0 + 8] = *(uint4*)(lv + 4);
        }
        __syncthreads();

#pragma unroll
        for (int ks = 0; ks < 2; ks++) {
            u32 aH[2][4], aL[2][4];
#pragma unroll
            for (int mt = 0; mt < 2; mt++) {
                ldsm4(aH[mt], aAddr[0][mt] + ks * 32);
                ldsm4(aL[mt], aAddr[1][mt] + ks * 32);
            }
#pragma unroll
            for (int nt = 0; nt < NT; nt++) {
                u32 bH[2], bL[2];
                ldsm2t(bH, bBase[0] + nt * 16 + ks * 4352);
                ldsm2t(bL, bBase[1] + nt * 16 + ks * 4352);
#pragma unroll
                for (int mt = 0; mt < 2; mt++) {
                    mma16(acc[mt][nt], aH[mt], bH);
                    mma16(acc[mt][nt], aH[mt], bL);
                    mma16(acc[mt][nt], aL[mt], bH);
                }
            }
        }
        __syncthreads();
    }

    // ---- store + bias ----
#pragma unroll
    for (int mt = 0; mt < 2; mt++) {
#pragma unroll
        for (int nt = 0; nt < NT; nt++) {
            int p = wn * NSPAN + nt * 8 + (lane & 3) * 2;
            int py = p >> 5, px = p & 31;
#pragma unroll
            for (int half = 0; half < 2; half++) {
                int row = co0 + wm * 32 + mt * 16 + (lane >> 2) + half * 8;
                if (row >= Cout) continue;
                float bv = bias[row];
                float v0 = acc[mt][nt][half * 2 + 0] + bv;
                float v1 = acc[mt][nt][half * 2 + 1] + bv;
                if (ILV) {
                    int oy = 2 * (y0 + py) + OY;
                    long base = ((long)(b * Cout + row) * (2 * H) + oy) * (2 * W);
                    out[base + 2 * (x0 + px) + OX] = v0;
                    out[base + 2 * (x0 + px + 1) + OX] = v1;
                } else {
                    long base = ((long)(b * Cout + row) * H + y0 + py) * W;
                    *(float2*)&out[base + x0 + px] = make_float2(v0, v1);
                }
            }
        }
    }
}

// ---------------------------------------------------------------------------
// GroupNorm: partial stats + finalize + fused apply->bf16 hi/lo padded planes
// ---------------------------------------------------------------------------
#define GN_CH 16

__global__ void gn_part_k(const float* __restrict__ x, float* __restrict__ part,
                          int C, int HW, int groups) {
    int bg = blockIdx.x;
    int chunk = blockIdx.y;
    int g = bg % groups, b = bg / groups;
    int Cg = C / groups;
    long base = (long)(b * C + g * Cg) * HW;
    long n4 = ((long)Cg * HW) >> 2;
    long clen = n4 / GN_CH;
    const float4* xp = (const float4*)(x + base) + chunk * clen;
    float s = 0.f, s2 = 0.f;
    for (long i = threadIdx.x; i < clen; i += blockDim.x) {
        float4 v = xp[i];
        s += v.x + v.y + v.z + v.w;
        s2 += v.x * v.x + v.y * v.y + v.z * v.z + v.w * v.w;
    }
    __shared__ float sh[512];
    int tid = threadIdx.x;
    sh[tid] = s;
    sh[256 + tid] = s2;
    __syncthreads();
    for (int o = 128; o > 0; o >>= 1) {
        if (tid < o) { sh[tid] += sh[tid + o]; sh[256 + tid] += sh[256 + tid + o]; }
        __syncthreads();
    }
    if (tid == 0) {
        part[(bg * GN_CH + chunk) * 2] = sh[0];
        part[(bg * GN_CH + chunk) * 2 + 1] = sh[256];
    }
}

__global__ void gn_fin_k(const float* __restrict__ part, float* __restrict__ mv,
                         int C, int HW, int groups) {
    int bg = blockIdx.x;
    int lane = threadIdx.x;
    float s = 0.f, s2 = 0.f;
    if (lane < GN_CH) {
        s = part[(bg * GN_CH + lane) * 2];
        s2 = part[(bg * GN_CH + lane) * 2 + 1];
    }
#pragma unroll
    for (int o = 16; o > 0; o >>= 1) {
        s += __shfl_xor_sync(0xffffffff, s, o);
        s2 += __shfl_xor_sync(0xffffffff, s2, o);
    }
    if (lane == 0) {
        float n = (float)((long)(C / groups) * HW);
        float mean = s / n;
        float var = s2 / n - mean * mean;
        mv[bg * 2] = mean;
        mv[bg * 2 + 1] = rsqrtf(var + 1e-5f);
    }
}

// apply + relu + bf16 split into padded planes
__global__ void gn_apply_k(const float* __restrict__ x, const float* __restrict__ mv,
                           const float* __restrict__ gamma, const float* __restrict__ beta,
                           u16* __restrict__ oH, u16* __restrict__ oL,
                           int C, int H, int W, int groups, int total4) {
    int i = blockIdx.x * blockDim.x + threadIdx.x;
    if (i >= total4) return;
    long e = (long)i * 4;
    int HW = H * W;
    int c = (int)((e / HW) % C);
    int b = (int)(e / ((long)HW * C));
    int r = (int)(e % HW);
    int y = r / W, xx = r - y * W;
    int g = c / (C / groups);
    float mean = mv[(b * groups + g) * 2];
    float rstd = mv[(b * groups + g) * 2 + 1];
    float ga = gamma[c] * rstd;
    float bb = beta[c] - mean * ga;
    float4 v = ((const float4*)x)[i];
    float f[4] = {fmaxf(v.x * ga + bb, 0.f), fmaxf(v.y * ga + bb, 0.f),
                  fmaxf(v.z * ga + bb, 0.f), fmaxf(v.w * ga + bb, 0.f)};
    u16 hs[4], ls[4];
#pragma unroll
    for (int j = 0; j < 4; j++) {
        hs[j] = bhi(f[j]);
        ls[j] = bhi(f[j] - bback(hs[j]));
    }
    long off = ((long)((b * C + c) * (H + 2) + y + 1)) * (W + 4) + xx + 2;
    *(u32*)(oH + off) = (u32)hs[0] | ((u32)hs[1] << 16);
    *(u32*)(oH + off + 2) = (u32)hs[2] | ((u32)hs[3] << 16);
    *(u32*)(oL + off) = (u32)ls[0] | ((u32)ls[1] << 16);
    *(u32*)(oL + off + 2) = (u32)ls[2] | ((u32)ls[3] << 16);
}

// ---------------------------------------------------------------------------
// Launcher
// ---------------------------------------------------------------------------
static float* s_part;

static void run_gn(const float* buf, float* mvp, const float* gamma, const float* beta,
                   u16* oH, u16* oL, int C, int H, int W, int groups) {
    int HW = H * W;
    gn_part_k<<<dim3(NB * groups, GN_CH), 256>>>(buf, s_part, C, HW, groups);
    gn_fin_k<<<NB * groups, 32>>>(s_part, mvp, C, HW, groups);
    int total4 = NB * C * HW / 4;
    gn_apply_k<<<(total4 + 255) / 256, 256>>>(buf, mvp, gamma, beta, oH, oL,
                                              C, H, W, groups, total4);
}

extern "C" void kernel_launch(void* const* d_in, const int* in_sizes, int n_in,
                              void* d_out, int out_size) {
    const float* x  = (const float*)d_in[0];
    const float* Kd = (const float*)d_in[1];
    const float* Kr = (const float*)d_in[2];
    const float* W1 = (const float*)d_in[3];  const float* b1 = (const float*)d_in[4];
    const float* g1 = (const float*)d_in[5];  const float* be1 = (const float*)d_in[6];
    const float* W2 = (const float*)d_in[7];  const float* b2 = (const float*)d_in[8];
    const float* g2 = (const float*)d_in[9];  const float* be2 = (const float*)d_in[10];
    const float* W3 = (const float*)d_in[11]; const float* b3 = (const float*)d_in[12];
    const float* g3 = (const float*)d_in[13]; const float* be3 = (const float*)d_in[14];
    const float* W4 = (const float*)d_in[15]; const float* b4 = (const float*)d_in[16];
    const float* g4 = (const float*)d_in[17]; const float* be4 = (const float*)d_in[18];
    const float* Wt = (const float*)d_in[19]; const float* bt = (const float*)d_in[20];
    const float* g5 = (const float*)d_in[21]; const float* be5 = (const float*)d_in[22];
    const float* W6 = (const float*)d_in[23]; const float* b6 = (const float*)d_in[24];
    float* out = (float*)d_out;

    void* p;
    cudaGetSymbolAddress(&p, g_s0);  float* s0 = (float*)p;
    cudaGetSymbolAddress(&p, g_sA);  float* sA = (float*)p;
    cudaGetSymbolAddress(&p, g_sB);  float* sB = (float*)p;
    cudaGetSymbolAddress(&p, g_sC);  float* sC = (float*)p;
    cudaGetSymbolAddress(&p, g_mv);  float* mv = (float*)p;
    cudaGetSymbolAddress(&p, g_part); s_part = (float*)p;
    cudaGetSymbolAddress(&p, g_p0H); u16* p0H = (u16*)p;
    cudaGetSymbolAddress(&p, g_p0L); u16* p0L = (u16*)p;
    cudaGetSymbolAddress(&p, g_pCH); u16* pCH = (u16*)p;
    cudaGetSymbolAddress(&p, g_pCL); u16* pCL = (u16*)p;
    cudaGetSymbolAddress(&p, g_pBH); u16* pBH = (u16*)p;
    cudaGetSymbolAddress(&p, g_pBL); u16* pBL = (u16*)p;
    cudaGetSymbolAddress(&p, g_pAH); u16* pAH = (u16*)p;
    cudaGetSymbolAddress(&p, g_pAL); u16* pAL = (u16*)p;
    cudaGetSymbolAddress(&p, g_wH);  u16* wH = (u16*)p;
    cudaGetSymbolAddress(&p, g_wL);  u16* wL = (u16*)p;

    // prep: halo rings + weight conversion
    {
        int n;
        n = 16 * 32 * (2 * 132 + 128 * 4);
        ring_k<<<(n + 255) / 256, 256>>>(p0H, p0L, 16 * 32, 130, 132);
        n = 16 * 64 * (2 * 132 + 128 * 4);
        ring_k<<<(n + 255) / 256, 256>>>(pCH, pCL, 16 * 64, 130, 132);
        n = 16 * 128 * (2 * 68 + 64 * 4);
        ring_k<<<(n + 255) / 256, 256>>>(pBH, pBL, 16 * 128, 66, 68);
        n = 16 * 256 * (2 * 68 + 64 * 4);
        ring_k<<<(n + 255) / 256, 256>>>(pAH, pAL, 16 * 256, 66, 68);
        wcvt_k<<<(64 * 288 + 255) / 256, 256>>>(W1, wH + WO1, wL + WO1, 64 * 288);
        wcvt_k<<<(128 * 576 + 255) / 256, 256>>>(W2, wH + WO2, wL + WO2, 128 * 576);
        wcvt_k<<<(256 * 1152 + 255) / 256, 256>>>(W3, wH + WO3, wL + WO3, 256 * 1152);
        wcvt_k<<<(128 * 2304 + 255) / 256, 256>>>(W4, wH + WO4, wL + WO4, 128 * 2304);
        wcvt_k<<<(16 * 576 + 255) / 256, 256>>>(W6, wH + WO6, wL + WO6, 16 * 576);
        wrepcvt_k<<<(4 * 64 * 512 + 255) / 256, 256>>>(Wt, wH, wL);
    }

    // DWT -> p0 planes
    dwt2d_k<<<(16 * 8 * 128 * 128) / 256, 256>>>(x, Kd, p0H, p0L);

    // conv1: 32->64 @128 (M64)
    conv_gemm_k<3, 1, 1, 0, 0><<<dim3(128, 1, NB), 256>>>(
        p0H, p0L, wH + WO1, wL + WO1, b1, sC, 32, 64, 128, 128, 128, 128, -1, -1);
    run_gn(sC, mv, g1, be1, pCH, pCL, 64, 128, 128, 8);

    // conv2: 64->128 s2 @64 (BIGM)
    conv_gemm_k<3, 2, 1, 0, 1><<<dim3(32, 1, NB), 256>>>(
        pCH, pCL, wH + WO2, wL + WO2, b2, sB, 64, 128, 64, 64, 128, 128, -1, -1);
    run_gn(sB, mv, g2, be2, pBH, pBL, 128, 64, 64, 16);

    // conv3: 128->256 @64 (BIGM, 2 M-blocks)
    conv_gemm_k<3, 1, 1, 0, 1><<<dim3(32, 2, NB), 256>>>(
        pBH, pBL, wH + WO3, wL + WO3, b3, sA, 128, 256, 64, 64, 64, 64, -1, -1);
    run_gn(sA, mv, g3, be3, pAH, pAL, 256, 64, 64, 32);

    // conv4: 256->128 @64 (BIGM)
    conv_gemm_k<3, 1, 1, 0, 1><<<dim3(32, 1, NB), 256>>>(
        pAH, pAL, wH + WO4, wL + WO4, b4, sB, 256, 128, 64, 64, 64, 64, -1, -1);
    run_gn(sB, mv, g4, be4, pBH, pBL, 128, 64, 64, 16);

    // convT: 4 classes (M64, interleaved store)
    for (int cls = 0; cls < 4; cls++) {
        int dy = cls >> 1, dx = cls & 1;
        conv_gemm_k<2, 1, -1, 1, 0><<<dim3(32, 1, NB), 256>>>(
            pBH, pBL, wH + WOT + cls * 64 * 512, wL + WOT + cls * 64 * 512, bt, sC,
            128, 64, 64, 64, 64, 64, dy, dx);
    }
    run_gn(sC, mv, g5, be5, pCH, pCL, 64, 128, 128, 8);

    // conv6: 64->16 @128 (M64) -> fp32
    conv_gemm_k<3, 1, 1, 0, 0><<<dim3(128, 1, NB), 256>>>(
        pCH, pCL, wH + WO6, wL + WO6, b6, s0, 64, 16, 128, 128, 128, 128, -1, -1);

    // IDWT
    idwt2d_k<<<(16 * 4 * 128 * 128) / 256, 256>>>(s0, Kr, out);
}

// round 7
// speedup vs baseline: 3.9384x; 1.1505x over previous
#include <cuda_runtime.h>
#include <cuda_bf16.h>

// ---------------------------------------------------------------------------
// WaveletDiffusion round 6: bf16 3-term implicit GEMM, software-pipelined
// (reg-prefetch B + cp.async A, double-buffered smem, 1 barrier/stage),
// M16 tile for conv6.
// ---------------------------------------------------------------------------

#define NB 16
typedef unsigned short u16;
typedef unsigned int u32;

__device__ float g_s0[16 * 32 * 128 * 128];
__device__ float g_sA[16 * 256 * 64 * 64];
__device__ float g_sB[16 * 128 * 64 * 64];
__device__ float g_sC[16 * 64 * 128 * 128];
__device__ __align__(16) u16 g_p0H[16 * 32 * 130 * 132], g_p0L[16 * 32 * 130 * 132];
__device__ __align__(16) u16 g_pCH[16 * 64 * 130 * 132], g_pCL[16 * 64 * 130 * 132];
__device__ __align__(16) u16 g_pBH[16 * 128 * 66 * 68],  g_pBL[16 * 128 * 66 * 68];
__device__ __align__(16) u16 g_pAH[16 * 256 * 66 * 68],  g_pAL[16 * 256 * 66 * 68];
#define WO1 0
#define WO2 18432
#define WO3 92160
#define WO4 387072
#define WOT 681984
#define WO6 813056
#define WTOT 822272
__device__ __align__(16) u16 g_wH[WTOT], g_wL[WTOT];
__device__ float g_mv[1024];
__device__ float g_part[512 * 16 * 2];

__device__ __forceinline__ u16 bhi(float v) {
    return __bfloat16_as_ushort(__float2bfloat16_rn(v));
}
__device__ __forceinline__ float bback(u16 u) {
    return __bfloat162float(__ushort_as_bfloat16(u));
}
__device__ __forceinline__ void mma16(float* c, const u32* a, const u32* b) {
    asm volatile(
        "mma.sync.aligned.m16n8k16.row.col.f32.bf16.bf16.f32 "
        "{%0,%1,%2,%3}, {%4,%5,%6,%7}, {%8,%9}, {%0,%1,%2,%3};"
        : "+f"(c[0]), "+f"(c[1]), "+f"(c[2]), "+f"(c[3])
        : "r"(a[0]), "r"(a[1]), "r"(a[2]), "r"(a[3]), "r"(b[0]), "r"(b[1]));
}
__device__ __forceinline__ void ldsm4(u32* r, u32 addr) {
    asm volatile("ldmatrix.sync.aligned.m8n8.x4.shared.b16 {%0,%1,%2,%3}, [%4];"
                 : "=r"(r[0]), "=r"(r[1]), "=r"(r[2]), "=r"(r[3]) : "r"(addr));
}
__device__ __forceinline__ void ldsm2t(u32* r, u32 addr) {
    asm volatile("ldmatrix.sync.aligned.m8n8.x2.trans.shared.b16 {%0,%1}, [%2];"
                 : "=r"(r[0]), "=r"(r[1]) : "r"(addr));
}
__device__ __forceinline__ void cp16(u32 dst, const void* src) {
    asm volatile("cp.async.cg.shared.global [%0], [%1], 16;" :: "r"(dst), "l"(src));
}
__device__ __forceinline__ void cp_commit() {
    asm volatile("cp.async.commit_group;" ::: "memory");
}
__device__ __forceinline__ void cp_wait0() {
    asm volatile("cp.async.wait_group 0;" ::: "memory");
}

// ---------------------------------------------------------------------------
// prep
// ---------------------------------------------------------------------------
__global__ void wcvt_k(const float* __restrict__ src, u16* __restrict__ dH,
                       u16* __restrict__ dL, int n) {
    int i = blockIdx.x * blockDim.x + threadIdx.x;
    if (i >= n) return;
    float v = src[i];
    u16 h = bhi(v);
    dH[i] = h;
    dL[i] = bhi(v - bback(h));
}

__global__ void wrepcvt_k(const float* __restrict__ Wt, u16* __restrict__ dH,
                          u16* __restrict__ dL) {
    int idx = blockIdx.x * blockDim.x + threadIdx.x;
    if (idx >= 4 * 64 * 512) return;
    int e = idx & 3;
    int ci = (idx >> 2) & 127;
    int co = (idx >> 9) & 63;
    int cls = idx >> 15;
    int dy = cls >> 1, dx = cls & 1;
    int u = e >> 1, v = e & 1;
    float w = Wt[((long)ci * 64 + co) * 16 + ((1 - dy) + 2 * u) * 4 + (1 - dx) + 2 * v];
    u16 h = bhi(w);
    dH[WOT + idx] = h;
    dL[WOT + idx] = bhi(w - bback(h));
}

__global__ void ring_k(u16* __restrict__ pH, u16* __restrict__ pL,
                       int nch, int Hp, int Wp) {
    int ring = 2 * Wp + (Hp - 2) * 4;
    int idx = blockIdx.x * blockDim.x + threadIdx.x;
    if (idx >= nch * ring) return;
    int ch = idx / ring, r = idx - ch * ring;
    int row, col;
    if (r < 2 * Wp) { row = (r < Wp) ? 0 : Hp - 1; col = (r < Wp) ? r : r - Wp; }
    else {
        int rr = r - 2 * Wp;
        row = 1 + (rr >> 2);
        int q = rr & 3;
        col = (q < 2) ? q : Wp - 4 + q;
    }
    long off = ((long)ch * Hp + row) * Wp + col;
    pH[off] = 0;
    pL[off] = 0;
}

// ---------------------------------------------------------------------------
// DWT / IDWT
// ---------------------------------------------------------------------------
__global__ void dwt2d_k(const float* __restrict__ x, const float* __restrict__ Kd,
                        u16* __restrict__ oH, u16* __restrict__ oL) {
    int idx = blockIdx.x * blockDim.x + threadIdx.x;
    if (idx >= 16 * 8 * 128 * 128) return;
    int w = idx & 127;
    int h = (idx >> 7) & 127;
    int c = (idx >> 14) & 7;
    int b = idx >> 17;
    const float* xp = x + (((b * 8 + c) * 256 + 2 * h) * 256 + 2 * w);
    float x00 = xp[0], x01 = xp[1], x10 = xp[256], x11 = xp[257];
#pragma unroll
    for (int s = 0; s < 4; s++) {
        float v = x00 * Kd[s * 4 + 0] + x01 * Kd[s * 4 + 1]
                + x10 * Kd[s * 4 + 2] + x11 * Kd[s * 4 + 3];
        long off = ((long)(b * 32 + c * 4 + s) * 130 + h + 1) * 132 + w + 2;
        u16 hv = bhi(v);
        oH[off] = hv;
        oL[off] = bhi(v - bback(hv));
    }
}

__global__ void idwt2d_k(const float* __restrict__ in, const float* __restrict__ Kr,
                         float* __restrict__ out) {
    int idx = blockIdx.x * blockDim.x + threadIdx.x;
    if (idx >= 16 * 4 * 128 * 128) return;
    int w = idx & 127;
    int h = (idx >> 7) & 127;
    int c = (idx >> 14) & 3;
    int b = idx >> 16;
    float v[4];
#pragma unroll
    for (int s = 0; s < 4; s++)
        v[s] = in[(((b * 16 + c * 4 + s) * 128 + h) * 128 + w)];
    float* op = out + (((b * 4 + c) * 256 + 2 * h) * 256 + 2 * w);
#pragma unroll
    for (int d = 0; d < 2; d++)
#pragma unroll
        for (int e = 0; e < 2; e++) {
            float y = v[0] * Kr[0 * 4 + d * 2 + e] + v[1] * Kr[1 * 4 + d * 2 + e]
                    + v[2] * Kr[2 * 4 + d * 2 + e] + v[3] * Kr[3 * 4 + d * 2 + e];
            op[d * 256 + e] = y;
        }
}

// ---------------------------------------------------------------------------
// Pipelined implicit-GEMM conv.
// MODE 0: M=64  (warps 2Mx4N, warp 32x32)
// MODE 1: M=128 (warps 4Mx2N, warp 32x64)
// MODE 2: M=16  (warps 1Mx8N, warp 16x16)
// N = 128 pixels (32w x 4h), K-stage 32.
// ---------------------------------------------------------------------------
template <int KS, int STRIDE, int SGN, int ILV, int MODE>
__global__ __launch_bounds__(256, 2)
void conv_gemm_k(const u16* __restrict__ inH, const u16* __restrict__ inL,
                 const u16* __restrict__ wHp, const u16* __restrict__ wLp,
                 const float* __restrict__ bias, float* __restrict__ out,
                 int Cin, int Cout, int H, int W, int Hi, int Wi, int OY, int OX) {
    const int KS2 = KS * KS;
    const int K = Cin * KS2;
    const int MROWS = (MODE == 1) ? 128 : (MODE == 2 ? 16 : 64);
    const int NSPAN = (MODE == 1) ? 64 : (MODE == 2 ? 16 : 32);
    const int NT = NSPAN / 8;
    const int MT = (MODE == 2) ? 1 : 2;
    const int Hp = Hi + 2, Wp = Wi + 4;

    __shared__ __align__(16) u16 As[2][2][MROWS][40];   // [pipe][hilo]
    __shared__ __align__(16) u16 Bs[2][2][32][136];
    const int A_PIPE = 2 * MROWS * 80;                  // bytes
    const int B_PIPE = 2 * 32 * 272;

    int tid = threadIdx.x;
    int warp = tid >> 5, lane = tid & 31;
    int nx = W >> 5;
    int x0 = (blockIdx.x % nx) * 32, y0 = (blockIdx.x / nx) * 4;
    int co0 = blockIdx.y * MROWS;
    int b = blockIdx.z;
    int wm = (MODE == 1) ? (warp >> 1) : (MODE == 2 ? 0 : (warp >> 2));
    int wn = (MODE == 1) ? (warp & 1) : (MODE == 2 ? warp : (warp & 3));

    float acc[MT][NT][4];
#pragma unroll
    for (int mt = 0; mt < MT; mt++)
#pragma unroll
        for (int nt = 0; nt < NT; nt++)
#pragma unroll
            for (int i = 0; i < 4; i++) acc[mt][nt][i] = 0.f;

    const u16* ibH = inH + (long)b * Cin * Hp * Wp;
    const u16* ibL = inL + (long)b * Cin * Hp * Wp;

    // B fill coords
    int fkr = tid >> 3, seg = tid & 7;
    int px0 = seg * 16, fpy = px0 >> 5, fpx = px0 & 31;
    // A fill coords
    int fm, fq;
    if (MODE == 1) { fm = tid >> 1; fq = (tid & 1) * 16; }
    else           { fm = tid >> 2; fq = (tid & 3) * 8; }
    bool aact = (MODE == 2) ? (tid < 64) : true;
    u32 aDstH = (u32)__cvta_generic_to_shared(&As[0][0][fm & (MROWS - 1)][fq]);
    u32 aDstL = aDstH + MROWS * 80;
    u32 bDst = (u32)__cvta_generic_to_shared(&Bs[0][0][fkr][px0]);

    // fragment addrs (pipe 0)
    u32 aAddr[2][MT], bBase[2];
#pragma unroll
    for (int h = 0; h < 2; h++) {
#pragma unroll
        for (int mt = 0; mt < MT; mt++) {
            int row = wm * 32 + mt * 16 + (lane & 7) + ((lane >> 3) & 1) * 8;
            int kc = ((lane >> 4) & 1) * 8;
            aAddr[h][mt] = (u32)__cvta_generic_to_shared(&As[0][h][row][kc]);
        }
        bBase[h] = (u32)__cvta_generic_to_shared(&Bs[0][h][lane & 15][wn * NSPAN]);
    }

    u32 hv[8], lv[8];

    // ---- prefetch helpers ----
    auto ldgB = [&](int kk) {
        int k = kk + fkr;
        int ci = k / KS2, e = k - ci * KS2;
        int dh = e / KS, dw = e - dh * KS;
        int iy = (y0 + fpy) * STRIDE + SGN * dh + OY;
        int ixb = (x0 + fpx) * STRIDE + SGN * dw + OX;
        long roff = ((long)ci * Hp + iy + 1) * Wp + ixb + 2;
        const u16* pH = ibH + roff;
        const u16* pL = ibL + roff;
#pragma unroll
        for (int j = 0; j < 8; j++) {
            hv[j] = (u32)pH[(2 * j) * STRIDE] | ((u32)pH[(2 * j + 1) * STRIDE] << 16);
            lv[j] = (u32)pL[(2 * j) * STRIDE] | ((u32)pL[(2 * j + 1) * STRIDE] << 16);
        }
    };
    auto cpA = [&](int kk, int st) {
        if (!aact) return;
        const u16* sH = wHp + (long)(co0 + fm) * K + kk + fq;
        const u16* sL = wLp + (long)(co0 + fm) * K + kk + fq;
        u32 dH = aDstH + st * A_PIPE;
        u32 dL = aDstL + st * A_PIPE;
        cp16(dH, sH);
        cp16(dL, sL);
        if (MODE == 1) { cp16(dH + 16, sH + 8); cp16(dL + 16, sL + 8); }
    };
    auto stsB = [&](int st) {
        u32 d0 = bDst + st * B_PIPE;
        u32 d1 = d0 + 32 * 272;   // lo plane
        asm volatile("st.shared.v4.b32 [%0], {%1,%2,%3,%4};" :: "r"(d0),
                     "r"(hv[0]), "r"(hv[1]), "r"(hv[2]), "r"(hv[3]));
        asm volatile("st.shared.v4.b32 [%0], {%1,%2,%3,%4};" :: "r"(d0 + 16),
                     "r"(hv[4]), "r"(hv[5]), "r"(hv[6]), "r"(hv[7]));
        asm volatile("st.shared.v4.b32 [%0], {%1,%2,%3,%4};" :: "r"(d1),
                     "r"(lv[0]), "r"(lv[1]), "r"(lv[2]), "r"(lv[3]));
        asm volatile("st.shared.v4.b32 [%0], {%1,%2,%3,%4};" :: "r"(d1 + 16),
                     "r"(lv[4]), "r"(lv[5]), "r"(lv[6]), "r"(lv[7]));
    };

    // ---- pipelined mainloop ----
    ldgB(0);
    cpA(0, 0);
    cp_commit();
    int st = 0;
    for (int kk = 0; kk < K; kk += 32, st ^= 1) {
        stsB(st);
        cp_wait0();
        __syncthreads();
        if (kk + 32 < K) {
            ldgB(kk + 32);
            cpA(kk + 32, st ^ 1);
            cp_commit();
        }
#pragma unroll
        for (int ks = 0; ks < 2; ks++) {
            u32 aH[MT][4], aL[MT][4];
#pragma unroll
            for (int mt = 0; mt < MT; mt++) {
                ldsm4(aH[mt], aAddr[0][mt] + st * A_PIPE + ks * 32);
                ldsm4(aL[mt], aAddr[1][mt] + st * A_PIPE + ks * 32);
            }
#pragma unroll
            for (int nt = 0; nt < NT; nt++) {
                u32 bH[2], bL[2];
                ldsm2t(bH, bBase[0] + st * B_PIPE + nt * 16 + ks * 4352);
                ldsm2t(bL, bBase[1] + st * B_PIPE + nt * 16 + ks * 4352);
#pragma unroll
                for (int mt = 0; mt < MT; mt++) {
                    mma16(acc[mt][nt], aH[mt], bH);
                    mma16(acc[mt][nt], aH[mt], bL);
                    mma16(acc[mt][nt], aL[mt], bH);
                }
            }
        }
    }

    // ---- store + bias ----
#pragma unroll
    for (int mt = 0; mt < MT; mt++) {
#pragma unroll
        for (int nt = 0; nt < NT; nt++) {
            int p = wn * NSPAN + nt * 8 + (lane & 3) * 2;
            int py = p >> 5, px = p & 31;
#pragma unroll
            for (int half = 0; half < 2; half++) {
                int row = co0 + wm * 32 + mt * 16 + (lane >> 2) + half * 8;
                if (row >= Cout) continue;
                float bv = bias[row];
                float v0 = acc[mt][nt][half * 2 + 0] + bv;
                float v1 = acc[mt][nt][half * 2 + 1] + bv;
                if (ILV) {
                    int oy = 2 * (y0 + py) + OY;
                    long base = ((long)(b * Cout + row) * (2 * H) + oy) * (2 * W);
                    out[base + 2 * (x0 + px) + OX] = v0;
                    out[base + 2 * (x0 + px + 1) + OX] = v1;
                } else {
                    long base = ((long)(b * Cout + row) * H + y0 + py) * W;
                    *(float2*)&out[base + x0 + px] = make_float2(v0, v1);
                }
            }
        }
    }
}

// ---------------------------------------------------------------------------
// GroupNorm
// ---------------------------------------------------------------------------
#define GN_CH 16

__global__ void gn_part_k(const float* __restrict__ x, float* __restrict__ part,
                          int C, int HW, int groups) {
    int bg = blockIdx.x;
    int chunk = blockIdx.y;
    int g = bg % groups, b = bg / groups;
    int Cg = C / groups;
    long base = (long)(b * C + g * Cg) * HW;
    long n4 = ((long)Cg * HW) >> 2;
    long clen = n4 / GN_CH;
    const float4* xp = (const float4*)(x + base) + chunk * clen;
    float s = 0.f, s2 = 0.f;
    for (long i = threadIdx.x; i < clen; i += blockDim.x) {
        float4 v = xp[i];
        s += v.x + v.y + v.z + v.w;
        s2 += v.x * v.x + v.y * v.y + v.z * v.z + v.w * v.w;
    }
    __shared__ float sh[512];
    int tid = threadIdx.x;
    sh[tid] = s;
    sh[256 + tid] = s2;
    __syncthreads();
    for (int o = 128; o > 0; o >>= 1) {
        if (tid < o) { sh[tid] += sh[tid + o]; sh[256 + tid] += sh[256 + tid + o]; }
        __syncthreads();
    }
    if (tid == 0) {
        part[(bg * GN_CH + chunk) * 2] = sh[0];
        part[(bg * GN_CH + chunk) * 2 + 1] = sh[256];
    }
}

__global__ void gn_fin_k(const float* __restrict__ part, float* __restrict__ mv,
                         int C, int HW, int groups) {
    int bg = blockIdx.x;
    int lane = threadIdx.x;
    float s = 0.f, s2 = 0.f;
    if (lane < GN_CH) {
        s = part[(bg * GN_CH + lane) * 2];
        s2 = part[(bg * GN_CH + lane) * 2 + 1];
    }
#pragma unroll
    for (int o = 16; o > 0; o >>= 1) {
        s += __shfl_xor_sync(0xffffffff, s, o);
        s2 += __shfl_xor_sync(0xffffffff, s2, o);
    }
    if (lane == 0) {
        float n = (float)((long)(C / groups) * HW);
        float mean = s / n;
        float var = s2 / n - mean * mean;
        mv[bg * 2] = mean;
        mv[bg * 2 + 1] = rsqrtf(var + 1e-5f);
    }
}

__global__ void gn_apply_k(const float* __restrict__ x, const float* __restrict__ mv,
                           const float* __restrict__ gamma, const float* __restrict__ beta,
                           u16* __restrict__ oH, u16* __restrict__ oL,
                           int C, int H, int W, int groups, int total4) {
    int i = blockIdx.x * blockDim.x + threadIdx.x;
    if (i >= total4) return;
    long e = (long)i * 4;
    int HW = H * W;
    int c = (int)((e / HW) % C);
    int b = (int)(e / ((long)HW * C));
    int r = (int)(e % HW);
    int y = r / W, xx = r - y * W;
    int g = c / (C / groups);
    float mean = mv[(b * groups + g) * 2];
    float rstd = mv[(b * groups + g) * 2 + 1];
    float ga = gamma[c] * rstd;
    float bb = beta[c] - mean * ga;
    float4 v = ((const float4*)x)[i];
    float f[4] = {fmaxf(v.x * ga + bb, 0.f), fmaxf(v.y * ga + bb, 0.f),
                  fmaxf(v.z * ga + bb, 0.f), fmaxf(v.w * ga + bb, 0.f)};
    u16 hs[4], ls[4];
#pragma unroll
    for (int j = 0; j < 4; j++) {
        hs[j] = bhi(f[j]);
        ls[j] = bhi(f[j] - bback(hs[j]));
    }
    long off = ((long)((b * C + c) * (H + 2) + y + 1)) * (W + 4) + xx + 2;
    *(u32*)(oH + off) = (u32)hs[0] | ((u32)hs[1] << 16);
    *(u32*)(oH + off + 2) = (u32)hs[2] | ((u32)hs[3] << 16);
    *(u32*)(oL + off) = (u32)ls[0] | ((u32)ls[1] << 16);
    *(u32*)(oL + off + 2) = (u32)ls[2] | ((u32)ls[3] << 16);
}

// ---------------------------------------------------------------------------
// Launcher
// ---------------------------------------------------------------------------
static float* s_part;

static void run_gn(const float* buf, float* mvp, const float* gamma, const float* beta,
                   u16* oH, u16* oL, int C, int H, int W, int groups) {
    int HW = H * W;
    gn_part_k<<<dim3(NB * groups, GN_CH), 256>>>(buf, s_part, C, HW, groups);
    gn_fin_k<<<NB * groups, 32>>>(s_part, mvp, C, HW, groups);
    int total4 = NB * C * HW / 4;
    gn_apply_k<<<(total4 + 255) / 256, 256>>>(buf, mvp, gamma, beta, oH, oL,
                                              C, H, W, groups, total4);
}

extern "C" void kernel_launch(void* const* d_in, const int* in_sizes, int n_in,
                              void* d_out, int out_size) {
    const float* x  = (const float*)d_in[0];
    const float* Kd = (const float*)d_in[1];
    const float* Kr = (const float*)d_in[2];
    const float* W1 = (const float*)d_in[3];  const float* b1 = (const float*)d_in[4];
    const float* g1 = (const float*)d_in[5];  const float* be1 = (const float*)d_in[6];
    const float* W2 = (const float*)d_in[7];  const float* b2 = (const float*)d_in[8];
    const float* g2 = (const float*)d_in[9];  const float* be2 = (const float*)d_in[10];
    const float* W3 = (const float*)d_in[11]; const float* b3 = (const float*)d_in[12];
    const float* g3 = (const float*)d_in[13]; const float* be3 = (const float*)d_in[14];
    const float* W4 = (const float*)d_in[15]; const float* b4 = (const float*)d_in[16];
    const float* g4 = (const float*)d_in[17]; const float* be4 = (const float*)d_in[18];
    const float* Wt = (const float*)d_in[19]; const float* bt = (const float*)d_in[20];
    const float* g5 = (const float*)d_in[21]; const float* be5 = (const float*)d_in[22];
    const float* W6 = (const float*)d_in[23]; const float* b6 = (const float*)d_in[24];
    float* out = (float*)d_out;

    void* p;
    cudaGetSymbolAddress(&p, g_s0);  float* s0 = (float*)p;
    cudaGetSymbolAddress(&p, g_sA);  float* sA = (float*)p;
    cudaGetSymbolAddress(&p, g_sB);  float* sB = (float*)p;
    cudaGetSymbolAddress(&p, g_sC);  float* sC = (float*)p;
    cudaGetSymbolAddress(&p, g_mv);  float* mv = (float*)p;
    cudaGetSymbolAddress(&p, g_part); s_part = (float*)p;
    cudaGetSymbolAddress(&p, g_p0H); u16* p0H = (u16*)p;
    cudaGetSymbolAddress(&p, g_p0L); u16* p0L = (u16*)p;
    cudaGetSymbolAddress(&p, g_pCH); u16* pCH = (u16*)p;
    cudaGetSymbolAddress(&p, g_pCL); u16* pCL = (u16*)p;
    cudaGetSymbolAddress(&p, g_pBH); u16* pBH = (u16*)p;
    cudaGetSymbolAddress(&p, g_pBL); u16* pBL = (u16*)p;
    cudaGetSymbolAddress(&p, g_pAH); u16* pAH = (u16*)p;
    cudaGetSymbolAddress(&p, g_pAL); u16* pAL = (u16*)p;
    cudaGetSymbolAddress(&p, g_wH);  u16* wH = (u16*)p;
    cudaGetSymbolAddress(&p, g_wL);  u16* wL = (u16*)p;

    // prep
    {
        int n;
        n = 16 * 32 * (2 * 132 + 128 * 4);
        ring_k<<<(n + 255) / 256, 256>>>(p0H, p0L, 16 * 32, 130, 132);
        n = 16 * 64 * (2 * 132 + 128 * 4);
        ring_k<<<(n + 255) / 256, 256>>>(pCH, pCL, 16 * 64, 130, 132);
        n = 16 * 128 * (2 * 68 + 64 * 4);
        ring_k<<<(n + 255) / 256, 256>>>(pBH, pBL, 16 * 128, 66, 68);
        n = 16 * 256 * (2 * 68 + 64 * 4);
        ring_k<<<(n + 255) / 256, 256>>>(pAH, pAL, 16 * 256, 66, 68);
        wcvt_k<<<(64 * 288 + 255) / 256, 256>>>(W1, wH + WO1, wL + WO1, 64 * 288);
        wcvt_k<<<(128 * 576 + 255) / 256, 256>>>(W2, wH + WO2, wL + WO2, 128 * 576);
        wcvt_k<<<(256 * 1152 + 255) / 256, 256>>>(W3, wH + WO3, wL + WO3, 256 * 1152);
        wcvt_k<<<(128 * 2304 + 255) / 256, 256>>>(W4, wH + WO4, wL + WO4, 128 * 2304);
        wcvt_k<<<(16 * 576 + 255) / 256, 256>>>(W6, wH + WO6, wL + WO6, 16 * 576);
        wrepcvt_k<<<(4 * 64 * 512 + 255) / 256, 256>>>(Wt, wH, wL);
    }

    // DWT -> p0 planes
    dwt2d_k<<<(16 * 8 * 128 * 128) / 256, 256>>>(x, Kd, p0H, p0L);

    // conv1: 32->64 @128 (MODE0)
    conv_gemm_k<3, 1, 1, 0, 0><<<dim3(128, 1, NB), 256>>>(
        p0H, p0L, wH + WO1, wL + WO1, b1, sC, 32, 64, 128, 128, 128, 128, -1, -1);
    run_gn(sC, mv, g1, be1, pCH, pCL, 64, 128, 128, 8);

    // conv2: 64->128 s2 @64 (MODE1)
    conv_gemm_k<3, 2, 1, 0, 1><<<dim3(32, 1, NB), 256>>>(
        pCH, pCL, wH + WO2, wL + WO2, b2, sB, 64, 128, 64, 64, 128, 128, -1, -1);
    run_gn(sB, mv, g2, be2, pBH, pBL, 128, 64, 64, 16);

    // conv3: 128->256 @64 (MODE1, 2 M-blocks)
    conv_gemm_k<3, 1, 1, 0, 1><<<dim3(32, 2, NB), 256>>>(
        pBH, pBL, wH + WO3, wL + WO3, b3, sA, 128, 256, 64, 64, 64, 64, -1, -1);
    run_gn(sA, mv, g3, be3, pAH, pAL, 256, 64, 64, 32);

    // conv4: 256->128 @64 (MODE1)
    conv_gemm_k<3, 1, 1, 0, 1><<<dim3(32, 1, NB), 256>>>(
        pAH, pAL, wH + WO4, wL + WO4, b4, sB, 256, 128, 64, 64, 64, 64, -1, -1);
    run_gn(sB, mv, g4, be4, pBH, pBL, 128, 64, 64, 16);

    // convT: 4 classes (MODE0, interleaved store)
    for (int cls = 0; cls < 4; cls++) {
        int dy = cls >> 1, dx = cls & 1;
        conv_gemm_k<2, 1, -1, 1, 0><<<dim3(32, 1, NB), 256>>>(
            pBH, pBL, wH + WOT + cls * 64 * 512, wL + WOT + cls * 64 * 512, bt, sC,
            128, 64, 64, 64, 64, 64, dy, dx);
    }
    run_gn(sC, mv, g5, be5, pCH, pCL, 64, 128, 128, 8);

    // conv6: 64->16 @128 (MODE2, exact M=16)
    conv_gemm_k<3, 1, 1, 0, 2><<<dim3(128, 1, NB), 256>>>(
        pCH, pCL, wH + WO6, wL + WO6, b6, s0, 64, 16, 128, 128, 128, 128, -1, -1);

    // IDWT
    idwt2d_k<<<(16 * 4 * 128 * 128) / 256, 256>>>(s0, Kr, out);
}

// round 11
// speedup vs baseline: 4.0149x; 1.0194x over previous
#include <cuda_runtime.h>
#include <cuda_bf16.h>

// ---------------------------------------------------------------------------
// WaveletDiffusion round 10: single-stream (multi-stream graphs violate the
// harness teardown memory check). R7 conv kernels + fused convT launch,
// gn_fin merged into gn_apply, consolidated prep kernels.
// ---------------------------------------------------------------------------

#define NB 16
typedef unsigned short u16;
typedef unsigned int u32;

__device__ float g_s0[16 * 32 * 128 * 128];
__device__ float g_sA[16 * 256 * 64 * 64];
__device__ float g_sB[16 * 128 * 64 * 64];
__device__ float g_sC[16 * 64 * 128 * 128];
__device__ __align__(16) u16 g_p0H[16 * 32 * 130 * 132], g_p0L[16 * 32 * 130 * 132];
__device__ __align__(16) u16 g_pCH[16 * 64 * 130 * 132], g_pCL[16 * 64 * 130 * 132];
__device__ __align__(16) u16 g_pBH[16 * 128 * 66 * 68],  g_pBL[16 * 128 * 66 * 68];
__device__ __align__(16) u16 g_pAH[16 * 256 * 66 * 68],  g_pAL[16 * 256 * 66 * 68];
#define WO1 0
#define WO2 18432
#define WO3 92160
#define WO4 387072
#define WOT 681984
#define WO6 813056
#define WTOT 822272
__device__ __align__(16) u16 g_wH[WTOT], g_wL[WTOT];
__device__ float g_mv[1024];
__device__ float g_part[512 * 16 * 2];

__device__ __forceinline__ u16 bhi(float v) {
    return __bfloat16_as_ushort(__float2bfloat16_rn(v));
}
__device__ __forceinline__ float bback(u16 u) {
    return __bfloat162float(__ushort_as_bfloat16(u));
}
__device__ __forceinline__ void mma16(float* c, const u32* a, const u32* b) {
    asm volatile(
        "mma.sync.aligned.m16n8k16.row.col.f32.bf16.bf16.f32 "
        "{%0,%1,%2,%3}, {%4,%5,%6,%7}, {%8,%9}, {%0,%1,%2,%3};"
        : "+f"(c[0]), "+f"(c[1]), "+f"(c[2]), "+f"(c[3])
        : "r"(a[0]), "r"(a[1]), "r"(a[2]), "r"(a[3]), "r"(b[0]), "r"(b[1]));
}
__device__ __forceinline__ void ldsm4(u32* r, u32 addr) {
    asm volatile("ldmatrix.sync.aligned.m8n8.x4.shared.b16 {%0,%1,%2,%3}, [%4];"
                 : "=r"(r[0]), "=r"(r[1]), "=r"(r[2]), "=r"(r[3]) : "r"(addr));
}
__device__ __forceinline__ void ldsm2t(u32* r, u32 addr) {
    asm volatile("ldmatrix.sync.aligned.m8n8.x2.trans.shared.b16 {%0,%1}, [%2];"
                 : "=r"(r[0]), "=r"(r[1]) : "r"(addr));
}
__device__ __forceinline__ void cp16(u32 dst, const void* src) {
    asm volatile("cp.async.cg.shared.global [%0], [%1], 16;" :: "r"(dst), "l"(src));
}
__device__ __forceinline__ void cp_commit() {
    asm volatile("cp.async.commit_group;" ::: "memory");
}
__device__ __forceinline__ void cp_wait0() {
    asm volatile("cp.async.wait_group 0;" ::: "memory");
}

// ---------------------------------------------------------------------------
// prep: one kernel for all weight conversions, one for all halo rings
// ---------------------------------------------------------------------------
__global__ void wcvt_all_k(const float* __restrict__ W1, const float* __restrict__ W2,
                           const float* __restrict__ W3, const float* __restrict__ W4,
                           const float* __restrict__ W6, const float* __restrict__ Wt,
                           u16* __restrict__ dH, u16* __restrict__ dL) {
    int i = blockIdx.x * blockDim.x + threadIdx.x;
    float v;
    int o = i;
    if (i < WO2) v = W1[i - WO1];
    else if (i < WO3) v = W2[i - WO2];
    else if (i < WO4) v = W3[i - WO3];
    else if (i < WOT) v = W4[i - WO4];
    else if (i < WO6) {
        int idx = i - WOT;
        int e = idx & 3;
        int ci = (idx >> 2) & 127;
        int co = (idx >> 9) & 63;
        int cls = idx >> 15;
        int dy = cls >> 1, dx = cls & 1;
        int u = e >> 1, vv = e & 1;
        v = Wt[((long)ci * 64 + co) * 16 + ((1 - dy) + 2 * u) * 4 + (1 - dx) + 2 * vv];
    } else if (i < WTOT) v = W6[i - WO6];
    else return;
    u16 h = bhi(v);
    dH[o] = h;
    dL[o] = bhi(v - bback(h));
}

// segments: (planeH, planeL, nch, Hp, Wp)
__global__ void ring_all_k(u16* pAH_, u16* pAL_, u16* pBH_, u16* pBL_,
                           u16* pCH_, u16* pCL_, u16* p0H_, u16* p0L_) {
    // ring lengths
    const int r130 = 2 * 132 + 128 * 4;     // Hp=130, Wp=132
    const int r66  = 2 * 68 + 64 * 4;       // Hp=66, Wp=68
    const int n0 = 16 * 32 * r130;          // p0
    const int nC = 16 * 64 * r130;          // pC
    const int nBx = 16 * 128 * r66;         // pB
    const int nAx = 16 * 256 * r66;         // pA
    int idx = blockIdx.x * blockDim.x + threadIdx.x;
    u16 *pH, *pL;
    int ring, Hp, Wp;
    if (idx < n0) { pH = p0H_; pL = p0L_; ring = r130; Hp = 130; Wp = 132; }
    else if ((idx -= n0) < nC) { pH = pCH_; pL = pCL_; ring = r130; Hp = 130; Wp = 132; }
    else if ((idx -= nC) < nBx) { pH = pBH_; pL = pBL_; ring = r66; Hp = 66; Wp = 68; }
    else if ((idx -= nBx) < nAx) { pH = pAH_; pL = pAL_; ring = r66; Hp = 66; Wp = 68; }
    else return;
    int ch = idx / ring, r = idx - ch * ring;
    int row, col;
    if (r < 2 * Wp) { row = (r < Wp) ? 0 : Hp - 1; col = (r < Wp) ? r : r - Wp; }
    else {
        int rr = r - 2 * Wp;
        row = 1 + (rr >> 2);
        int q = rr & 3;
        col = (q < 2) ? q : Wp - 4 + q;
    }
    long off = ((long)ch * Hp + row) * Wp + col;
    pH[off] = 0;
    pL[off] = 0;
}

// ---------------------------------------------------------------------------
// DWT / IDWT
// ---------------------------------------------------------------------------
__global__ void dwt2d_k(const float* __restrict__ x, const float* __restrict__ Kd,
                        u16* __restrict__ oH, u16* __restrict__ oL) {
    int idx = blockIdx.x * blockDim.x + threadIdx.x;
    int w = idx & 127;
    int h = (idx >> 7) & 127;
    int c = (idx >> 14) & 7;
    int b = idx >> 17;
    const float* xp = x + (((b * 8 + c) * 256 + 2 * h) * 256 + 2 * w);
    float x00 = xp[0], x01 = xp[1], x10 = xp[256], x11 = xp[257];
#pragma unroll
    for (int s = 0; s < 4; s++) {
        float v = x00 * Kd[s * 4 + 0] + x01 * Kd[s * 4 + 1]
                + x10 * Kd[s * 4 + 2] + x11 * Kd[s * 4 + 3];
        long off = ((long)(b * 32 + c * 4 + s) * 130 + h + 1) * 132 + w + 2;
        u16 hv = bhi(v);
        oH[off] = hv;
        oL[off] = bhi(v - bback(hv));
    }
}

__global__ void idwt2d_k(const float* __restrict__ in, const float* __restrict__ Kr,
                         float* __restrict__ out) {
    int idx = blockIdx.x * blockDim.x + threadIdx.x;
    int w = idx & 127;
    int h = (idx >> 7) & 127;
    int c = (idx >> 14) & 3;
    int b = idx >> 16;
    float v[4];
#pragma unroll
    for (int s = 0; s < 4; s++)
        v[s] = in[(((b * 16 + c * 4 + s) * 128 + h) * 128 + w)];
    float* op = out + (((b * 4 + c) * 256 + 2 * h) * 256 + 2 * w);
#pragma unroll
    for (int d = 0; d < 2; d++)
#pragma unroll
        for (int e = 0; e < 2; e++) {
            float y = v[0] * Kr[0 * 4 + d * 2 + e] + v[1] * Kr[1 * 4 + d * 2 + e]
                    + v[2] * Kr[2 * 4 + d * 2 + e] + v[3] * Kr[3 * 4 + d * 2 + e];
            op[d * 256 + e] = y;
        }
}

// ---------------------------------------------------------------------------
// Pipelined implicit-GEMM conv.
// MODE 0: M=64 (2Mx4N). MODE 1: M=128 (4Mx2N). MODE 2: M=16 (1Mx8N).
// CVT: convT mode — blockIdx.y selects class (dy,dx) and weight offset.
// N = 128 pixels (32w x 4h), K-stage 32.
// ---------------------------------------------------------------------------
template <int KS, int STRIDE, int SGN, int ILV, int MODE, int CVT>
__global__ __launch_bounds__(256, 2)
void conv_gemm_k(const u16* __restrict__ inH, const u16* __restrict__ inL,
                 const u16* __restrict__ wHp, const u16* __restrict__ wLp,
                 const float* __restrict__ bias, float* __restrict__ out,
                 int Cin, int Cout, int H, int W, int Hi, int Wi, int OY_, int OX_) {
    const int KS2 = KS * KS;
    const int K = Cin * KS2;
    const int MROWS = (MODE == 1) ? 128 : (MODE == 2 ? 16 : 64);
    const int NSPAN = (MODE == 1) ? 64 : (MODE == 2 ? 16 : 32);
    const int NT = NSPAN / 8;
    const int MT = (MODE == 2) ? 1 : 2;
    const int Hp = Hi + 2, Wp = Wi + 4;

    __shared__ __align__(16) u16 As[2][2][MROWS][40];
    __shared__ __align__(16) u16 Bs[2][2][32][136];
    const int A_PIPE = 2 * MROWS * 80;
    const int B_PIPE = 2 * 32 * 272;

    int tid = threadIdx.x;
    int warp = tid >> 5, lane = tid & 31;
    int nx = W >> 5;
    int x0 = (blockIdx.x % nx) * 32, y0 = (blockIdx.x / nx) * 4;
    int OY, OX, co0;
    const u16 *wH_ = wHp, *wL_ = wLp;
    if (CVT) {
        int cls = blockIdx.y;
        OY = cls >> 1; OX = cls & 1;
        co0 = 0;
        wH_ += (long)cls * 64 * 512;
        wL_ += (long)cls * 64 * 512;
    } else {
        OY = OY_; OX = OX_;
        co0 = blockIdx.y * MROWS;
    }
    int b = blockIdx.z;
    int wm = (MODE == 1) ? (warp >> 1) : (MODE == 2 ? 0 : (warp >> 2));
    int wn = (MODE == 1) ? (warp & 1) : (MODE == 2 ? warp : (warp & 3));

    float acc[MT][NT][4];
#pragma unroll
    for (int mt = 0; mt < MT; mt++)
#pragma unroll
        for (int nt = 0; nt < NT; nt++)
#pragma unroll
            for (int i = 0; i < 4; i++) acc[mt][nt][i] = 0.f;

    const u16* ibH = inH + (long)b * Cin * Hp * Wp;
    const u16* ibL = inL + (long)b * Cin * Hp * Wp;

    int fkr = tid >> 3, seg = tid & 7;
    int px0 = seg * 16, fpy = px0 >> 5, fpx = px0 & 31;
    int fm, fq;
    if (MODE == 1) { fm = tid >> 1; fq = (tid & 1) * 16; }
    else           { fm = tid >> 2; fq = (tid & 3) * 8; }
    bool aact = (MODE == 2) ? (tid < 64) : true;
    u32 aDstH = (u32)__cvta_generic_to_shared(&As[0][0][fm & (MROWS - 1)][fq]);
    u32 aDstL = aDstH + MROWS * 80;
    u32 bDst = (u32)__cvta_generic_to_shared(&Bs[0][0][fkr][px0]);

    u32 aAddr[2][MT], bBase[2];
#pragma unroll
    for (int h = 0; h < 2; h++) {
#pragma unroll
        for (int mt = 0; mt < MT; mt++) {
            int row = wm * 32 + mt * 16 + (lane & 7) + ((lane >> 3) & 1) * 8;
            int kc = ((lane >> 4) & 1) * 8;
            aAddr[h][mt] = (u32)__cvta_generic_to_shared(&As[0][h][row][kc]);
        }
        bBase[h] = (u32)__cvta_generic_to_shared(&Bs[0][h][lane & 15][wn * NSPAN]);
    }

    u32 hv[8], lv[8];

    auto ldgB = [&](int kk) {
        int k = kk + fkr;
        int ci = k / KS2, e = k - ci * KS2;
        int dh = e / KS, dw = e - dh * KS;
        int iy = (y0 + fpy) * STRIDE + SGN * dh + OY;
        int ixb = (x0 + fpx) * STRIDE + SGN * dw + OX;
        long roff = ((long)ci * Hp + iy + 1) * Wp + ixb + 2;
        const u16* pH = ibH + roff;
        const u16* pL = ibL + roff;
#pragma unroll
        for (int j = 0; j < 8; j++) {
            hv[j] = (u32)pH[(2 * j) * STRIDE] | ((u32)pH[(2 * j + 1) * STRIDE] << 16);
            lv[j] = (u32)pL[(2 * j) * STRIDE] | ((u32)pL[(2 * j + 1) * STRIDE] << 16);
        }
    };
    auto cpA = [&](int kk, int st) {
        if (!aact) return;
        const u16* sH = wH_ + (long)(co0 + fm) * K + kk + fq;
        const u16* sL = wL_ + (long)(co0 + fm) * K + kk + fq;
        u32 dH = aDstH + st * A_PIPE;
        u32 dL = aDstL + st * A_PIPE;
        cp16(dH, sH);
        cp16(dL, sL);
        if (MODE == 1) { cp16(dH + 16, sH + 8); cp16(dL + 16, sL + 8); }
    };
    auto stsB = [&](int st) {
        u32 d0 = bDst + st * B_PIPE;
        u32 d1 = d0 + 32 * 272;
        asm volatile("st.shared.v4.b32 [%0], {%1,%2,%3,%4};" :: "r"(d0),
                     "r"(hv[0]), "r"(hv[1]), "r"(hv[2]), "r"(hv[3]));
        asm volatile("st.shared.v4.b32 [%0], {%1,%2,%3,%4};" :: "r"(d0 + 16),
                     "r"(hv[4]), "r"(hv[5]), "r"(hv[6]), "r"(hv[7]));
        asm volatile("st.shared.v4.b32 [%0], {%1,%2,%3,%4};" :: "r"(d1),
                     "r"(lv[0]), "r"(lv[1]), "r"(lv[2]), "r"(lv[3]));
        asm volatile("st.shared.v4.b32 [%0], {%1,%2,%3,%4};" :: "r"(d1 + 16),
                     "r"(lv[4]), "r"(lv[5]), "r"(lv[6]), "r"(lv[7]));
    };

    ldgB(0);
    cpA(0, 0);
    cp_commit();
    int st = 0;
    for (int kk = 0; kk < K; kk += 32, st ^= 1) {
        stsB(st);
        cp_wait0();
        __syncthreads();
        if (kk + 32 < K) {
            ldgB(kk + 32);
            cpA(kk + 32, st ^ 1);
            cp_commit();
        }
#pragma unroll
        for (int ks = 0; ks < 2; ks++) {
            u32 aH[MT][4], aL[MT][4];
#pragma unroll
            for (int mt = 0; mt < MT; mt++) {
                ldsm4(aH[mt], aAddr[0][mt] + st * A_PIPE + ks * 32);
                ldsm4(aL[mt], aAddr[1][mt] + st * A_PIPE + ks * 32);
            }
#pragma unroll
            for (int nt = 0; nt < NT; nt++) {
                u32 bH[2], bL[2];
                ldsm2t(bH, bBase[0] + st * B_PIPE + nt * 16 + ks * 4352);
                ldsm2t(bL, bBase[1] + st * B_PIPE + nt * 16 + ks * 4352);
#pragma unroll
                for (int mt = 0; mt < MT; mt++) {
                    mma16(acc[mt][nt], aH[mt], bH);
                    mma16(acc[mt][nt], aH[mt], bL);
                    mma16(acc[mt][nt], aL[mt], bH);
                }
            }
        }
    }

#pragma unroll
    for (int mt = 0; mt < MT; mt++) {
#pragma unroll
        for (int nt = 0; nt < NT; nt++) {
            int p = wn * NSPAN + nt * 8 + (lane & 3) * 2;
            int py = p >> 5, px = p & 31;
#pragma unroll
            for (int half = 0; half < 2; half++) {
                int row = co0 + wm * 32 + mt * 16 + (lane >> 2) + half * 8;
                if (row >= Cout) continue;
                float bv = bias[row];
                float v0 = acc[mt][nt][half * 2 + 0] + bv;
                float v1 = acc[mt][nt][half * 2 + 1] + bv;
                if (ILV) {
                    int oy = 2 * (y0 + py) + OY;
                    long base = ((long)(b * Cout + row) * (2 * H) + oy) * (2 * W);
                    out[base + 2 * (x0 + px) + OX] = v0;
                    out[base + 2 * (x0 + px + 1) + OX] = v1;
                } else {
                    long base = ((long)(b * Cout + row) * H + y0 + py) * W;
                    *(float2*)&out[base + x0 + px] = make_float2(v0, v1);
                }
            }
        }
    }
}

// ---------------------------------------------------------------------------
// GroupNorm: partial stats, then apply (which re-reduces the 16 partials)
// ---------------------------------------------------------------------------
#define GN_CH 16

__global__ void gn_part_k(const float* __restrict__ x, float* __restrict__ part,
                          int C, int HW, int groups) {
    int bg = blockIdx.x;
    int chunk = blockIdx.y;
    int g = bg % groups, b = bg / groups;
    int Cg = C / groups;
    long base = (long)(b * C + g * Cg) * HW;
    long n4 = ((long)Cg * HW) >> 2;
    long clen = n4 / GN_CH;
    const float4* xp = (const float4*)(x + base) + chunk * clen;
    float s = 0.f, s2 = 0.f;
    for (long i = threadIdx.x; i < clen; i += blockDim.x) {
        float4 v = xp[i];
        s += v.x + v.y + v.z + v.w;
        s2 += v.x * v.x + v.y * v.y + v.z * v.z + v.w * v.w;
    }
    __shared__ float sh[512];
    int tid = threadIdx.x;
    sh[tid] = s;
    sh[256 + tid] = s2;
    __syncthreads();
    for (int o = 128; o > 0; o >>= 1) {
        if (tid < o) { sh[tid] += sh[tid + o]; sh[256 + tid] += sh[256 + tid + o]; }
        __syncthreads();
    }
    if (tid == 0) {
        part[(bg * GN_CH + chunk) * 2] = sh[0];
        part[(bg * GN_CH + chunk) * 2 + 1] = sh[256];
    }
}

// apply + relu + bf16 split; block computes mean/rstd from partials itself
__global__ void gn_apply_k(const float* __restrict__ x, const float* __restrict__ part,
                           const float* __restrict__ gamma, const float* __restrict__ beta,
                           u16* __restrict__ oH, u16* __restrict__ oL,
                           int C, int H, int W, int groups, int total4) {
    __shared__ float shms[2];
    int i0 = blockIdx.x * blockDim.x;
    int i = i0 + threadIdx.x;
    int HW = H * W;
    long e0 = (long)i0 * 4;
    // all threads in a block share the same (b, g)? Block = 256 thr * 4 el = 1024
    // contiguous elements; HW >= 4096, Cg*HW >= 16384 -> same group per block.
    int cblk = (int)((e0 / HW) % C);
    int bblk = (int)(e0 / ((long)HW * C));
    int gblk = cblk / (C / groups);
    if (threadIdx.x < 32) {
        int bg = bblk * groups + gblk;
        float s = 0.f, s2 = 0.f;
        if (threadIdx.x < GN_CH) {
            s = part[(bg * GN_CH + threadIdx.x) * 2];
            s2 = part[(bg * GN_CH + threadIdx.x) * 2 + 1];
        }
#pragma unroll
        for (int o = 8; o > 0; o >>= 1) {
            s += __shfl_xor_sync(0xffffffff, s, o);
            s2 += __shfl_xor_sync(0xffffffff, s2, o);
        }
        if (threadIdx.x == 0) {
            float n = (float)((long)(C / groups) * HW);
            float mean = s / n;
            float var = s2 / n - mean * mean;
            shms[0] = mean;
            shms[1] = rsqrtf(var + 1e-5f);
        }
    }
    __syncthreads();
    if (i >= total4) return;
    long e = (long)i * 4;
    int c = (int)((e / HW) % C);
    int b = (int)(e / ((long)HW * C));
    int r = (int)(e % HW);
    int y = r / W, xx = r - y * W;
    float mean = shms[0];
    float rstd = shms[1];
    float ga = gamma[c] * rstd;
    float bb = beta[c] - mean * ga;
    float4 v = ((const float4*)x)[i];
    float f[4] = {fmaxf(v.x * ga + bb, 0.f), fmaxf(v.y * ga + bb, 0.f),
                  fmaxf(v.z * ga + bb, 0.f), fmaxf(v.w * ga + bb, 0.f)};
    u16 hs[4], ls[4];
#pragma unroll
    for (int j = 0; j < 4; j++) {
        hs[j] = bhi(f[j]);
        ls[j] = bhi(f[j] - bback(hs[j]));
    }
    long off = ((long)((b * C + c) * (H + 2) + y + 1)) * (W + 4) + xx + 2;
    *(u32*)(oH + off) = (u32)hs[0] | ((u32)hs[1] << 16);
    *(u32*)(oH + off + 2) = (u32)hs[2] | ((u32)hs[3] << 16);
    *(u32*)(oL + off) = (u32)ls[0] | ((u32)ls[1] << 16);
    *(u32*)(oL + off + 2) = (u32)ls[2] | ((u32)ls[3] << 16);
}

// ---------------------------------------------------------------------------
// Launcher (single stream)
// ---------------------------------------------------------------------------
static float* s_part;

static void run_gn(const float* buf, const float* gamma, const float* beta,
                   u16* oH, u16* oL, int C, int H, int W, int groups) {
    int HW = H * W;
    gn_part_k<<<dim3(NB * groups, GN_CH), 256>>>(buf, s_part, C, HW, groups);
    int total4 = NB * C * HW / 4;
    gn_apply_k<<<(total4 + 255) / 256, 256>>>(buf, s_part, gamma, beta, oH, oL,
                                              C, H, W, groups, total4);
}

extern "C" void kernel_launch(void* const* d_in, const int* in_sizes, int n_in,
                              void* d_out, int out_size) {
    const float* x  = (const float*)d_in[0];
    const float* Kd = (const float*)d_in[1];
    const float* Kr = (const float*)d_in[2];
    const float* W1 = (const float*)d_in[3];  const float* b1 = (const float*)d_in[4];
    const float* g1 = (const float*)d_in[5];  const float* be1 = (const float*)d_in[6];
    const float* W2 = (const float*)d_in[7];  const float* b2 = (const float*)d_in[8];
    const float* g2 = (const float*)d_in[9];  const float* be2 = (const float*)d_in[10];
    const float* W3 = (const float*)d_in[11]; const float* b3 = (const float*)d_in[12];
    const float* g3 = (const float*)d_in[13]; const float* be3 = (const float*)d_in[14];
    const float* W4 = (const float*)d_in[15]; const float* b4 = (const float*)d_in[16];
    const float* g4 = (const float*)d_in[17]; const float* be4 = (const float*)d_in[18];
    const float* Wt = (const float*)d_in[19]; const float* bt = (const float*)d_in[20];
    const float* g5 = (const float*)d_in[21]; const float* be5 = (const float*)d_in[22];
    const float* W6 = (const float*)d_in[23]; const float* b6 = (const float*)d_in[24];
    float* out = (float*)d_out;

    void* p;
    cudaGetSymbolAddress(&p, g_s0);  float* s0 = (float*)p;
    cudaGetSymbolAddress(&p, g_sA);  float* sA = (float*)p;
    cudaGetSymbolAddress(&p, g_sB);  float* sB = (float*)p;
    cudaGetSymbolAddress(&p, g_sC);  float* sC = (float*)p;
    cudaGetSymbolAddress(&p, g_part); s_part = (float*)p;
    cudaGetSymbolAddress(&p, g_p0H); u16* p0H = (u16*)p;
    cudaGetSymbolAddress(&p, g_p0L); u16* p0L = (u16*)p;
    cudaGetSymbolAddress(&p, g_pCH); u16* pCH = (u16*)p;
    cudaGetSymbolAddress(&p, g_pCL); u16* pCL = (u16*)p;
    cudaGetSymbolAddress(&p, g_pBH); u16* pBH = (u16*)p;
    cudaGetSymbolAddress(&p, g_pBL); u16* pBL = (u16*)p;
    cudaGetSymbolAddress(&p, g_pAH); u16* pAH = (u16*)p;
    cudaGetSymbolAddress(&p, g_pAL); u16* pAL = (u16*)p;
    cudaGetSymbolAddress(&p, g_wH);  u16* wH = (u16*)p;
    cudaGetSymbolAddress(&p, g_wL);  u16* wL = (u16*)p;

    // prep: one ring kernel, one weight-convert kernel
    {
        const int r130 = 2 * 132 + 128 * 4;
        const int r66 = 2 * 68 + 64 * 4;
        int ntot = 16 * 32 * r130 + 16 * 64 * r130 + 16 * 128 * r66 + 16 * 256 * r66;
        ring_all_k<<<(ntot + 255) / 256, 256>>>(pAH, pAL, pBH, pBL, pCH, pCL, p0H, p0L);
        wcvt_all_k<<<(WTOT + 255) / 256, 256>>>(W1, W2, W3, W4, W6, Wt, wH, wL);
    }

    // DWT
    dwt2d_k<<<(16 * 8 * 128 * 128) / 256, 256>>>(x, Kd, p0H, p0L);

    // conv1: 32->64 @128 (MODE0)
    conv_gemm_k<3, 1, 1, 0, 0, 0><<<dim3(128, 1, NB), 256>>>(
        p0H, p0L, wH + WO1, wL + WO1, b1, sC, 32, 64, 128, 128, 128, 128, -1, -1);
    run_gn(sC, g1, be1, pCH, pCL, 64, 128, 128, 8);

    // conv2: 64->128 s2 @64 (MODE1)
    conv_gemm_k<3, 2, 1, 0, 1, 0><<<dim3(32, 1, NB), 256>>>(
        pCH, pCL, wH + WO2, wL + WO2, b2, sB, 64, 128, 64, 64, 128, 128, -1, -1);
    run_gn(sB, g2, be2, pBH, pBL, 128, 64, 64, 16);

    // conv3: 128->256 @64 (MODE1, 2 M-blocks)
    conv_gemm_k<3, 1, 1, 0, 1, 0><<<dim3(32, 2, NB), 256>>>(
        pBH, pBL, wH + WO3, wL + WO3, b3, sA, 128, 256, 64, 64, 64, 64, -1, -1);
    run_gn(sA, g3, be3, pAH, pAL, 256, 64, 64, 32);

    // conv4: 256->128 @64 (MODE1)
    conv_gemm_k<3, 1, 1, 0, 1, 0><<<dim3(32, 1, NB), 256>>>(
        pAH, pAL, wH + WO4, wL + WO4, b4, sB, 256, 128, 64, 64, 64, 64, -1, -1);
    run_gn(sB, g4, be4, pBH, pBL, 128, 64, 64, 16);

    // convT: all 4 classes in ONE launch (grid.y = class)
    conv_gemm_k<2, 1, -1, 1, 0, 1><<<dim3(32, 4, NB), 256>>>(
        pBH, pBL, wH + WOT, wL + WOT, bt, sC,
        128, 64, 64, 64, 64, 64, 0, 0);
    run_gn(sC, g5, be5, pCH, pCL, 64, 128, 128, 8);

    // conv6: 64->16 @128 (MODE2)
    conv_gemm_k<3, 1, 1, 0, 2, 0><<<dim3(128, 1, NB), 256>>>(
        pCH, pCL, wH + WO6, wL + WO6, b6, s0, 64, 16, 128, 128, 128, 128, -1, -1);

    // IDWT
    idwt2d_k<<<(16 * 4 * 128 * 128) / 256, 256>>>(s0, Kr, out);
}

// round 12
// speedup vs baseline: 4.5480x; 1.1328x over previous
#include <cuda_runtime.h>
#include <cuda_bf16.h>

// ---------------------------------------------------------------------------
// WaveletDiffusion round 11: packed u32 {hi:lo} activation planes — B-fill
// does half the LDGs (16x LDG.32 + PRMT split instead of 32x LDG.U16).
// Conv kernels otherwise identical to R10 (1860us).
// ---------------------------------------------------------------------------

#define NB 16
typedef unsigned short u16;
typedef unsigned int u32;

__device__ float g_s0[16 * 32 * 128 * 128];
__device__ float g_sA[16 * 256 * 64 * 64];
__device__ float g_sB[16 * 128 * 64 * 64];
__device__ float g_sC[16 * 64 * 128 * 128];
// packed {hi:lo} bf16 activation planes [b*C][H+2][W+4]
__device__ __align__(16) u32 g_p0P[16 * 32 * 130 * 132];
__device__ __align__(16) u32 g_pCP[16 * 64 * 130 * 132];
__device__ __align__(16) u32 g_pBP[16 * 128 * 66 * 68];
__device__ __align__(16) u32 g_pAP[16 * 256 * 66 * 68];
#define WO1 0
#define WO2 18432
#define WO3 92160
#define WO4 387072
#define WOT 681984
#define WO6 813056
#define WTOT 822272
__device__ __align__(16) u16 g_wH[WTOT], g_wL[WTOT];
__device__ float g_part[512 * 16 * 2];

__device__ __forceinline__ u16 bhi(float v) {
    return __bfloat16_as_ushort(__float2bfloat16_rn(v));
}
__device__ __forceinline__ float bback(u16 u) {
    return __bfloat162float(__ushort_as_bfloat16(u));
}
__device__ __forceinline__ u32 pack_hl(float v) {
    u16 h = bhi(v);
    u16 l = bhi(v - bback(h));
    return (u32)h | ((u32)l << 16);
}
__device__ __forceinline__ u32 prmt(u32 a, u32 b, u32 sel) {
    u32 r;
    asm("prmt.b32 %0, %1, %2, %3;" : "=r"(r) : "r"(a), "r"(b), "r"(sel));
    return r;
}
__device__ __forceinline__ void mma16(float* c, const u32* a, const u32* b) {
    asm volatile(
        "mma.sync.aligned.m16n8k16.row.col.f32.bf16.bf16.f32 "
        "{%0,%1,%2,%3}, {%4,%5,%6,%7}, {%8,%9}, {%0,%1,%2,%3};"
        : "+f"(c[0]), "+f"(c[1]), "+f"(c[2]), "+f"(c[3])
        : "r"(a[0]), "r"(a[1]), "r"(a[2]), "r"(a[3]), "r"(b[0]), "r"(b[1]));
}
__device__ __forceinline__ void ldsm4(u32* r, u32 addr) {
    asm volatile("ldmatrix.sync.aligned.m8n8.x4.shared.b16 {%0,%1,%2,%3}, [%4];"
                 : "=r"(r[0]), "=r"(r[1]), "=r"(r[2]), "=r"(r[3]) : "r"(addr));
}
__device__ __forceinline__ void ldsm2t(u32* r, u32 addr) {
    asm volatile("ldmatrix.sync.aligned.m8n8.x2.trans.shared.b16 {%0,%1}, [%2];"
                 : "=r"(r[0]), "=r"(r[1]) : "r"(addr));
}
__device__ __forceinline__ void cp16(u32 dst, const void* src) {
    asm volatile("cp.async.cg.shared.global [%0], [%1], 16;" :: "r"(dst), "l"(src));
}
__device__ __forceinline__ void cp_commit() {
    asm volatile("cp.async.commit_group;" ::: "memory");
}
__device__ __forceinline__ void cp_wait0() {
    asm volatile("cp.async.wait_group 0;" ::: "memory");
}

// ---------------------------------------------------------------------------
// prep: one kernel for all weight conversions, one for all halo rings
// ---------------------------------------------------------------------------
__global__ void wcvt_all_k(const float* __restrict__ W1, const float* __restrict__ W2,
                           const float* __restrict__ W3, const float* __restrict__ W4,
                           const float* __restrict__ W6, const float* __restrict__ Wt,
                           u16* __restrict__ dH, u16* __restrict__ dL) {
    int i = blockIdx.x * blockDim.x + threadIdx.x;
    float v;
    int o = i;
    if (i < WO2) v = W1[i - WO1];
    else if (i < WO3) v = W2[i - WO2];
    else if (i < WO4) v = W3[i - WO3];
    else if (i < WOT) v = W4[i - WO4];
    else if (i < WO6) {
        int idx = i - WOT;
        int e = idx & 3;
        int ci = (idx >> 2) & 127;
        int co = (idx >> 9) & 63;
        int cls = idx >> 15;
        int dy = cls >> 1, dx = cls & 1;
        int u = e >> 1, vv = e & 1;
        v = Wt[((long)ci * 64 + co) * 16 + ((1 - dy) + 2 * u) * 4 + (1 - dx) + 2 * vv];
    } else if (i < WTOT) v = W6[i - WO6];
    else return;
    u16 h = bhi(v);
    dH[o] = h;
    dL[o] = bhi(v - bback(h));
}

__global__ void ring_all_k(u32* pAP_, u32* pBP_, u32* pCP_, u32* p0P_) {
    const int r130 = 2 * 132 + 128 * 4;
    const int r66  = 2 * 68 + 64 * 4;
    const int n0 = 16 * 32 * r130;
    const int nC = 16 * 64 * r130;
    const int nBx = 16 * 128 * r66;
    const int nAx = 16 * 256 * r66;
    int idx = blockIdx.x * blockDim.x + threadIdx.x;
    u32* pP;
    int ring, Hp, Wp;
    if (idx < n0) { pP = p0P_; ring = r130; Hp = 130; Wp = 132; }
    else if ((idx -= n0) < nC) { pP = pCP_; ring = r130; Hp = 130; Wp = 132; }
    else if ((idx -= nC) < nBx) { pP = pBP_; ring = r66; Hp = 66; Wp = 68; }
    else if ((idx -= nBx) < nAx) { pP = pAP_; ring = r66; Hp = 66; Wp = 68; }
    else return;
    int ch = idx / ring, r = idx - ch * ring;
    int row, col;
    if (r < 2 * Wp) { row = (r < Wp) ? 0 : Hp - 1; col = (r < Wp) ? r : r - Wp; }
    else {
        int rr = r - 2 * Wp;
        row = 1 + (rr >> 2);
        int q = rr & 3;
        col = (q < 2) ? q : Wp - 4 + q;
    }
    pP[((long)ch * Hp + row) * Wp + col] = 0;
}

// ---------------------------------------------------------------------------
// DWT / IDWT
// ---------------------------------------------------------------------------
__global__ void dwt2d_k(const float* __restrict__ x, const float* __restrict__ Kd,
                        u32* __restrict__ oP) {
    int idx = blockIdx.x * blockDim.x + threadIdx.x;
    int w = idx & 127;
    int h = (idx >> 7) & 127;
    int c = (idx >> 14) & 7;
    int b = idx >> 17;
    const float* xp = x + (((b * 8 + c) * 256 + 2 * h) * 256 + 2 * w);
    float x00 = xp[0], x01 = xp[1], x10 = xp[256], x11 = xp[257];
#pragma unroll
    for (int s = 0; s < 4; s++) {
        float v = x00 * Kd[s * 4 + 0] + x01 * Kd[s * 4 + 1]
                + x10 * Kd[s * 4 + 2] + x11 * Kd[s * 4 + 3];
        long off = ((long)(b * 32 + c * 4 + s) * 130 + h + 1) * 132 + w + 2;
        oP[off] = pack_hl(v);
    }
}

__global__ void idwt2d_k(const float* __restrict__ in, const float* __restrict__ Kr,
                         float* __restrict__ out) {
    int idx = blockIdx.x * blockDim.x + threadIdx.x;
    int w = idx & 127;
    int h = (idx >> 7) & 127;
    int c = (idx >> 14) & 3;
    int b = idx >> 16;
    float v[4];
#pragma unroll
    for (int s = 0; s < 4; s++)
        v[s] = in[(((b * 16 + c * 4 + s) * 128 + h) * 128 + w)];
    float* op = out + (((b * 4 + c) * 256 + 2 * h) * 256 + 2 * w);
#pragma unroll
    for (int d = 0; d < 2; d++)
#pragma unroll
        for (int e = 0; e < 2; e++) {
            float y = v[0] * Kr[0 * 4 + d * 2 + e] + v[1] * Kr[1 * 4 + d * 2 + e]
                    + v[2] * Kr[2 * 4 + d * 2 + e] + v[3] * Kr[3 * 4 + d * 2 + e];
            op[d * 256 + e] = y;
        }
}

// ---------------------------------------------------------------------------
// Pipelined implicit-GEMM conv, packed-plane input.
// MODE 0: M=64 (2Mx4N). MODE 1: M=128 (4Mx2N). MODE 2: M=16 (1Mx8N).
// CVT: convT mode — blockIdx.y selects class. N=128 pixels, K-stage 32.
// ---------------------------------------------------------------------------
template <int KS, int STRIDE, int SGN, int ILV, int MODE, int CVT>
__global__ __launch_bounds__(256, 2)
void conv_gemm_k(const u32* __restrict__ inP,
                 const u16* __restrict__ wHp, const u16* __restrict__ wLp,
                 const float* __restrict__ bias, float* __restrict__ out,
                 int Cin, int Cout, int H, int W, int Hi, int Wi, int OY_, int OX_) {
    const int KS2 = KS * KS;
    const int K = Cin * KS2;
    const int MROWS = (MODE == 1) ? 128 : (MODE == 2 ? 16 : 64);
    const int NSPAN = (MODE == 1) ? 64 : (MODE == 2 ? 16 : 32);
    const int NT = NSPAN / 8;
    const int MT = (MODE == 2) ? 1 : 2;
    const int Hp = Hi + 2, Wp = Wi + 4;

    __shared__ __align__(16) u16 As[2][2][MROWS][40];
    __shared__ __align__(16) u16 Bs[2][2][32][136];
    const int A_PIPE = 2 * MROWS * 80;
    const int B_PIPE = 2 * 32 * 272;

    int tid = threadIdx.x;
    int warp = tid >> 5, lane = tid & 31;
    int nx = W >> 5;
    int x0 = (blockIdx.x % nx) * 32, y0 = (blockIdx.x / nx) * 4;
    int OY, OX, co0;
    const u16 *wH_ = wHp, *wL_ = wLp;
    if (CVT) {
        int cls = blockIdx.y;
        OY = cls >> 1; OX = cls & 1;
        co0 = 0;
        wH_ += (long)cls * 64 * 512;
        wL_ += (long)cls * 64 * 512;
    } else {
        OY = OY_; OX = OX_;
        co0 = blockIdx.y * MROWS;
    }
    int b = blockIdx.z;
    int wm = (MODE == 1) ? (warp >> 1) : (MODE == 2 ? 0 : (warp >> 2));
    int wn = (MODE == 1) ? (warp & 1) : (MODE == 2 ? warp : (warp & 3));

    float acc[MT][NT][4];
#pragma unroll
    for (int mt = 0; mt < MT; mt++)
#pragma unroll
        for (int nt = 0; nt < NT; nt++)
#pragma unroll
            for (int i = 0; i < 4; i++) acc[mt][nt][i] = 0.f;

    const u32* ibP = inP + (long)b * Cin * Hp * Wp;

    int fkr = tid >> 3, seg = tid & 7;
    int px0 = seg * 16, fpy = px0 >> 5, fpx = px0 & 31;
    int fm, fq;
    if (MODE == 1) { fm = tid >> 1; fq = (tid & 1) * 16; }
    else           { fm = tid >> 2; fq = (tid & 3) * 8; }
    bool aact = (MODE == 2) ? (tid < 64) : true;
    u32 aDstH = (u32)__cvta_generic_to_shared(&As[0][0][fm & (MROWS - 1)][fq]);
    u32 aDstL = aDstH + MROWS * 80;
    u32 bDst = (u32)__cvta_generic_to_shared(&Bs[0][0][fkr][px0]);

    u32 aAddr[2][MT], bBase[2];
#pragma unroll
    for (int h = 0; h < 2; h++) {
#pragma unroll
        for (int mt = 0; mt < MT; mt++) {
            int row = wm * 32 + mt * 16 + (lane & 7) + ((lane >> 3) & 1) * 8;
            int kc = ((lane >> 4) & 1) * 8;
            aAddr[h][mt] = (u32)__cvta_generic_to_shared(&As[0][h][row][kc]);
        }
        bBase[h] = (u32)__cvta_generic_to_shared(&Bs[0][h][lane & 15][wn * NSPAN]);
    }

    u32 hv[8], lv[8];

    auto ldgB = [&](int kk) {
        int k = kk + fkr;
        int ci = k / KS2, e = k - ci * KS2;
        int dh = e / KS, dw = e - dh * KS;
        int iy = (y0 + fpy) * STRIDE + SGN * dh + OY;
        int ixb = (x0 + fpx) * STRIDE + SGN * dw + OX;
        const u32* pP = ibP + ((long)ci * Hp + iy + 1) * Wp + ixb + 2;
        u32 w[16];
#pragma unroll
        for (int j = 0; j < 16; j++) w[j] = pP[j * STRIDE];
#pragma unroll
        for (int j = 0; j < 8; j++) {
            hv[j] = prmt(w[2 * j], w[2 * j + 1], 0x5410);
            lv[j] = prmt(w[2 * j], w[2 * j + 1], 0x7632);
        }
    };
    auto cpA = [&](int kk, int st) {
        if (!aact) return;
        const u16* sH = wH_ + (long)(co0 + fm) * K + kk + fq;
        const u16* sL = wL_ + (long)(co0 + fm) * K + kk + fq;
        u32 dH = aDstH + st * A_PIPE;
        u32 dL = aDstL + st * A_PIPE;
        cp16(dH, sH);
        cp16(dL, sL);
        if (MODE == 1) { cp16(dH + 16, sH + 8); cp16(dL + 16, sL + 8); }
    };
    auto stsB = [&](int st) {
        u32 d0 = bDst + st * B_PIPE;
        u32 d1 = d0 + 32 * 272;
        asm volatile("st.shared.v4.b32 [%0], {%1,%2,%3,%4};" :: "r"(d0),
                     "r"(hv[0]), "r"(hv[1]), "r"(hv[2]), "r"(hv[3]));
        asm volatile("st.shared.v4.b32 [%0], {%1,%2,%3,%4};" :: "r"(d0 + 16),
                     "r"(hv[4]), "r"(hv[5]), "r"(hv[6]), "r"(hv[7]));
        asm volatile("st.shared.v4.b32 [%0], {%1,%2,%3,%4};" :: "r"(d1),
                     "r"(lv[0]), "r"(lv[1]), "r"(lv[2]), "r"(lv[3]));
        asm volatile("st.shared.v4.b32 [%0], {%1,%2,%3,%4};" :: "r"(d1 + 16),
                     "r"(lv[4]), "r"(lv[5]), "r"(lv[6]), "r"(lv[7]));
    };

    ldgB(0);
    cpA(0, 0);
    cp_commit();
    int st = 0;
    for (int kk = 0; kk < K; kk += 32, st ^= 1) {
        stsB(st);
        cp_wait0();
        __syncthreads();
        if (kk + 32 < K) {
            ldgB(kk + 32);
            cpA(kk + 32, st ^ 1);
            cp_commit();
        }
#pragma unroll
        for (int ks = 0; ks < 2; ks++) {
            u32 aH[MT][4], aL[MT][4];
#pragma unroll
            for (int mt = 0; mt < MT; mt++) {
                ldsm4(aH[mt], aAddr[0][mt] + st * A_PIPE + ks * 32);
                ldsm4(aL[mt], aAddr[1][mt] + st * A_PIPE + ks * 32);
            }
#pragma unroll
            for (int nt = 0; nt < NT; nt++) {
                u32 bH[2], bL[2];
                ldsm2t(bH, bBase[0] + st * B_PIPE + nt * 16 + ks * 4352);
                ldsm2t(bL, bBase[1] + st * B_PIPE + nt * 16 + ks * 4352);
#pragma unroll
                for (int mt = 0; mt < MT; mt++) {
                    mma16(acc[mt][nt], aH[mt], bH);
                    mma16(acc[mt][nt], aH[mt], bL);
                    mma16(acc[mt][nt], aL[mt], bH);
                }
            }
        }
    }

#pragma unroll
    for (int mt = 0; mt < MT; mt++) {
#pragma unroll
        for (int nt = 0; nt < NT; nt++) {
            int p = wn * NSPAN + nt * 8 + (lane & 3) * 2;
            int py = p >> 5, px = p & 31;
#pragma unroll
            for (int half = 0; half < 2; half++) {
                int row = co0 + wm * 32 + mt * 16 + (lane >> 2) + half * 8;
                if (row >= Cout) continue;
                float bv = bias[row];
                float v0 = acc[mt][nt][half * 2 + 0] + bv;
                float v1 = acc[mt][nt][half * 2 + 1] + bv;
                if (ILV) {
                    int oy = 2 * (y0 + py) + OY;
                    long base = ((long)(b * Cout + row) * (2 * H) + oy) * (2 * W);
                    out[base + 2 * (x0 + px) + OX] = v0;
                    out[base + 2 * (x0 + px + 1) + OX] = v1;
                } else {
                    long base = ((long)(b * Cout + row) * H + y0 + py) * W;
                    *(float2*)&out[base + x0 + px] = make_float2(v0, v1);
                }
            }
        }
    }
}

// ---------------------------------------------------------------------------
// GroupNorm: partial stats, then apply (re-reduces the 16 partials in-block)
// ---------------------------------------------------------------------------
#define GN_CH 16

__global__ void gn_part_k(const float* __restrict__ x, float* __restrict__ part,
                          int C, int HW, int groups) {
    int bg = blockIdx.x;
    int chunk = blockIdx.y;
    int g = bg % groups, b = bg / groups;
    int Cg = C / groups;
    long base = (long)(b * C + g * Cg) * HW;
    long n4 = ((long)Cg * HW) >> 2;
    long clen = n4 / GN_CH;
    const float4* xp = (const float4*)(x + base) + chunk * clen;
    float s = 0.f, s2 = 0.f;
    for (long i = threadIdx.x; i < clen; i += blockDim.x) {
        float4 v = xp[i];
        s += v.x + v.y + v.z + v.w;
        s2 += v.x * v.x + v.y * v.y + v.z * v.z + v.w * v.w;
    }
    __shared__ float sh[512];
    int tid = threadIdx.x;
    sh[tid] = s;
    sh[256 + tid] = s2;
    __syncthreads();
    for (int o = 128; o > 0; o >>= 1) {
        if (tid < o) { sh[tid] += sh[tid + o]; sh[256 + tid] += sh[256 + tid + o]; }
        __syncthreads();
    }
    if (tid == 0) {
        part[(bg * GN_CH + chunk) * 2] = sh[0];
        part[(bg * GN_CH + chunk) * 2 + 1] = sh[256];
    }
}

__global__ void gn_apply_k(const float* __restrict__ x, const float* __restrict__ part,
                           const float* __restrict__ gamma, const float* __restrict__ beta,
                           u32* __restrict__ oP,
                           int C, int H, int W, int groups, int total4) {
    __shared__ float shms[2];
    int i0 = blockIdx.x * blockDim.x;
    int i = i0 + threadIdx.x;
    int HW = H * W;
    long e0 = (long)i0 * 4;
    int cblk = (int)((e0 / HW) % C);
    int bblk = (int)(e0 / ((long)HW * C));
    int gblk = cblk / (C / groups);
    if (threadIdx.x < 32) {
        int bg = bblk * groups + gblk;
        float s = 0.f, s2 = 0.f;
        if (threadIdx.x < GN_CH) {
            s = part[(bg * GN_CH + threadIdx.x) * 2];
            s2 = part[(bg * GN_CH + threadIdx.x) * 2 + 1];
        }
#pragma unroll
        for (int o = 8; o > 0; o >>= 1) {
            s += __shfl_xor_sync(0xffffffff, s, o);
            s2 += __shfl_xor_sync(0xffffffff, s2, o);
        }
        if (threadIdx.x == 0) {
            float n = (float)((long)(C / groups) * HW);
            float mean = s / n;
            float var = s2 / n - mean * mean;
            shms[0] = mean;
            shms[1] = rsqrtf(var + 1e-5f);
        }
    }
    __syncthreads();
    if (i >= total4) return;
    long e = (long)i * 4;
    int c = (int)((e / HW) % C);
    int b = (int)(e / ((long)HW * C));
    int r = (int)(e % HW);
    int y = r / W, xx = r - y * W;
    float mean = shms[0];
    float rstd = shms[1];
    float ga = gamma[c] * rstd;
    float bb = beta[c] - mean * ga;
    float4 v = ((const float4*)x)[i];
    u32 p0 = pack_hl(fmaxf(v.x * ga + bb, 0.f));
    u32 p1 = pack_hl(fmaxf(v.y * ga + bb, 0.f));
    u32 p2 = pack_hl(fmaxf(v.z * ga + bb, 0.f));
    u32 p3 = pack_hl(fmaxf(v.w * ga + bb, 0.f));
    long off = ((long)((b * C + c) * (H + 2) + y + 1)) * (W + 4) + xx + 2;
    *(uint2*)(oP + off) = make_uint2(p0, p1);
    *(uint2*)(oP + off + 2) = make_uint2(p2, p3);
}

// ---------------------------------------------------------------------------
// Launcher (single stream)
// ---------------------------------------------------------------------------
static float* s_part;

static void run_gn(const float* buf, const float* gamma, const float* beta,
                   u32* oP, int C, int H, int W, int groups) {
    int HW = H * W;
    gn_part_k<<<dim3(NB * groups, GN_CH), 256>>>(buf, s_part, C, HW, groups);
    int total4 = NB * C * HW / 4;
    gn_apply_k<<<(total4 + 255) / 256, 256>>>(buf, s_part, gamma, beta, oP,
                                              C, H, W, groups, total4);
}

extern "C" void kernel_launch(void* const* d_in, const int* in_sizes, int n_in,
                              void* d_out, int out_size) {
    const float* x  = (const float*)d_in[0];
    const float* Kd = (const float*)d_in[1];
    const float* Kr = (const float*)d_in[2];
    const float* W1 = (const float*)d_in[3];  const float* b1 = (const float*)d_in[4];
    const float* g1 = (const float*)d_in[5];  const float* be1 = (const float*)d_in[6];
    const float* W2 = (const float*)d_in[7];  const float* b2 = (const float*)d_in[8];
    const float* g2 = (const float*)d_in[9];  const float* be2 = (const float*)d_in[10];
    const float* W3 = (const float*)d_in[11]; const float* b3 = (const float*)d_in[12];
    const float* g3 = (const float*)d_in[13]; const float* be3 = (const float*)d_in[14];
    const float* W4 = (const float*)d_in[15]; const float* b4 = (const float*)d_in[16];
    const float* g4 = (const float*)d_in[17]; const float* be4 = (const float*)d_in[18];
    const float* Wt = (const float*)d_in[19]; const float* bt = (const float*)d_in[20];
    const float* g5 = (const float*)d_in[21]; const float* be5 = (const float*)d_in[22];
    const float* W6 = (const float*)d_in[23]; const float* b6 = (const float*)d_in[24];
    float* out = (float*)d_out;

    void* p;
    cudaGetSymbolAddress(&p, g_s0);  float* s0 = (float*)p;
    cudaGetSymbolAddress(&p, g_sA);  float* sA = (float*)p;
    cudaGetSymbolAddress(&p, g_sB);  float* sB = (float*)p;
    cudaGetSymbolAddress(&p, g_sC);  float* sC = (float*)p;
    cudaGetSymbolAddress(&p, g_part); s_part = (float*)p;
    cudaGetSymbolAddress(&p, g_p0P); u32* p0P = (u32*)p;
    cudaGetSymbolAddress(&p, g_pCP); u32* pCP = (u32*)p;
    cudaGetSymbolAddress(&p, g_pBP); u32* pBP = (u32*)p;
    cudaGetSymbolAddress(&p, g_pAP); u32* pAP = (u32*)p;
    cudaGetSymbolAddress(&p, g_wH);  u16* wH = (u16*)p;
    cudaGetSymbolAddress(&p, g_wL);  u16* wL = (u16*)p;

    // prep: one ring kernel, one weight-convert kernel
    {
        const int r130 = 2 * 132 + 128 * 4;
        const int r66 = 2 * 68 + 64 * 4;
        int ntot = 16 * 32 * r130 + 16 * 64 * r130 + 16 * 128 * r66 + 16 * 256 * r66;
        ring_all_k<<<(ntot + 255) / 256, 256>>>(pAP, pBP, pCP, p0P);
        wcvt_all_k<<<(WTOT + 255) / 256, 256>>>(W1, W2, W3, W4, W6, Wt, wH, wL);
    }

    // DWT
    dwt2d_k<<<(16 * 8 * 128 * 128) / 256, 256>>>(x, Kd, p0P);

    // conv1: 32->64 @128 (MODE0)
    conv_gemm_k<3, 1, 1, 0, 0, 0><<<dim3(128, 1, NB), 256>>>(
        p0P, wH + WO1, wL + WO1, b1, sC, 32, 64, 128, 128, 128, 128, -1, -1);
    run_gn(sC, g1, be1, pCP, 64, 128, 128, 8);

    // conv2: 64->128 s2 @64 (MODE1)
    conv_gemm_k<3, 2, 1, 0, 1, 0><<<dim3(32, 1, NB), 256>>>(
        pCP, wH + WO2, wL + WO2, b2, sB, 64, 128, 64, 64, 128, 128, -1, -1);
    run_gn(sB, g2, be2, pBP, 128, 64, 64, 16);

    // conv3: 128->256 @64 (MODE1, 2 M-blocks)
    conv_gemm_k<3, 1, 1, 0, 1, 0><<<dim3(32, 2, NB), 256>>>(
        pBP, wH + WO3, wL + WO3, b3, sA, 128, 256, 64, 64, 64, 64, -1, -1);
    run_gn(sA, g3, be3, pAP, 256, 64, 64, 32);

    // conv4: 256->128 @64 (MODE1)
    conv_gemm_k<3, 1, 1, 0, 1, 0><<<dim3(32, 1, NB), 256>>>(
        pAP, wH + WO4, wL + WO4, b4, sB, 256, 128, 64, 64, 64, 64, -1, -1);
    run_gn(sB, g4, be4, pBP, 128, 64, 64, 16);

    // convT: all 4 classes in ONE launch (grid.y = class)
    conv_gemm_k<2, 1, -1, 1, 0, 1><<<dim3(32, 4, NB), 256>>>(
        pBP, wH + WOT, wL + WOT, bt, sC,
        128, 64, 64, 64, 64, 64, 0, 0);
    run_gn(sC, g5, be5, pCP, 64, 128, 128, 8);

    // conv6: 64->16 @128 (MODE2)
    conv_gemm_k<3, 1, 1, 0, 2, 0><<<dim3(128, 1, NB), 256>>>(
        pCP, wH + WO6, wL + WO6, b6, s0, 64, 16, 128, 128, 128, 128, -1, -1);

    // IDWT
    idwt2d_k<<<(16 * 4 * 128 * 128) / 256, 256>>>(s0, Kr, out);
}

// round 13
// speedup vs baseline: 4.5870x; 1.0086x over previous
#include <cuda_runtime.h>
#include <cuda_bf16.h>

// ---------------------------------------------------------------------------
// WaveletDiffusion round 12: GN statistics fused into the conv epilogue
// (deterministic per-block partial sums -> slotted global array), removing
// the separate full-tensor gn_part pass. Conv mainloop identical to R11.
// ---------------------------------------------------------------------------

#define NB 16
typedef unsigned short u16;
typedef unsigned int u32;

__device__ float g_s0[16 * 32 * 128 * 128];
__device__ float g_sA[16 * 256 * 64 * 64];
__device__ float g_sB[16 * 128 * 64 * 64];
__device__ float g_sC[16 * 64 * 128 * 128];
__device__ __align__(16) u32 g_p0P[16 * 32 * 130 * 132];
__device__ __align__(16) u32 g_pCP[16 * 64 * 130 * 132];
__device__ __align__(16) u32 g_pBP[16 * 128 * 66 * 68];
__device__ __align__(16) u32 g_pAP[16 * 256 * 66 * 68];
#define WO1 0
#define WO2 18432
#define WO3 92160
#define WO4 387072
#define WOT 681984
#define WO6 813056
#define WTOT 822272
__device__ __align__(16) u16 g_wH[WTOT], g_wL[WTOT];
__device__ float g_part[16 * 32 * 128 * 2];   // [bg][slot][2]

__device__ __forceinline__ u16 bhi(float v) {
    return __bfloat16_as_ushort(__float2bfloat16_rn(v));
}
__device__ __forceinline__ float bback(u16 u) {
    return __bfloat162float(__ushort_as_bfloat16(u));
}
__device__ __forceinline__ u32 pack_hl(float v) {
    u16 h = bhi(v);
    u16 l = bhi(v - bback(h));
    return (u32)h | ((u32)l << 16);
}
__device__ __forceinline__ u32 prmt(u32 a, u32 b, u32 sel) {
    u32 r;
    asm("prmt.b32 %0, %1, %2, %3;" : "=r"(r) : "r"(a), "r"(b), "r"(sel));
    return r;
}
__device__ __forceinline__ void mma16(float* c, const u32* a, const u32* b) {
    asm volatile(
        "mma.sync.aligned.m16n8k16.row.col.f32.bf16.bf16.f32 "
        "{%0,%1,%2,%3}, {%4,%5,%6,%7}, {%8,%9}, {%0,%1,%2,%3};"
        : "+f"(c[0]), "+f"(c[1]), "+f"(c[2]), "+f"(c[3])
        : "r"(a[0]), "r"(a[1]), "r"(a[2]), "r"(a[3]), "r"(b[0]), "r"(b[1]));
}
__device__ __forceinline__ void ldsm4(u32* r, u32 addr) {
    asm volatile("ldmatrix.sync.aligned.m8n8.x4.shared.b16 {%0,%1,%2,%3}, [%4];"
                 : "=r"(r[0]), "=r"(r[1]), "=r"(r[2]), "=r"(r[3]) : "r"(addr));
}
__device__ __forceinline__ void ldsm2t(u32* r, u32 addr) {
    asm volatile("ldmatrix.sync.aligned.m8n8.x2.trans.shared.b16 {%0,%1}, [%2];"
                 : "=r"(r[0]), "=r"(r[1]) : "r"(addr));
}
__device__ __forceinline__ void cp16(u32 dst, const void* src) {
    asm volatile("cp.async.cg.shared.global [%0], [%1], 16;" :: "r"(dst), "l"(src));
}
__device__ __forceinline__ void cp_commit() {
    asm volatile("cp.async.commit_group;" ::: "memory");
}
__device__ __forceinline__ void cp_wait0() {
    asm volatile("cp.async.wait_group 0;" ::: "memory");
}

// ---------------------------------------------------------------------------
// prep
// ---------------------------------------------------------------------------
__global__ void wcvt_all_k(const float* __restrict__ W1, const float* __restrict__ W2,
                           const float* __restrict__ W3, const float* __restrict__ W4,
                           const float* __restrict__ W6, const float* __restrict__ Wt,
                           u16* __restrict__ dH, u16* __restrict__ dL) {
    int i = blockIdx.x * blockDim.x + threadIdx.x;
    float v;
    int o = i;
    if (i < WO2) v = W1[i - WO1];
    else if (i < WO3) v = W2[i - WO2];
    else if (i < WO4) v = W3[i - WO3];
    else if (i < WOT) v = W4[i - WO4];
    else if (i < WO6) {
        int idx = i - WOT;
        int e = idx & 3;
        int ci = (idx >> 2) & 127;
        int co = (idx >> 9) & 63;
        int cls = idx >> 15;
        int dy = cls >> 1, dx = cls & 1;
        int u = e >> 1, vv = e & 1;
        v = Wt[((long)ci * 64 + co) * 16 + ((1 - dy) + 2 * u) * 4 + (1 - dx) + 2 * vv];
    } else if (i < WTOT) v = W6[i - WO6];
    else return;
    u16 h = bhi(v);
    dH[o] = h;
    dL[o] = bhi(v - bback(h));
}

__global__ void ring_all_k(u32* pAP_, u32* pBP_, u32* pCP_, u32* p0P_) {
    const int r130 = 2 * 132 + 128 * 4;
    const int r66  = 2 * 68 + 64 * 4;
    const int n0 = 16 * 32 * r130;
    const int nC = 16 * 64 * r130;
    const int nBx = 16 * 128 * r66;
    const int nAx = 16 * 256 * r66;
    int idx = blockIdx.x * blockDim.x + threadIdx.x;
    u32* pP;
    int ring, Hp, Wp;
    if (idx < n0) { pP = p0P_; ring = r130; Hp = 130; Wp = 132; }
    else if ((idx -= n0) < nC) { pP = pCP_; ring = r130; Hp = 130; Wp = 132; }
    else if ((idx -= nC) < nBx) { pP = pBP_; ring = r66; Hp = 66; Wp = 68; }
    else if ((idx -= nBx) < nAx) { pP = pAP_; ring = r66; Hp = 66; Wp = 68; }
    else return;
    int ch = idx / ring, r = idx - ch * ring;
    int row, col;
    if (r < 2 * Wp) { row = (r < Wp) ? 0 : Hp - 1; col = (r < Wp) ? r : r - Wp; }
    else {
        int rr = r - 2 * Wp;
        row = 1 + (rr >> 2);
        int q = rr & 3;
        col = (q < 2) ? q : Wp - 4 + q;
    }
    pP[((long)ch * Hp + row) * Wp + col] = 0;
}

// ---------------------------------------------------------------------------
// DWT / IDWT
// ---------------------------------------------------------------------------
__global__ void dwt2d_k(const float* __restrict__ x, const float* __restrict__ Kd,
                        u32* __restrict__ oP) {
    int idx = blockIdx.x * blockDim.x + threadIdx.x;
    int w = idx & 127;
    int h = (idx >> 7) & 127;
    int c = (idx >> 14) & 7;
    int b = idx >> 17;
    const float* xp = x + (((b * 8 + c) * 256 + 2 * h) * 256 + 2 * w);
    float x00 = xp[0], x01 = xp[1], x10 = xp[256], x11 = xp[257];
#pragma unroll
    for (int s = 0; s < 4; s++) {
        float v = x00 * Kd[s * 4 + 0] + x01 * Kd[s * 4 + 1]
                + x10 * Kd[s * 4 + 2] + x11 * Kd[s * 4 + 3];
        long off = ((long)(b * 32 + c * 4 + s) * 130 + h + 1) * 132 + w + 2;
        oP[off] = pack_hl(v);
    }
}

__global__ void idwt2d_k(const float* __restrict__ in, const float* __restrict__ Kr,
                         float* __restrict__ out) {
    int idx = blockIdx.x * blockDim.x + threadIdx.x;
    int w = idx & 127;
    int h = (idx >> 7) & 127;
    int c = (idx >> 14) & 3;
    int b = idx >> 16;
    float v[4];
#pragma unroll
    for (int s = 0; s < 4; s++)
        v[s] = in[(((b * 16 + c * 4 + s) * 128 + h) * 128 + w)];
    float* op = out + (((b * 4 + c) * 256 + 2 * h) * 256 + 2 * w);
#pragma unroll
    for (int d = 0; d < 2; d++)
#pragma unroll
        for (int e = 0; e < 2; e++) {
            float y = v[0] * Kr[0 * 4 + d * 2 + e] + v[1] * Kr[1 * 4 + d * 2 + e]
                    + v[2] * Kr[2 * 4 + d * 2 + e] + v[3] * Kr[3 * 4 + d * 2 + e];
            op[d * 256 + e] = y;
        }
}

// ---------------------------------------------------------------------------
// Pipelined implicit-GEMM conv, packed-plane input, fused GN partial stats.
// MODE 0: M=64 (2Mx4N). MODE 1: M=128 (4Mx2N). MODE 2: M=16 (1Mx8N).
// CVT: convT mode — blockIdx.y selects class. N=128 pixels, K-stage 32.
// GNS: write per-block per-group (sum, sumsq) to part (Cg=8 layers only).
// ---------------------------------------------------------------------------
template <int KS, int STRIDE, int SGN, int ILV, int MODE, int CVT, int GNS>
__global__ __launch_bounds__(256, 2)
void conv_gemm_k(const u32* __restrict__ inP,
                 const u16* __restrict__ wHp, const u16* __restrict__ wLp,
                 const float* __restrict__ bias, float* __restrict__ out,
                 float* __restrict__ part, int groups, int NPB,
                 int Cin, int Cout, int H, int W, int Hi, int Wi, int OY_, int OX_) {
    const int KS2 = KS * KS;
    const int K = Cin * KS2;
    const int MROWS = (MODE == 1) ? 128 : (MODE == 2 ? 16 : 64);
    const int NSPAN = (MODE == 1) ? 64 : (MODE == 2 ? 16 : 32);
    const int NT = NSPAN / 8;
    const int MT = (MODE == 2) ? 1 : 2;
    const int WN = (MODE == 1) ? 2 : 4;     // wn count (MODE2 unused for GNS)
    const int Hp = Hi + 2, Wp = Wi + 4;

    __shared__ __align__(16) u16 As[2][2][MROWS][40];
    __shared__ __align__(16) u16 Bs[2][2][32][136];
    const int A_PIPE = 2 * MROWS * 80;
    const int B_PIPE = 2 * 32 * 272;

    int tid = threadIdx.x;
    int warp = tid >> 5, lane = tid & 31;
    int nx = W >> 5;
    int x0 = (blockIdx.x % nx) * 32, y0 = (blockIdx.x / nx) * 4;
    int OY, OX, co0, slot;
    const u16 *wH_ = wHp, *wL_ = wLp;
    if (CVT) {
        int cls = blockIdx.y;
        OY = cls >> 1; OX = cls & 1;
        co0 = 0;
        wH_ += (long)cls * 64 * 512;
        wL_ += (long)cls * 64 * 512;
        slot = blockIdx.x + 32 * cls;
    } else {
        OY = OY_; OX = OX_;
        co0 = blockIdx.y * MROWS;
        slot = blockIdx.x;
    }
    int b = blockIdx.z;
    int wm = (MODE == 1) ? (warp >> 1) : (MODE == 2 ? 0 : (warp >> 2));
    int wn = (MODE == 1) ? (warp & 1) : (MODE == 2 ? warp : (warp & 3));

    float acc[MT][NT][4];
#pragma unroll
    for (int mt = 0; mt < MT; mt++)
#pragma unroll
        for (int nt = 0; nt < NT; nt++)
#pragma unroll
            for (int i = 0; i < 4; i++) acc[mt][nt][i] = 0.f;

    const u32* ibP = inP + (long)b * Cin * Hp * Wp;

    int fkr = tid >> 3, seg = tid & 7;
    int px0 = seg * 16, fpy = px0 >> 5, fpx = px0 & 31;
    int fm, fq;
    if (MODE == 1) { fm = tid >> 1; fq = (tid & 1) * 16; }
    else           { fm = tid >> 2; fq = (tid & 3) * 8; }
    bool aact = (MODE == 2) ? (tid < 64) : true;
    u32 aDstH = (u32)__cvta_generic_to_shared(&As[0][0][fm & (MROWS - 1)][fq]);
    u32 aDstL = aDstH + MROWS * 80;
    u32 bDst = (u32)__cvta_generic_to_shared(&Bs[0][0][fkr][px0]);

    u32 aAddr[2][MT], bBase[2];
#pragma unroll
    for (int h = 0; h < 2; h++) {
#pragma unroll
        for (int mt = 0; mt < MT; mt++) {
            int row = wm * 32 + mt * 16 + (lane & 7) + ((lane >> 3) & 1) * 8;
            int kc = ((lane >> 4) & 1) * 8;
            aAddr[h][mt] = (u32)__cvta_generic_to_shared(&As[0][h][row][kc]);
        }
        bBase[h] = (u32)__cvta_generic_to_shared(&Bs[0][h][lane & 15][wn * NSPAN]);
    }

    u32 hv[8], lv[8];

    auto ldgB = [&](int kk) {
        int k = kk + fkr;
        int ci = k / KS2, e = k - ci * KS2;
        int dh = e / KS, dw = e - dh * KS;
        int iy = (y0 + fpy) * STRIDE + SGN * dh + OY;
        int ixb = (x0 + fpx) * STRIDE + SGN * dw + OX;
        const u32* pP = ibP + ((long)ci * Hp + iy + 1) * Wp + ixb + 2;
        u32 w[16];
#pragma unroll
        for (int j = 0; j < 16; j++) w[j] = pP[j * STRIDE];
#pragma unroll
        for (int j = 0; j < 8; j++) {
            hv[j] = prmt(w[2 * j], w[2 * j + 1], 0x5410);
            lv[j] = prmt(w[2 * j], w[2 * j + 1], 0x7632);
        }
    };
    auto cpA = [&](int kk, int st) {
        if (!aact) return;
        const u16* sH = wH_ + (long)(co0 + fm) * K + kk + fq;
        const u16* sL = wL_ + (long)(co0 + fm) * K + kk + fq;
        u32 dH = aDstH + st * A_PIPE;
        u32 dL = aDstL + st * A_PIPE;
        cp16(dH, sH);
        cp16(dL, sL);
        if (MODE == 1) { cp16(dH + 16, sH + 8); cp16(dL + 16, sL + 8); }
    };
    auto stsB = [&](int st) {
        u32 d0 = bDst + st * B_PIPE;
        u32 d1 = d0 + 32 * 272;
        asm volatile("st.shared.v4.b32 [%0], {%1,%2,%3,%4};" :: "r"(d0),
                     "r"(hv[0]), "r"(hv[1]), "r"(hv[2]), "r"(hv[3]));
        asm volatile("st.shared.v4.b32 [%0], {%1,%2,%3,%4};" :: "r"(d0 + 16),
                     "r"(hv[4]), "r"(hv[5]), "r"(hv[6]), "r"(hv[7]));
        asm volatile("st.shared.v4.b32 [%0], {%1,%2,%3,%4};" :: "r"(d1),
                     "r"(lv[0]), "r"(lv[1]), "r"(lv[2]), "r"(lv[3]));
        asm volatile("st.shared.v4.b32 [%0], {%1,%2,%3,%4};" :: "r"(d1 + 16),
                     "r"(lv[4]), "r"(lv[5]), "r"(lv[6]), "r"(lv[7]));
    };

    ldgB(0);
    cpA(0, 0);
    cp_commit();
    int st = 0;
    for (int kk = 0; kk < K; kk += 32, st ^= 1) {
        stsB(st);
        cp_wait0();
        __syncthreads();
        if (kk + 32 < K) {
            ldgB(kk + 32);
            cpA(kk + 32, st ^ 1);
            cp_commit();
        }
#pragma unroll
        for (int ks = 0; ks < 2; ks++) {
            u32 aH[MT][4], aL[MT][4];
#pragma unroll
            for (int mt = 0; mt < MT; mt++) {
                ldsm4(aH[mt], aAddr[0][mt] + st * A_PIPE + ks * 32);
                ldsm4(aL[mt], aAddr[1][mt] + st * A_PIPE + ks * 32);
            }
#pragma unroll
            for (int nt = 0; nt < NT; nt++) {
                u32 bH[2], bL[2];
                ldsm2t(bH, bBase[0] + st * B_PIPE + nt * 16 + ks * 4352);
                ldsm2t(bL, bBase[1] + st * B_PIPE + nt * 16 + ks * 4352);
#pragma unroll
                for (int mt = 0; mt < MT; mt++) {
                    mma16(acc[mt][nt], aH[mt], bH);
                    mma16(acc[mt][nt], aH[mt], bL);
                    mma16(acc[mt][nt], aL[mt], bH);
                }
            }
        }
    }

    // ---- store + bias (+ GN partial accumulation) ----
    float sgs[MT][2], sgs2[MT][2];
    if (GNS) {
#pragma unroll
        for (int mt = 0; mt < MT; mt++)
#pragma unroll
            for (int hf = 0; hf < 2; hf++) { sgs[mt][hf] = 0.f; sgs2[mt][hf] = 0.f; }
    }
#pragma unroll
    for (int mt = 0; mt < MT; mt++) {
#pragma unroll
        for (int nt = 0; nt < NT; nt++) {
            int p = wn * NSPAN + nt * 8 + (lane & 3) * 2;
            int py = p >> 5, px = p & 31;
#pragma unroll
            for (int half = 0; half < 2; half++) {
                int row = co0 + wm * 32 + mt * 16 + (lane >> 2) + half * 8;
                if (row >= Cout) continue;
                float bv = bias[row];
                float v0 = acc[mt][nt][half * 2 + 0] + bv;
                float v1 = acc[mt][nt][half * 2 + 1] + bv;
                if (GNS) {
                    sgs[mt][half] += v0 + v1;
                    sgs2[mt][half] += v0 * v0 + v1 * v1;
                }
                if (ILV) {
                    int oy = 2 * (y0 + py) + OY;
                    long base = ((long)(b * Cout + row) * (2 * H) + oy) * (2 * W);
                    out[base + 2 * (x0 + px) + OX] = v0;
                    out[base + 2 * (x0 + px + 1) + OX] = v1;
                } else {
                    long base = ((long)(b * Cout + row) * H + y0 + py) * W;
                    *(float2*)&out[base + x0 + px] = make_float2(v0, v1);
                }
            }
        }
    }

    if (GNS) {
        // smem overlay on As (mainloop done; sync before reuse)
        float* shs = (float*)&As[0][0][0][0];   // [warp][4][2]
        __syncthreads();
#pragma unroll
        for (int mt = 0; mt < MT; mt++)
#pragma unroll
            for (int hf = 0; hf < 2; hf++) {
                float s = sgs[mt][hf], s2 = sgs2[mt][hf];
#pragma unroll
                for (int o = 16; o > 0; o >>= 1) {
                    s += __shfl_xor_sync(0xffffffff, s, o);
                    s2 += __shfl_xor_sync(0xffffffff, s2, o);
                }
                if (lane == 0) {
                    shs[(warp * 4 + mt * 2 + hf) * 2] = s;
                    shs[(warp * 4 + mt * 2 + hf) * 2 + 1] = s2;
                }
            }
        __syncthreads();
        const int ngroups = MROWS / 8;
        if (tid < ngroups) {
            int wmg = tid >> 2, e = tid & 3;
            float s = 0.f, s2 = 0.f;
#pragma unroll
            for (int w2 = 0; w2 < WN; w2++) {
                int wrp = wmg * WN + w2;
                s += shs[(wrp * 4 + e) * 2];
                s2 += shs[(wrp * 4 + e) * 2 + 1];
            }
            int gg = (co0 >> 3) + tid;
            long pidx = ((long)(b * groups + gg) * NPB + slot) * 2;
            part[pidx] = s;
            part[pidx + 1] = s2;
        }
    }
}

// ---------------------------------------------------------------------------
// GroupNorm apply: reduces the NPB per-block partials, then normalizes,
// relu, packs to the bf16 hi/lo plane.
// ---------------------------------------------------------------------------
__global__ void gn_apply_k(const float* __restrict__ x, const float* __restrict__ part,
                           const float* __restrict__ gamma, const float* __restrict__ beta,
                           u32* __restrict__ oP,
                           int C, int H, int W, int groups, int NPB, int total4) {
    __shared__ float shms[2];
    int i0 = blockIdx.x * blockDim.x;
    int i = i0 + threadIdx.x;
    int HW = H * W;
    long e0 = (long)i0 * 4;
    int cblk = (int)((e0 / HW) % C);
    int bblk = (int)(e0 / ((long)HW * C));
    int gblk = cblk / (C / groups);
    if (threadIdx.x < 32) {
        int bg = bblk * groups + gblk;
        float s = 0.f, s2 = 0.f;
        for (int j = threadIdx.x; j < NPB; j += 32) {
            s += part[((long)bg * NPB + j) * 2];
            s2 += part[((long)bg * NPB + j) * 2 + 1];
        }
#pragma unroll
        for (int o = 16; o > 0; o >>= 1) {
            s += __shfl_xor_sync(0xffffffff, s, o);
            s2 += __shfl_xor_sync(0xffffffff, s2, o);
        }
        if (threadIdx.x == 0) {
            float n = (float)((long)(C / groups) * HW);
            float mean = s / n;
            float var = s2 / n - mean * mean;
            shms[0] = mean;
            shms[1] = rsqrtf(var + 1e-5f);
        }
    }
    __syncthreads();
    if (i >= total4) return;
    long e = (long)i * 4;
    int c = (int)((e / HW) % C);
    int b = (int)(e / ((long)HW * C));
    int r = (int)(e % HW);
    int y = r / W, xx = r - y * W;
    float mean = shms[0];
    float rstd = shms[1];
    float ga = gamma[c] * rstd;
    float bb = beta[c] - mean * ga;
    float4 v = ((const float4*)x)[i];
    u32 q0 = pack_hl(fmaxf(v.x * ga + bb, 0.f));
    u32 q1 = pack_hl(fmaxf(v.y * ga + bb, 0.f));
    u32 q2 = pack_hl(fmaxf(v.z * ga + bb, 0.f));
    u32 q3 = pack_hl(fmaxf(v.w * ga + bb, 0.f));
    long off = ((long)((b * C + c) * (H + 2) + y + 1)) * (W + 4) + xx + 2;
    *(uint2*)(oP + off) = make_uint2(q0, q1);
    *(uint2*)(oP + off + 2) = make_uint2(q2, q3);
}

// ---------------------------------------------------------------------------
// Launcher (single stream)
// ---------------------------------------------------------------------------
static float* s_part;

static void run_gn(const float* buf, const float* gamma, const float* beta,
                   u32* oP, int C, int H, int W, int groups, int NPB) {
    int HW = H * W;
    int total4 = NB * C * HW / 4;
    gn_apply_k<<<(total4 + 255) / 256, 256>>>(buf, s_part, gamma, beta, oP,
                                              C, H, W, groups, NPB, total4);
}

extern "C" void kernel_launch(void* const* d_in, const int* in_sizes, int n_in,
                              void* d_out, int out_size) {
    const float* x  = (const float*)d_in[0];
    const float* Kd = (const float*)d_in[1];
    const float* Kr = (const float*)d_in[2];
    const float* W1 = (const float*)d_in[3];  const float* b1 = (const float*)d_in[4];
    const float* g1 = (const float*)d_in[5];  const float* be1 = (const float*)d_in[6];
    const float* W2 = (const float*)d_in[7];  const float* b2 = (const float*)d_in[8];
    const float* g2 = (const float*)d_in[9];  const float* be2 = (const float*)d_in[10];
    const float* W3 = (const float*)d_in[11]; const float* b3 = (const float*)d_in[12];
    const float* g3 = (const float*)d_in[13]; const float* be3 = (const float*)d_in[14];
    const float* W4 = (const float*)d_in[15]; const float* b4 = (const float*)d_in[16];
    const float* g4 = (const float*)d_in[17]; const float* be4 = (const float*)d_in[18];
    const float* Wt = (const float*)d_in[19]; const float* bt = (const float*)d_in[20];
    const float* g5 = (const float*)d_in[21]; const float* be5 = (const float*)d_in[22];
    const float* W6 = (const float*)d_in[23]; const float* b6 = (const float*)d_in[24];
    float* out = (float*)d_out;

    void* p;
    cudaGetSymbolAddress(&p, g_s0);  float* s0 = (float*)p;
    cudaGetSymbolAddress(&p, g_sA);  float* sA = (float*)p;
    cudaGetSymbolAddress(&p, g_sB);  float* sB = (float*)p;
    cudaGetSymbolAddress(&p, g_sC);  float* sC = (float*)p;
    cudaGetSymbolAddress(&p, g_part); s_part = (float*)p;
    cudaGetSymbolAddress(&p, g_p0P); u32* p0P = (u32*)p;
    cudaGetSymbolAddress(&p, g_pCP); u32* pCP = (u32*)p;
    cudaGetSymbolAddress(&p, g_pBP); u32* pBP = (u32*)p;
    cudaGetSymbolAddress(&p, g_pAP); u32* pAP = (u32*)p;
    cudaGetSymbolAddress(&p, g_wH);  u16* wH = (u16*)p;
    cudaGetSymbolAddress(&p, g_wL);  u16* wL = (u16*)p;

    // prep
    {
        const int r130 = 2 * 132 + 128 * 4;
        const int r66 = 2 * 68 + 64 * 4;
        int ntot = 16 * 32 * r130 + 16 * 64 * r130 + 16 * 128 * r66 + 16 * 256 * r66;
        ring_all_k<<<(ntot + 255) / 256, 256>>>(pAP, pBP, pCP, p0P);
        wcvt_all_k<<<(WTOT + 255) / 256, 256>>>(W1, W2, W3, W4, W6, Wt, wH, wL);
    }

    // DWT
    dwt2d_k<<<(16 * 8 * 128 * 128) / 256, 256>>>(x, Kd, p0P);

    // conv1: 32->64 @128 (MODE0, GN stats fused, NPB=128)
    conv_gemm_k<3, 1, 1, 0, 0, 0, 1><<<dim3(128, 1, NB), 256>>>(
        p0P, wH + WO1, wL + WO1, b1, sC, s_part, 8, 128,
        32, 64, 128, 128, 128, 128, -1, -1);
    run_gn(sC, g1, be1, pCP, 64, 128, 128, 8, 128);

    // conv2: 64->128 s2 @64 (MODE1, NPB=32)
    conv_gemm_k<3, 2, 1, 0, 1, 0, 1><<<dim3(32, 1, NB), 256>>>(
        pCP, wH + WO2, wL + WO2, b2, sB, s_part, 16, 32,
        64, 128, 64, 64, 128, 128, -1, -1);
    run_gn(sB, g2, be2, pBP, 128, 64, 64, 16, 32);

    // conv3: 128->256 @64 (MODE1, 2 M-blocks, NPB=32)
    conv_gemm_k<3, 1, 1, 0, 1, 0, 1><<<dim3(32, 2, NB), 256>>>(
        pBP, wH + WO3, wL + WO3, b3, sA, s_part, 32, 32,
        128, 256, 64, 64, 64, 64, -1, -1);
    run_gn(sA, g3, be3, pAP, 256, 64, 64, 32, 32);

    // conv4: 256->128 @64 (MODE1, NPB=32)
    conv_gemm_k<3, 1, 1, 0, 1, 0, 1><<<dim3(32, 1, NB), 256>>>(
        pAP, wH + WO4, wL + WO4, b4, sB, s_part, 16, 32,
        256, 128, 64, 64, 64, 64, -1, -1);
    run_gn(sB, g4, be4, pBP, 128, 64, 64, 16, 32);

    // convT: all 4 classes in ONE launch (grid.y = class, NPB=128)
    conv_gemm_k<2, 1, -1, 1, 0, 1, 1><<<dim3(32, 4, NB), 256>>>(
        pBP, wH + WOT, wL + WOT, bt, sC, s_part, 8, 128,
        128, 64, 64, 64, 64, 64, 0, 0);
    run_gn(sC, g5, be5, pCP, 64, 128, 128, 8, 128);

    // conv6: 64->16 @128 (MODE2, no GN)
    conv_gemm_k<3, 1, 1, 0, 2, 0, 0><<<dim3(128, 1, NB), 256>>>(
        pCP, wH + WO6, wL + WO6, b6, s0, (float*)0, 0, 0,
        64, 16, 128, 128, 128, 128, -1, -1);

    // IDWT
    idwt2d_k<<<(16 * 4 * 128 * 128) / 256, 256>>>(s0, Kr, out);
}